// round 6
// baseline (speedup 1.0000x reference)
#include <cuda_runtime.h>
#include <math.h>
#include <stdint.h>

// ---------------------------------------------------------------------------
// Problem constants: B=2, Se=4096, Sd=2048, H=256, NH=4, hd=64, F=1024, L=6
// ---------------------------------------------------------------------------
#define C_B   2
#define C_SE  4096
#define C_SD  2048
#define C_H   256
#define C_NH  4
#define C_F   1024
#define C_L   6

// ---------------------------------------------------------------------------
// Scratch (device globals; no allocations allowed)
// ---------------------------------------------------------------------------
__device__ float g_xenc[C_B * C_SE * C_H];
__device__ float g_h   [C_B * C_SD * C_H];
__device__ float g_qkv [3 * C_B * C_SD * C_H];
__device__ float g_q   [C_B * C_SD * C_H];
__device__ float g_kv  [2 * C_B * C_SE * C_H];
__device__ float g_ctx [C_B * C_SD * C_H];
__device__ float g_tmp [C_B * C_SD * C_H];
__device__ float g_ffn [C_B * C_SD * C_F];

// ---------------------------------------------------------------------------
// Helpers: tf32 mma (m16n8k8 row.col f32 accum), cp.async
// fp32 values are fed to the mma directly (hw truncates to tf32); Q is the
// only operand still converted with round-to-nearest (once, cheap).
// ---------------------------------------------------------------------------
__device__ __forceinline__ uint32_t f2tf(float x) {
    uint32_t u;
    asm("cvt.rna.tf32.f32 %0, %1;" : "=r"(u) : "f"(x));
    return u;
}
__device__ __forceinline__ float4 cvt4(float4 v) {
    return make_float4(__uint_as_float(f2tf(v.x)), __uint_as_float(f2tf(v.y)),
                       __uint_as_float(f2tf(v.z)), __uint_as_float(f2tf(v.w)));
}
__device__ __forceinline__ void mma_tf32(float* c, const uint32_t* a,
                                         uint32_t b0, uint32_t b1) {
    asm volatile(
        "mma.sync.aligned.m16n8k8.row.col.f32.tf32.tf32.f32 "
        "{%0,%1,%2,%3}, {%4,%5,%6,%7}, {%8,%9}, {%0,%1,%2,%3};"
        : "+f"(c[0]), "+f"(c[1]), "+f"(c[2]), "+f"(c[3])
        : "r"(a[0]), "r"(a[1]), "r"(a[2]), "r"(a[3]), "r"(b0), "r"(b1));
}
__device__ __forceinline__ void cp16(float* dst_smem, const float* src) {
    uint32_t d = (uint32_t)__cvta_generic_to_shared(dst_smem);
    asm volatile("cp.async.cg.shared.global [%0], [%1], 16;" :: "r"(d), "l"(src));
}
__device__ __forceinline__ void cp_commit() {
    asm volatile("cp.async.commit_group;");
}
template <int N>
__device__ __forceinline__ void cp_wait() {
    asm volatile("cp.async.wait_group %0;" :: "n"(N));
}

// ---------------------------------------------------------------------------
// x_enc = x + pos_embed
// ---------------------------------------------------------------------------
__global__ void add_pos_kernel(const float* __restrict__ x,
                               const float* __restrict__ pos,
                               float* __restrict__ out, int total, int seh) {
    int i = blockIdx.x * blockDim.x + threadIdx.x;
    if (i < total) out[i] = x[i] + pos[i % seh];
}

__device__ __forceinline__ float gelu_f(float x) {
    float x3 = x * x * x;
    return 0.5f * x * (1.0f + tanhf(0.7978845608028654f * (x + 0.044715f * x3)));
}

// ---------------------------------------------------------------------------
// Tensor-core GEMM: C = A[M,K] @ W + bias (+GELU) (+Res). W may be a stack of
// part matrices (each K x nPart); output block n0 uses part = n0/nPart and is
// written at C + part*M*nPart.
// BM=64, BN=64, BK=32, 128 threads (4 warps, 2x2 of 32x32 warp tiles).
// cp.async double-buffered stages; 2-deep register fragment pipeline.
// A stride 36, B stride 72 -> all fragment LDS bank-conflict-free.
// ---------------------------------------------------------------------------
template <bool GELU, bool RES>
__global__ __launch_bounds__(128) void gemm_tc(
    const float* __restrict__ A, const float* __restrict__ W,
    const float* __restrict__ bias, const float* __restrict__ Res,
    float* __restrict__ C, int M, int N, int K, int nPart) {
    __shared__ float As[2][64 * 36];
    __shared__ float Bs[2][32 * 72];

    const int tid = threadIdx.x;
    const int lane = tid & 31, warp = tid >> 5;
    const int g = lane >> 2, c = lane & 3;
    const int wm = warp >> 1, wn = warp & 1;
    const int m0 = blockIdx.y << 6;
    const int n0 = blockIdx.x << 6;
    const int part = n0 / nPart;
    const int nc = n0 - part * nPart;
    const float* Wp = W + (size_t)part * K * nPart + nc;

    // staging maps: A tile 64x32 (2 thr/row, 16 floats each);
    //               B tile 32x64 (4 thr/row, 16 floats each)
    const int arow = tid >> 1, acol = (tid & 1) * 16;
    const int brow = tid >> 2, bcol = (tid & 3) * 16;
    const float* Agp = A + (size_t)(m0 + arow) * K + acol;
    const float* Bgp = Wp + (size_t)brow * nPart + bcol;

    auto stage = [&](int buf, int k0) {
        const float* ag = Agp + k0;
        float* ad = &As[buf][arow * 36 + acol];
#pragma unroll
        for (int j = 0; j < 4; ++j) cp16(ad + 4 * j, ag + 4 * j);
        const float* bg = Bgp + (size_t)k0 * nPart;
        float* bd = &Bs[buf][brow * 72 + bcol];
#pragma unroll
        for (int j = 0; j < 4; ++j) cp16(bd + 4 * j, bg + 4 * j);
    };

    float acc[2][4][4] = {};

    stage(0, 0);
    cp_commit();

    const int KT = K >> 5;
    for (int kt = 0; kt < KT; ++kt) {
        const int buf = kt & 1;
        if (kt + 1 < KT) {
            stage(buf ^ 1, (kt + 1) << 5);
            cp_commit();
            cp_wait<1>();
        } else {
            cp_wait<0>();
        }
        __syncthreads();

        const float* Ab = As[buf];
        const float* Bb = Bs[buf];
        uint32_t af[2][2][4];
        uint32_t bf[2][4][2];
        auto ldfrag = [&](int s, int kk) {
#pragma unroll
            for (int mf = 0; mf < 2; ++mf) {
                int rb = wm * 32 + mf * 16;
                af[s][mf][0] = __float_as_uint(Ab[(rb + g) * 36 + kk + c]);
                af[s][mf][1] = __float_as_uint(Ab[(rb + g + 8) * 36 + kk + c]);
                af[s][mf][2] = __float_as_uint(Ab[(rb + g) * 36 + kk + c + 4]);
                af[s][mf][3] = __float_as_uint(Ab[(rb + g + 8) * 36 + kk + c + 4]);
            }
#pragma unroll
            for (int nf = 0; nf < 4; ++nf) {
                int nb = wn * 32 + nf * 8;
                bf[s][nf][0] = __float_as_uint(Bb[(kk + c) * 72 + nb + g]);
                bf[s][nf][1] = __float_as_uint(Bb[(kk + c + 4) * 72 + nb + g]);
            }
        };
        ldfrag(0, 0);
#pragma unroll
        for (int kk = 0; kk < 4; ++kk) {
            const int s = kk & 1;
            if (kk < 3) ldfrag(s ^ 1, (kk + 1) * 8);
#pragma unroll
            for (int nf = 0; nf < 4; ++nf) {
                mma_tf32(acc[0][nf], af[s][0], bf[s][nf][0], bf[s][nf][1]);
                mma_tf32(acc[1][nf], af[s][1], bf[s][nf][0], bf[s][nf][1]);
            }
        }
        __syncthreads();
    }

    // epilogue
    const float* bp = bias + (size_t)part * nPart;
    float* Cp = C + (size_t)part * M * nPart;
    const float* Rp = RES ? (Res + (size_t)part * M * nPart) : nullptr;
#pragma unroll
    for (int mf = 0; mf < 2; ++mf) {
        int r0 = m0 + wm * 32 + mf * 16 + g;
#pragma unroll
        for (int nf = 0; nf < 4; ++nf) {
            int col = nc + wn * 32 + nf * 8 + 2 * c;
            float2 bi = *(const float2*)&bp[col];
            float v00 = acc[mf][nf][0] + bi.x;
            float v01 = acc[mf][nf][1] + bi.y;
            float v10 = acc[mf][nf][2] + bi.x;
            float v11 = acc[mf][nf][3] + bi.y;
            if (GELU) {
                v00 = gelu_f(v00); v01 = gelu_f(v01);
                v10 = gelu_f(v10); v11 = gelu_f(v11);
            }
            if (RES) {
                float2 ra  = *(const float2*)&Rp[(size_t)r0 * nPart + col];
                float2 rb2 = *(const float2*)&Rp[(size_t)(r0 + 8) * nPart + col];
                v00 += ra.x; v01 += ra.y; v10 += rb2.x; v11 += rb2.y;
            }
            *(float2*)&Cp[(size_t)r0 * nPart + col] = make_float2(v00, v01);
            *(float2*)&Cp[(size_t)(r0 + 8) * nPart + col] = make_float2(v10, v11);
        }
    }
}

// ---------------------------------------------------------------------------
// Tensor-core flash attention: hd=64, NH=4, H=256, no mask.
// 128 threads (4 warps x 16 q-rows of a 64-q tile). K/V tiles double-buffered
// via cp.async, stored naturally [k][d] at stride 72 (all fragment reads
// conflict-free). K smem reused as the P buffer after the score phase.
// Dynamic smem: 4 * 64 * 72 * 4B = 73728 bytes.
// ---------------------------------------------------------------------------
__global__ __launch_bounds__(128) void attn_tc(
    const float* __restrict__ Q, const float* __restrict__ K,
    const float* __restrict__ V, float* __restrict__ Ctx, int Sq, int Sk) {
    const int H = 256;
    extern __shared__ float smp[];
    float* KsBuf[2] = { smp, smp + 64 * 72 };
    float* VsBuf[2] = { smp + 2 * 64 * 72, smp + 3 * 64 * 72 };

    const int tid = threadIdx.x;
    const int lane = tid & 31, warp = tid >> 5;
    const int g = lane >> 2, c = lane & 3;
    const int q0 = blockIdx.x << 6;
    const int b  = blockIdx.y >> 2;
    const int h0 = (blockIdx.y & 3) << 6;
    const int rb = warp << 4;            // warp's q-row base
    const int sr = tid >> 1;             // staging row 0..63
    const int sc = (tid & 1) * 32;       // staging col base

    const float* Kb = K + (size_t)b * Sk * H + h0;
    const float* Vb = V + (size_t)b * Sk * H + h0;

    // ---- stage Q (with RNA tf32 convert) into KsBuf[0], build fragments ----
    {
        const float* qp = Q + ((size_t)(b * Sq + q0 + sr)) * H + h0 + sc;
        float* qd = &KsBuf[0][sr * 72 + sc];
#pragma unroll
        for (int t = 0; t < 8; ++t)
            *(float4*)(qd + 4 * t) = cvt4(*(const float4*)(qp + 4 * t));
    }
    __syncthreads();
    uint32_t qf[8][4];
#pragma unroll
    for (int dc = 0; dc < 8; ++dc) {
        qf[dc][0] = __float_as_uint(KsBuf[0][(rb + g) * 72 + dc * 8 + c]);
        qf[dc][1] = __float_as_uint(KsBuf[0][(rb + g + 8) * 72 + dc * 8 + c]);
        qf[dc][2] = __float_as_uint(KsBuf[0][(rb + g) * 72 + dc * 8 + c + 4]);
        qf[dc][3] = __float_as_uint(KsBuf[0][(rb + g + 8) * 72 + dc * 8 + c + 4]);
    }
    __syncthreads();   // fragments built before cp.async overwrites KsBuf[0]

    auto stage_kv = [&](int buf, int k0) {
        const float* kg = Kb + (size_t)(k0 + sr) * H + sc;
        float* kd = &KsBuf[buf][sr * 72 + sc];
#pragma unroll
        for (int j = 0; j < 8; ++j) cp16(kd + 4 * j, kg + 4 * j);
        const float* vg = Vb + (size_t)(k0 + sr) * H + sc;
        float* vd = &VsBuf[buf][sr * 72 + sc];
#pragma unroll
        for (int j = 0; j < 8; ++j) cp16(vd + 4 * j, vg + 4 * j);
    };

    stage_kv(0, 0);
    cp_commit();

    float mr0 = -1e30f, mr1 = -1e30f, l0 = 0.0f, l1 = 0.0f;
    float oacc[8][4] = {};

    const int T = Sk >> 6;
    for (int t = 0; t < T; ++t) {
        const int buf = t & 1;
        if (t + 1 < T) {
            stage_kv(buf ^ 1, (t + 1) << 6);
            cp_commit();
            cp_wait<1>();
        } else {
            cp_wait<0>();
        }
        __syncthreads();

        const float* Ks = KsBuf[buf];
        const float* Vs = VsBuf[buf];

        // ---- S = Q @ K^T ----
        float sacc[8][4] = {};
#pragma unroll
        for (int dc = 0; dc < 8; ++dc) {
#pragma unroll
            for (int nt = 0; nt < 8; ++nt) {
                uint32_t b0 = __float_as_uint(Ks[(nt * 8 + g) * 72 + dc * 8 + c]);
                uint32_t b1 = __float_as_uint(Ks[(nt * 8 + g) * 72 + dc * 8 + c + 4]);
                mma_tf32(sacc[nt], qf[dc], b0, b1);
            }
        }
        __syncthreads();   // all warps done reading K before P overwrite

        // ---- online softmax ----
        float* Ps = KsBuf[buf];
        const float scale = 0.125f;
        float mx0 = -1e30f, mx1 = -1e30f;
#pragma unroll
        for (int nt = 0; nt < 8; ++nt) {
            sacc[nt][0] *= scale; sacc[nt][1] *= scale;
            sacc[nt][2] *= scale; sacc[nt][3] *= scale;
            mx0 = fmaxf(mx0, fmaxf(sacc[nt][0], sacc[nt][1]));
            mx1 = fmaxf(mx1, fmaxf(sacc[nt][2], sacc[nt][3]));
        }
        mx0 = fmaxf(mx0, __shfl_xor_sync(0xffffffffu, mx0, 1));
        mx0 = fmaxf(mx0, __shfl_xor_sync(0xffffffffu, mx0, 2));
        mx1 = fmaxf(mx1, __shfl_xor_sync(0xffffffffu, mx1, 1));
        mx1 = fmaxf(mx1, __shfl_xor_sync(0xffffffffu, mx1, 2));
        float mn0 = fmaxf(mr0, mx0), mn1 = fmaxf(mr1, mx1);
        float corr0 = __expf(mr0 - mn0), corr1 = __expf(mr1 - mn1);
        float s0 = 0.0f, s1 = 0.0f;
#pragma unroll
        for (int nt = 0; nt < 8; ++nt) {
            float p0 = __expf(sacc[nt][0] - mn0);
            float p1 = __expf(sacc[nt][1] - mn0);
            float p2 = __expf(sacc[nt][2] - mn1);
            float p3 = __expf(sacc[nt][3] - mn1);
            s0 += p0 + p1; s1 += p2 + p3;
            *(float2*)&Ps[(rb + g) * 72 + nt * 8 + 2 * c]     = make_float2(p0, p1);
            *(float2*)&Ps[(rb + g + 8) * 72 + nt * 8 + 2 * c] = make_float2(p2, p3);
            oacc[nt][0] *= corr0; oacc[nt][1] *= corr0;
            oacc[nt][2] *= corr1; oacc[nt][3] *= corr1;
        }
        s0 += __shfl_xor_sync(0xffffffffu, s0, 1);
        s0 += __shfl_xor_sync(0xffffffffu, s0, 2);
        s1 += __shfl_xor_sync(0xffffffffu, s1, 1);
        s1 += __shfl_xor_sync(0xffffffffu, s1, 2);
        l0 = l0 * corr0 + s0;
        l1 = l1 * corr1 + s1;
        mr0 = mn0; mr1 = mn1;
        __syncwarp();      // P rows visible within owning warp

        // ---- O += P @ V ----
#pragma unroll
        for (int kc = 0; kc < 8; ++kc) {
            uint32_t pa[4];
            pa[0] = __float_as_uint(Ps[(rb + g) * 72 + kc * 8 + c]);
            pa[1] = __float_as_uint(Ps[(rb + g + 8) * 72 + kc * 8 + c]);
            pa[2] = __float_as_uint(Ps[(rb + g) * 72 + kc * 8 + c + 4]);
            pa[3] = __float_as_uint(Ps[(rb + g + 8) * 72 + kc * 8 + c + 4]);
#pragma unroll
            for (int nt = 0; nt < 8; ++nt) {
                uint32_t b0 = __float_as_uint(Vs[(kc * 8 + c) * 72 + nt * 8 + g]);
                uint32_t b1 = __float_as_uint(Vs[(kc * 8 + c + 4) * 72 + nt * 8 + g]);
                mma_tf32(oacc[nt], pa, b0, b1);
            }
        }
        __syncthreads();   // buf fully consumed before next iter's cp.async
    }

    // ---- write context ----
    float inv0 = 1.0f / l0, inv1 = 1.0f / l1;
    float* op0 = Ctx + ((size_t)(b * Sq + q0 + rb + g)) * H + h0;
    float* op1 = Ctx + ((size_t)(b * Sq + q0 + rb + g + 8)) * H + h0;
#pragma unroll
    for (int nt = 0; nt < 8; ++nt) {
        *(float2*)&op0[nt * 8 + 2 * c] =
            make_float2(oacc[nt][0] * inv0, oacc[nt][1] * inv0);
        *(float2*)&op1[nt * 8 + 2 * c] =
            make_float2(oacc[nt][2] * inv1, oacc[nt][3] * inv1);
    }
}

// ---------------------------------------------------------------------------
// LayerNorm over last dim (H=256). Warp per row, 8 rows per 256-thread block.
// ---------------------------------------------------------------------------
__global__ __launch_bounds__(256) void ln_kernel(
    const float* __restrict__ in, const float* __restrict__ gamma,
    const float* __restrict__ beta, float* __restrict__ out) {
    const int warp = threadIdx.x >> 5, lane = threadIdx.x & 31;
    const size_t row = (size_t)blockIdx.x * 8 + warp;
    const float* p = in + row * 256 + lane * 8;
    float4 a = *(const float4*)p;
    float4 b = *(const float4*)(p + 4);

    float s = (a.x + a.y) + (a.z + a.w) + (b.x + b.y) + (b.z + b.w);
#pragma unroll
    for (int off = 16; off > 0; off >>= 1)
        s += __shfl_xor_sync(0xffffffffu, s, off);
    float mu = s * (1.0f / 256.0f);

    float dx = a.x - mu, dy = a.y - mu, dz = a.z - mu, dw = a.w - mu;
    float ex = b.x - mu, ey = b.y - mu, ez = b.z - mu, ew = b.w - mu;
    float q = dx * dx + dy * dy + dz * dz + dw * dw +
              ex * ex + ey * ey + ez * ez + ew * ew;
#pragma unroll
    for (int off = 16; off > 0; off >>= 1)
        q += __shfl_xor_sync(0xffffffffu, q, off);
    float inv = rsqrtf(q * (1.0f / 256.0f) + 1e-12f);

    float4 ga = *(const float4*)&gamma[lane * 8];
    float4 gb = *(const float4*)&gamma[lane * 8 + 4];
    float4 ba = *(const float4*)&beta[lane * 8];
    float4 bb = *(const float4*)&beta[lane * 8 + 4];
    float* o = out + row * 256 + lane * 8;
    *(float4*)o = make_float4(dx * inv * ga.x + ba.x, dy * inv * ga.y + ba.y,
                              dz * inv * ga.z + ba.z, dw * inv * ga.w + ba.w);
    *(float4*)(o + 4) = make_float4(ex * inv * gb.x + bb.x, ey * inv * gb.y + bb.y,
                                    ez * inv * gb.z + bb.z, ew * inv * gb.w + bb.w);
}

// ---------------------------------------------------------------------------
// Orchestration
// ---------------------------------------------------------------------------
extern "C" void kernel_launch(void* const* d_in, const int* in_sizes, int n_in,
                              void* d_out, int out_size) {
    const float* x      = (const float*)d_in[0];
    const float* y      = (const float*)d_in[1];
    const float* pos    = (const float*)d_in[2];
    const float* sqkvw  = (const float*)d_in[3];
    const float* sqkvb  = (const float*)d_in[4];
    const float* sow    = (const float*)d_in[5];
    const float* sob    = (const float*)d_in[6];
    const float* cqkvw  = (const float*)d_in[7];
    const float* cqkvb  = (const float*)d_in[8];
    const float* cow    = (const float*)d_in[9];
    const float* cob    = (const float*)d_in[10];
    const float* fw1    = (const float*)d_in[11];
    const float* fb1    = (const float*)d_in[12];
    const float* fw2    = (const float*)d_in[13];
    const float* fb2    = (const float*)d_in[14];
    const float* lng    = (const float*)d_in[15];
    const float* lnb    = (const float*)d_in[16];
    float* out = (float*)d_out;

    const int B = C_B, Se = C_SE, Sd = C_SD, H = C_H, F = C_F, L = C_L, NH = C_NH;
    const int Md = B * Sd;   // 4096
    const int Me = B * Se;   // 8192
    const int ATTN_SMEM = 4 * 64 * 72 * 4;   // 73728 B

    static bool attr_set = false;
    if (!attr_set) {
        cudaFuncSetAttribute(attn_tc, cudaFuncAttributeMaxDynamicSharedMemorySize,
                             ATTN_SMEM);
        attr_set = true;
    }

    float *xenc, *h, *qkv, *q, *kv, *ctx, *tmp, *ffn;
    cudaGetSymbolAddress((void**)&xenc, g_xenc);
    cudaGetSymbolAddress((void**)&h,    g_h);
    cudaGetSymbolAddress((void**)&qkv,  g_qkv);
    cudaGetSymbolAddress((void**)&q,    g_q);
    cudaGetSymbolAddress((void**)&kv,   g_kv);
    cudaGetSymbolAddress((void**)&ctx,  g_ctx);
    cudaGetSymbolAddress((void**)&tmp,  g_tmp);
    cudaGetSymbolAddress((void**)&ffn,  g_ffn);

    {
        int total = B * Se * H;
        add_pos_kernel<<<(total + 255) / 256, 256>>>(x, pos, xenc, total, Se * H);
    }
    cudaMemcpyAsync(h, y, sizeof(float) * (size_t)Md * H, cudaMemcpyDeviceToDevice);

    const dim3 blk(128);
    const dim3 gSelfQKV(768 / 64, Md / 64);
    const dim3 gProj(256 / 64, Md / 64);
    const dim3 gCrossKV(512 / 64, Me / 64);
    const dim3 gFfn1(1024 / 64, Md / 64);
    const dim3 gAttn(Sd / 64, B * NH);

    for (int i = 0; i < L; ++i) {
        const float* sw  = sqkvw + (size_t)i * 3 * H * H;
        const float* sb  = sqkvb + (size_t)i * 3 * H;
        const float* sOw = sow + (size_t)i * H * H;
        const float* sOb = sob + (size_t)i * H;
        const float* cw  = cqkvw + (size_t)i * 3 * H * H;
        const float* cb  = cqkvb + (size_t)i * 3 * H;
        const float* cOw = cow + (size_t)i * H * H;
        const float* cOb = cob + (size_t)i * H;
        const float* w1  = fw1 + (size_t)i * H * F;
        const float* b1  = fb1 + (size_t)i * F;
        const float* w2  = fw2 + (size_t)i * F * H;
        const float* b2  = fb2 + (size_t)i * H;

        // ---- self attention ----
        gemm_tc<false, false><<<gSelfQKV, blk>>>(h, sw, sb, nullptr, qkv,
                                                 Md, 768, H, 256);
        attn_tc<<<gAttn, blk, ATTN_SMEM>>>(qkv, qkv + (size_t)Md * H,
                                           qkv + (size_t)2 * Md * H, ctx, Sd, Sd);
        gemm_tc<false, true><<<gProj, blk>>>(ctx, sOw, sOb, h, tmp, Md, 256, H, 256);
        ln_kernel<<<Md / 8, 256>>>(tmp, lng + (size_t)(i * 3 + 0) * H,
                                   lnb + (size_t)(i * 3 + 0) * H, h);

        // ---- cross attention ----
        gemm_tc<false, false><<<gProj, blk>>>(h, cw, cb, nullptr, q, Md, 256, H, 256);
        gemm_tc<false, false><<<gCrossKV, blk>>>(xenc, cw + (size_t)H * H, cb + H,
                                                 nullptr, kv, Me, 512, H, 256);
        attn_tc<<<gAttn, blk, ATTN_SMEM>>>(q, kv, kv + (size_t)Me * H, ctx, Sd, Se);
        gemm_tc<false, true><<<gProj, blk>>>(ctx, cOw, cOb, h, tmp, Md, 256, H, 256);
        ln_kernel<<<Md / 8, 256>>>(tmp, lng + (size_t)(i * 3 + 1) * H,
                                   lnb + (size_t)(i * 3 + 1) * H, h);

        // ---- FFN ----
        gemm_tc<true, false><<<gFfn1, blk>>>(h, w1, b1, nullptr, ffn, Md, 1024, H, 1024);
        gemm_tc<false, true><<<gProj, blk>>>(ffn, w2, b2, h, tmp, Md, 256, F, 256);
        ln_kernel<<<Md / 8, 256>>>(tmp, lng + (size_t)(i * 3 + 2) * H,
                                   lnb + (size_t)(i * 3 + 2) * H,
                                   (i == L - 1) ? out : h);
    }
}

// round 7
// speedup vs baseline: 1.0375x; 1.0375x over previous
#include <cuda_runtime.h>
#include <math.h>
#include <stdint.h>

// ---------------------------------------------------------------------------
// Problem constants: B=2, Se=4096, Sd=2048, H=256, NH=4, hd=64, F=1024, L=6
// ---------------------------------------------------------------------------
#define C_B   2
#define C_SE  4096
#define C_SD  2048
#define C_H   256
#define C_NH  4
#define C_F   1024
#define C_L   6

// ---------------------------------------------------------------------------
// Scratch (device globals; no allocations allowed)
// ---------------------------------------------------------------------------
__device__ float g_xenc [C_B * C_SE * C_H];
__device__ float g_h    [C_B * C_SD * C_H];
__device__ float g_qkv  [3 * C_B * C_SD * C_H];
__device__ float g_q    [C_B * C_SD * C_H];
__device__ float g_kv   [2 * C_B * C_SE * C_H];
__device__ float g_ctx  [C_B * C_SD * C_H];
__device__ float g_tmp  [C_B * C_SD * C_H];
__device__ float g_ffn  [C_B * C_SD * C_F];
__device__ float g_opart[4 * 8 * C_SD * 64];      // split-K partial O (16.8MB)
__device__ float g_ml   [4 * 8 * C_SD * 2];       // split-K per-row (m, l)

// ---------------------------------------------------------------------------
// tf32 mma (m16n8k8 row.col f32 accum), cp.async helpers
// ---------------------------------------------------------------------------
__device__ __forceinline__ uint32_t f2tf(float x) {
    uint32_t u;
    asm("cvt.rna.tf32.f32 %0, %1;" : "=r"(u) : "f"(x));
    return u;
}
__device__ __forceinline__ float4 cvt4(float4 v) {
    return make_float4(__uint_as_float(f2tf(v.x)), __uint_as_float(f2tf(v.y)),
                       __uint_as_float(f2tf(v.z)), __uint_as_float(f2tf(v.w)));
}
__device__ __forceinline__ void mma_tf32(float* c, const uint32_t* a,
                                         uint32_t b0, uint32_t b1) {
    asm volatile(
        "mma.sync.aligned.m16n8k8.row.col.f32.tf32.tf32.f32 "
        "{%0,%1,%2,%3}, {%4,%5,%6,%7}, {%8,%9}, {%0,%1,%2,%3};"
        : "+f"(c[0]), "+f"(c[1]), "+f"(c[2]), "+f"(c[3])
        : "r"(a[0]), "r"(a[1]), "r"(a[2]), "r"(a[3]), "r"(b0), "r"(b1));
}
__device__ __forceinline__ void cp16(float* dst_smem, const float* src) {
    uint32_t d = (uint32_t)__cvta_generic_to_shared(dst_smem);
    asm volatile("cp.async.cg.shared.global [%0], [%1], 16;" :: "r"(d), "l"(src));
}
__device__ __forceinline__ void cp_commit() {
    asm volatile("cp.async.commit_group;");
}
template <int N>
__device__ __forceinline__ void cp_wait() {
    asm volatile("cp.async.wait_group %0;" :: "n"(N));
}

// ---------------------------------------------------------------------------
// x_enc = x + pos_embed
// ---------------------------------------------------------------------------
__global__ void add_pos_kernel(const float* __restrict__ x,
                               const float* __restrict__ pos,
                               float* __restrict__ out, int total, int seh) {
    int i = blockIdx.x * blockDim.x + threadIdx.x;
    if (i < total) out[i] = x[i] + pos[i % seh];
}

__device__ __forceinline__ float gelu_f(float x) {
    float x3 = x * x * x;
    return 0.5f * x * (1.0f + tanhf(0.7978845608028654f * (x + 0.044715f * x3)));
}

// ---------------------------------------------------------------------------
// Tensor-core GEMM (BM=64, BN=64, BK=32, 128 threads, 2x2 warp tiles).
// W may be a stack of part matrices (each K x nPart); block n0 uses
// part = n0/nPart; output written at C + part*M*nPart.
// ---------------------------------------------------------------------------
template <bool GELU, bool RES>
__global__ __launch_bounds__(128) void gemm_tc(
    const float* __restrict__ A, const float* __restrict__ W,
    const float* __restrict__ bias, const float* __restrict__ Res,
    float* __restrict__ C, int M, int N, int K, int nPart) {
    __shared__ float As[2][64 * 36];
    __shared__ float Bs[2][32 * 72];

    const int tid = threadIdx.x;
    const int lane = tid & 31, warp = tid >> 5;
    const int g = lane >> 2, c = lane & 3;
    const int wm = warp >> 1, wn = warp & 1;
    const int m0 = blockIdx.y << 6;
    const int n0 = blockIdx.x << 6;
    const int part = n0 / nPart;
    const int nc = n0 - part * nPart;
    const float* Wp = W + (size_t)part * K * nPart + nc;

    const int arow = tid >> 1, acol = (tid & 1) * 16;
    const int brow = tid >> 2, bcol = (tid & 3) * 16;
    const float* Agp = A + (size_t)(m0 + arow) * K + acol;
    const float* Bgp = Wp + (size_t)brow * nPart + bcol;

    auto stage = [&](int buf, int k0) {
        const float* ag = Agp + k0;
        float* ad = &As[buf][arow * 36 + acol];
#pragma unroll
        for (int j = 0; j < 4; ++j) cp16(ad + 4 * j, ag + 4 * j);
        const float* bg = Bgp + (size_t)k0 * nPart;
        float* bd = &Bs[buf][brow * 72 + bcol];
#pragma unroll
        for (int j = 0; j < 4; ++j) cp16(bd + 4 * j, bg + 4 * j);
    };

    float acc[2][4][4] = {};
    stage(0, 0);
    cp_commit();

    const int KT = K >> 5;
    for (int kt = 0; kt < KT; ++kt) {
        const int buf = kt & 1;
        if (kt + 1 < KT) {
            stage(buf ^ 1, (kt + 1) << 5);
            cp_commit();
            cp_wait<1>();
        } else {
            cp_wait<0>();
        }
        __syncthreads();

        const float* Ab = As[buf];
        const float* Bb = Bs[buf];
#pragma unroll
        for (int kk = 0; kk < 32; kk += 8) {
            uint32_t af[2][4];
#pragma unroll
            for (int mf = 0; mf < 2; ++mf) {
                int rb = wm * 32 + mf * 16;
                af[mf][0] = __float_as_uint(Ab[(rb + g) * 36 + kk + c]);
                af[mf][1] = __float_as_uint(Ab[(rb + g + 8) * 36 + kk + c]);
                af[mf][2] = __float_as_uint(Ab[(rb + g) * 36 + kk + c + 4]);
                af[mf][3] = __float_as_uint(Ab[(rb + g + 8) * 36 + kk + c + 4]);
            }
#pragma unroll
            for (int nf = 0; nf < 4; ++nf) {
                int nb = wn * 32 + nf * 8;
                uint32_t b0 = __float_as_uint(Bb[(kk + c) * 72 + nb + g]);
                uint32_t b1 = __float_as_uint(Bb[(kk + c + 4) * 72 + nb + g]);
                mma_tf32(acc[0][nf], af[0], b0, b1);
                mma_tf32(acc[1][nf], af[1], b0, b1);
            }
        }
        __syncthreads();
    }

    const float* bp = bias + (size_t)part * nPart;
    float* Cp = C + (size_t)part * M * nPart;
    const float* Rp = RES ? (Res + (size_t)part * M * nPart) : nullptr;
#pragma unroll
    for (int mf = 0; mf < 2; ++mf) {
        int r0 = m0 + wm * 32 + mf * 16 + g;
#pragma unroll
        for (int nf = 0; nf < 4; ++nf) {
            int col = nc + wn * 32 + nf * 8 + 2 * c;
            float2 bi = *(const float2*)&bp[col];
            float v00 = acc[mf][nf][0] + bi.x;
            float v01 = acc[mf][nf][1] + bi.y;
            float v10 = acc[mf][nf][2] + bi.x;
            float v11 = acc[mf][nf][3] + bi.y;
            if (GELU) {
                v00 = gelu_f(v00); v01 = gelu_f(v01);
                v10 = gelu_f(v10); v11 = gelu_f(v11);
            }
            if (RES) {
                float2 ra  = *(const float2*)&Rp[(size_t)r0 * nPart + col];
                float2 rb2 = *(const float2*)&Rp[(size_t)(r0 + 8) * nPart + col];
                v00 += ra.x; v01 += ra.y; v10 += rb2.x; v11 += rb2.y;
            }
            *(float2*)&Cp[(size_t)r0 * nPart + col] = make_float2(v00, v01);
            *(float2*)&Cp[(size_t)(r0 + 8) * nPart + col] = make_float2(v10, v11);
        }
    }
}

// ---------------------------------------------------------------------------
// Narrow GEMM (BM=32, BN=64, BK=32, 128 threads, 4 warps side-by-side in N).
// For the N=256 projections: doubles the grid (512 blocks) vs BM=64.
// Single weight matrix (no parts).
// ---------------------------------------------------------------------------
template <bool RES>
__global__ __launch_bounds__(128) void gemm32_tc(
    const float* __restrict__ A, const float* __restrict__ W,
    const float* __restrict__ bias, const float* __restrict__ Res,
    float* __restrict__ C, int M, int N, int K) {
    __shared__ float As[2][32 * 36];
    __shared__ float Bs[2][32 * 72];

    const int tid = threadIdx.x;
    const int lane = tid & 31, warp = tid >> 5;
    const int g = lane >> 2, c = lane & 3;
    const int m0 = blockIdx.y << 5;
    const int n0 = blockIdx.x << 6;

    const int arow = tid >> 2, acol = (tid & 3) * 8;
    const int brow = tid >> 2, bcol = (tid & 3) * 16;
    const float* Agp = A + (size_t)(m0 + arow) * K + acol;
    const float* Bgp = W + (size_t)brow * N + n0 + bcol;

    auto stage = [&](int buf, int k0) {
        const float* ag = Agp + k0;
        float* ad = &As[buf][arow * 36 + acol];
        cp16(ad, ag);
        cp16(ad + 4, ag + 4);
        const float* bg = Bgp + (size_t)k0 * N;
        float* bd = &Bs[buf][brow * 72 + bcol];
#pragma unroll
        for (int j = 0; j < 4; ++j) cp16(bd + 4 * j, bg + 4 * j);
    };

    float acc[2][2][4] = {};
    stage(0, 0);
    cp_commit();

    const int KT = K >> 5;
    for (int kt = 0; kt < KT; ++kt) {
        const int buf = kt & 1;
        if (kt + 1 < KT) {
            stage(buf ^ 1, (kt + 1) << 5);
            cp_commit();
            cp_wait<1>();
        } else {
            cp_wait<0>();
        }
        __syncthreads();

        const float* Ab = As[buf];
        const float* Bb = Bs[buf];
#pragma unroll
        for (int kk = 0; kk < 32; kk += 8) {
            uint32_t af[2][4];
#pragma unroll
            for (int mf = 0; mf < 2; ++mf) {
                int rb = mf * 16;
                af[mf][0] = __float_as_uint(Ab[(rb + g) * 36 + kk + c]);
                af[mf][1] = __float_as_uint(Ab[(rb + g + 8) * 36 + kk + c]);
                af[mf][2] = __float_as_uint(Ab[(rb + g) * 36 + kk + c + 4]);
                af[mf][3] = __float_as_uint(Ab[(rb + g + 8) * 36 + kk + c + 4]);
            }
#pragma unroll
            for (int nf = 0; nf < 2; ++nf) {
                int nb = warp * 16 + nf * 8;
                uint32_t b0 = __float_as_uint(Bb[(kk + c) * 72 + nb + g]);
                uint32_t b1 = __float_as_uint(Bb[(kk + c + 4) * 72 + nb + g]);
                mma_tf32(acc[0][nf], af[0], b0, b1);
                mma_tf32(acc[1][nf], af[1], b0, b1);
            }
        }
        __syncthreads();
    }

#pragma unroll
    for (int mf = 0; mf < 2; ++mf) {
        int r0 = m0 + mf * 16 + g;
#pragma unroll
        for (int nf = 0; nf < 2; ++nf) {
            int col = n0 + warp * 16 + nf * 8 + 2 * c;
            float2 bi = *(const float2*)&bias[col];
            float v00 = acc[mf][nf][0] + bi.x;
            float v01 = acc[mf][nf][1] + bi.y;
            float v10 = acc[mf][nf][2] + bi.x;
            float v11 = acc[mf][nf][3] + bi.y;
            if (RES) {
                float2 ra  = *(const float2*)&Res[(size_t)r0 * N + col];
                float2 rb2 = *(const float2*)&Res[(size_t)(r0 + 8) * N + col];
                v00 += ra.x; v01 += ra.y; v10 += rb2.x; v11 += rb2.y;
            }
            *(float2*)&C[(size_t)r0 * N + col] = make_float2(v00, v01);
            *(float2*)&C[(size_t)(r0 + 8) * N + col] = make_float2(v10, v11);
        }
    }
}

// ---------------------------------------------------------------------------
// Split-K tensor-core flash attention. Grid (Sq/64, B*NH, nSplit); each block
// processes kChunk keys starting at blockIdx.z*kChunk and writes unnormalized
// partial O plus per-row (m, l) to scratch. Dynamic smem 73728 B.
// ---------------------------------------------------------------------------
__global__ __launch_bounds__(128) void attn_tc(
    const float* __restrict__ Q, const float* __restrict__ K,
    const float* __restrict__ V, float* __restrict__ Opart,
    float* __restrict__ ml, int Sq, int Sk, int kChunk) {
    const int H = 256;
    extern __shared__ float smp[];
    float* KsBuf[2] = { smp, smp + 64 * 72 };
    float* VsBuf[2] = { smp + 2 * 64 * 72, smp + 3 * 64 * 72 };

    const int tid = threadIdx.x;
    const int lane = tid & 31, warp = tid >> 5;
    const int g = lane >> 2, c = lane & 3;
    const int q0 = blockIdx.x << 6;
    const int bh = blockIdx.y;
    const int b  = bh >> 2;
    const int h0 = (bh & 3) << 6;
    const int sp = blockIdx.z;
    const int BH = gridDim.y;
    const int kOff = sp * kChunk;
    const int rb = warp << 4;
    const int sr = tid >> 1;
    const int sc = (tid & 1) * 32;

    const float* Kb = K + (size_t)b * Sk * H + h0;
    const float* Vb = V + (size_t)b * Sk * H + h0;

    // stage Q (tf32 RNA convert) into KsBuf[0], build register fragments
    {
        const float* qp = Q + ((size_t)(b * Sq + q0 + sr)) * H + h0 + sc;
        float* qd = &KsBuf[0][sr * 72 + sc];
#pragma unroll
        for (int t = 0; t < 8; ++t)
            *(float4*)(qd + 4 * t) = cvt4(*(const float4*)(qp + 4 * t));
    }
    __syncthreads();
    uint32_t qf[8][4];
#pragma unroll
    for (int dc = 0; dc < 8; ++dc) {
        qf[dc][0] = __float_as_uint(KsBuf[0][(rb + g) * 72 + dc * 8 + c]);
        qf[dc][1] = __float_as_uint(KsBuf[0][(rb + g + 8) * 72 + dc * 8 + c]);
        qf[dc][2] = __float_as_uint(KsBuf[0][(rb + g) * 72 + dc * 8 + c + 4]);
        qf[dc][3] = __float_as_uint(KsBuf[0][(rb + g + 8) * 72 + dc * 8 + c + 4]);
    }
    __syncthreads();

    auto stage_kv = [&](int buf, int k0) {
        const float* kg = Kb + (size_t)(k0 + sr) * H + sc;
        float* kd = &KsBuf[buf][sr * 72 + sc];
#pragma unroll
        for (int j = 0; j < 8; ++j) cp16(kd + 4 * j, kg + 4 * j);
        const float* vg = Vb + (size_t)(k0 + sr) * H + sc;
        float* vd = &VsBuf[buf][sr * 72 + sc];
#pragma unroll
        for (int j = 0; j < 8; ++j) cp16(vd + 4 * j, vg + 4 * j);
    };

    stage_kv(0, kOff);
    cp_commit();

    float mr0 = -1e30f, mr1 = -1e30f, l0 = 0.0f, l1 = 0.0f;
    float oacc[8][4] = {};

    const int T = kChunk >> 6;
    for (int t = 0; t < T; ++t) {
        const int buf = t & 1;
        if (t + 1 < T) {
            stage_kv(buf ^ 1, kOff + ((t + 1) << 6));
            cp_commit();
            cp_wait<1>();
        } else {
            cp_wait<0>();
        }
        __syncthreads();

        const float* Ks = KsBuf[buf];
        const float* Vs = VsBuf[buf];

        // S = Q @ K^T
        float sacc[8][4] = {};
#pragma unroll
        for (int dc = 0; dc < 8; ++dc) {
#pragma unroll
            for (int nt = 0; nt < 8; ++nt) {
                uint32_t b0 = __float_as_uint(Ks[(nt * 8 + g) * 72 + dc * 8 + c]);
                uint32_t b1 = __float_as_uint(Ks[(nt * 8 + g) * 72 + dc * 8 + c + 4]);
                mma_tf32(sacc[nt], qf[dc], b0, b1);
            }
        }
        __syncthreads();

        // online softmax
        float* Ps = KsBuf[buf];
        const float scale = 0.125f;
        float mx0 = -1e30f, mx1 = -1e30f;
#pragma unroll
        for (int nt = 0; nt < 8; ++nt) {
            sacc[nt][0] *= scale; sacc[nt][1] *= scale;
            sacc[nt][2] *= scale; sacc[nt][3] *= scale;
            mx0 = fmaxf(mx0, fmaxf(sacc[nt][0], sacc[nt][1]));
            mx1 = fmaxf(mx1, fmaxf(sacc[nt][2], sacc[nt][3]));
        }
        mx0 = fmaxf(mx0, __shfl_xor_sync(0xffffffffu, mx0, 1));
        mx0 = fmaxf(mx0, __shfl_xor_sync(0xffffffffu, mx0, 2));
        mx1 = fmaxf(mx1, __shfl_xor_sync(0xffffffffu, mx1, 1));
        mx1 = fmaxf(mx1, __shfl_xor_sync(0xffffffffu, mx1, 2));
        float mn0 = fmaxf(mr0, mx0), mn1 = fmaxf(mr1, mx1);
        float corr0 = __expf(mr0 - mn0), corr1 = __expf(mr1 - mn1);
        float s0 = 0.0f, s1 = 0.0f;
#pragma unroll
        for (int nt = 0; nt < 8; ++nt) {
            float p0 = __expf(sacc[nt][0] - mn0);
            float p1 = __expf(sacc[nt][1] - mn0);
            float p2 = __expf(sacc[nt][2] - mn1);
            float p3 = __expf(sacc[nt][3] - mn1);
            s0 += p0 + p1; s1 += p2 + p3;
            *(float2*)&Ps[(rb + g) * 72 + nt * 8 + 2 * c]     = make_float2(p0, p1);
            *(float2*)&Ps[(rb + g + 8) * 72 + nt * 8 + 2 * c] = make_float2(p2, p3);
            oacc[nt][0] *= corr0; oacc[nt][1] *= corr0;
            oacc[nt][2] *= corr1; oacc[nt][3] *= corr1;
        }
        s0 += __shfl_xor_sync(0xffffffffu, s0, 1);
        s0 += __shfl_xor_sync(0xffffffffu, s0, 2);
        s1 += __shfl_xor_sync(0xffffffffu, s1, 1);
        s1 += __shfl_xor_sync(0xffffffffu, s1, 2);
        l0 = l0 * corr0 + s0;
        l1 = l1 * corr1 + s1;
        mr0 = mn0; mr1 = mn1;
        __syncwarp();

        // O += P @ V
#pragma unroll
        for (int kc = 0; kc < 8; ++kc) {
            uint32_t pa[4];
            pa[0] = __float_as_uint(Ps[(rb + g) * 72 + kc * 8 + c]);
            pa[1] = __float_as_uint(Ps[(rb + g + 8) * 72 + kc * 8 + c]);
            pa[2] = __float_as_uint(Ps[(rb + g) * 72 + kc * 8 + c + 4]);
            pa[3] = __float_as_uint(Ps[(rb + g + 8) * 72 + kc * 8 + c + 4]);
#pragma unroll
            for (int nt = 0; nt < 8; ++nt) {
                uint32_t b0 = __float_as_uint(Vs[(kc * 8 + c) * 72 + nt * 8 + g]);
                uint32_t b1 = __float_as_uint(Vs[(kc * 8 + c + 4) * 72 + nt * 8 + g]);
                mma_tf32(oacc[nt], pa, b0, b1);
            }
        }
        __syncthreads();
    }

    // write unnormalized partial O and (m, l)
    size_t row0 = ((size_t)sp * BH + bh) * Sq + q0 + rb + g;
    size_t row1 = row0 + 8;
    float* op0 = Opart + (row0 << 6);
    float* op1 = Opart + (row1 << 6);
#pragma unroll
    for (int nt = 0; nt < 8; ++nt) {
        *(float2*)&op0[nt * 8 + 2 * c] = make_float2(oacc[nt][0], oacc[nt][1]);
        *(float2*)&op1[nt * 8 + 2 * c] = make_float2(oacc[nt][2], oacc[nt][3]);
    }
    if (c == 0) {
        ml[row0 * 2]     = mr0;
        ml[row0 * 2 + 1] = l0;
        ml[row1 * 2]     = mr1;
        ml[row1 * 2 + 1] = l1;
    }
}

// ---------------------------------------------------------------------------
// Split-K combine: Ctx = sum_sp exp(m_sp - M) O_sp / sum_sp exp(m_sp - M) l_sp
// Grid (Sq/64, B*NH), 256 threads; 4 threads per q-row, 16 cols each.
// ---------------------------------------------------------------------------
__global__ __launch_bounds__(256) void attn_combine(
    const float* __restrict__ Opart, const float* __restrict__ ml,
    float* __restrict__ Ctx, int Sq, int nSplit) {
    const int BH = gridDim.y;
    const int bh = blockIdx.y;
    const int b = bh >> 2, h0 = (bh & 3) << 6;
    const int q = (blockIdx.x << 6) + (threadIdx.x >> 2);
    const int c0 = (threadIdx.x & 3) << 4;
    const size_t slab = (size_t)BH * Sq;
    const size_t rbase = (size_t)bh * Sq + q;

    float M = -1e30f;
    for (int sp = 0; sp < nSplit; ++sp)
        M = fmaxf(M, ml[(sp * slab + rbase) * 2]);

    float L = 0.0f;
    float4 a[4] = {{0,0,0,0},{0,0,0,0},{0,0,0,0},{0,0,0,0}};
    for (int sp = 0; sp < nSplit; ++sp) {
        size_t r = sp * slab + rbase;
        float w = __expf(ml[r * 2] - M);
        L += w * ml[r * 2 + 1];
        const float* p = Opart + (r << 6) + c0;
#pragma unroll
        for (int j = 0; j < 4; ++j) {
            float4 v = *(const float4*)(p + 4 * j);
            a[j].x += w * v.x; a[j].y += w * v.y;
            a[j].z += w * v.z; a[j].w += w * v.w;
        }
    }
    float inv = 1.0f / L;
    float* o = Ctx + ((size_t)(b * Sq + q)) * 256 + h0 + c0;
#pragma unroll
    for (int j = 0; j < 4; ++j)
        *(float4*)(o + 4 * j) = make_float4(a[j].x * inv, a[j].y * inv,
                                            a[j].z * inv, a[j].w * inv);
}

// ---------------------------------------------------------------------------
// LayerNorm over last dim (H=256). Warp per row, 8 rows per 256-thread block.
// ---------------------------------------------------------------------------
__global__ __launch_bounds__(256) void ln_kernel(
    const float* __restrict__ in, const float* __restrict__ gamma,
    const float* __restrict__ beta, float* __restrict__ out) {
    const int warp = threadIdx.x >> 5, lane = threadIdx.x & 31;
    const size_t row = (size_t)blockIdx.x * 8 + warp;
    const float* p = in + row * 256 + lane * 8;
    float4 a = *(const float4*)p;
    float4 b = *(const float4*)(p + 4);

    float s = (a.x + a.y) + (a.z + a.w) + (b.x + b.y) + (b.z + b.w);
#pragma unroll
    for (int off = 16; off > 0; off >>= 1)
        s += __shfl_xor_sync(0xffffffffu, s, off);
    float mu = s * (1.0f / 256.0f);

    float dx = a.x - mu, dy = a.y - mu, dz = a.z - mu, dw = a.w - mu;
    float ex = b.x - mu, ey = b.y - mu, ez = b.z - mu, ew = b.w - mu;
    float q = dx * dx + dy * dy + dz * dz + dw * dw +
              ex * ex + ey * ey + ez * ez + ew * ew;
#pragma unroll
    for (int off = 16; off > 0; off >>= 1)
        q += __shfl_xor_sync(0xffffffffu, q, off);
    float inv = rsqrtf(q * (1.0f / 256.0f) + 1e-12f);

    float4 ga = *(const float4*)&gamma[lane * 8];
    float4 gb = *(const float4*)&gamma[lane * 8 + 4];
    float4 ba = *(const float4*)&beta[lane * 8];
    float4 bb = *(const float4*)&beta[lane * 8 + 4];
    float* o = out + row * 256 + lane * 8;
    *(float4*)o = make_float4(dx * inv * ga.x + ba.x, dy * inv * ga.y + ba.y,
                              dz * inv * ga.z + ba.z, dw * inv * ga.w + ba.w);
    *(float4*)(o + 4) = make_float4(ex * inv * gb.x + bb.x, ey * inv * gb.y + bb.y,
                                    ez * inv * gb.z + bb.z, ew * inv * gb.w + bb.w);
}

// ---------------------------------------------------------------------------
// Orchestration
// ---------------------------------------------------------------------------
extern "C" void kernel_launch(void* const* d_in, const int* in_sizes, int n_in,
                              void* d_out, int out_size) {
    const float* x      = (const float*)d_in[0];
    const float* y      = (const float*)d_in[1];
    const float* pos    = (const float*)d_in[2];
    const float* sqkvw  = (const float*)d_in[3];
    const float* sqkvb  = (const float*)d_in[4];
    const float* sow    = (const float*)d_in[5];
    const float* sob    = (const float*)d_in[6];
    const float* cqkvw  = (const float*)d_in[7];
    const float* cqkvb  = (const float*)d_in[8];
    const float* cow    = (const float*)d_in[9];
    const float* cob    = (const float*)d_in[10];
    const float* fw1    = (const float*)d_in[11];
    const float* fb1    = (const float*)d_in[12];
    const float* fw2    = (const float*)d_in[13];
    const float* fb2    = (const float*)d_in[14];
    const float* lng    = (const float*)d_in[15];
    const float* lnb    = (const float*)d_in[16];
    float* out = (float*)d_out;

    const int B = C_B, Se = C_SE, Sd = C_SD, H = C_H, F = C_F, L = C_L, NH = C_NH;
    const int Md = B * Sd;   // 4096
    const int Me = B * Se;   // 8192
    const int ATTN_SMEM = 4 * 64 * 72 * 4;   // 73728 B

    static bool attr_set = false;
    if (!attr_set) {
        cudaFuncSetAttribute(attn_tc, cudaFuncAttributeMaxDynamicSharedMemorySize,
                             ATTN_SMEM);
        attr_set = true;
    }

    float *xenc, *h, *qkv, *q, *kv, *ctx, *tmp, *ffn, *opart, *ml;
    cudaGetSymbolAddress((void**)&xenc,  g_xenc);
    cudaGetSymbolAddress((void**)&h,     g_h);
    cudaGetSymbolAddress((void**)&qkv,   g_qkv);
    cudaGetSymbolAddress((void**)&q,     g_q);
    cudaGetSymbolAddress((void**)&kv,    g_kv);
    cudaGetSymbolAddress((void**)&ctx,   g_ctx);
    cudaGetSymbolAddress((void**)&tmp,   g_tmp);
    cudaGetSymbolAddress((void**)&ffn,   g_ffn);
    cudaGetSymbolAddress((void**)&opart, g_opart);
    cudaGetSymbolAddress((void**)&ml,    g_ml);

    {
        int total = B * Se * H;
        add_pos_kernel<<<(total + 255) / 256, 256>>>(x, pos, xenc, total, Se * H);
    }
    cudaMemcpyAsync(h, y, sizeof(float) * (size_t)Md * H, cudaMemcpyDeviceToDevice);

    const dim3 blk(128);
    const dim3 gSelfQKV(768 / 64, Md / 64);       // 768 blocks
    const dim3 gProj32(256 / 64, Md / 32);        // 512 blocks
    const dim3 gCrossKV(512 / 64, Me / 64);       // 1024 blocks
    const dim3 gFfn1(1024 / 64, Md / 64);         // 1024 blocks
    const dim3 gAttnSelf(Sd / 64, B * NH, 2);     // 512 blocks, kChunk=1024
    const dim3 gAttnCross(Sd / 64, B * NH, 4);    // 1024 blocks, kChunk=1024
    const dim3 gComb(Sd / 64, B * NH);

    for (int i = 0; i < L; ++i) {
        const float* sw  = sqkvw + (size_t)i * 3 * H * H;
        const float* sb  = sqkvb + (size_t)i * 3 * H;
        const float* sOw = sow + (size_t)i * H * H;
        const float* sOb = sob + (size_t)i * H;
        const float* cw  = cqkvw + (size_t)i * 3 * H * H;
        const float* cb  = cqkvb + (size_t)i * 3 * H;
        const float* cOw = cow + (size_t)i * H * H;
        const float* cOb = cob + (size_t)i * H;
        const float* w1  = fw1 + (size_t)i * H * F;
        const float* b1  = fb1 + (size_t)i * F;
        const float* w2  = fw2 + (size_t)i * F * H;
        const float* b2  = fb2 + (size_t)i * H;

        // ---- self attention ----
        gemm_tc<false, false><<<gSelfQKV, blk>>>(h, sw, sb, nullptr, qkv,
                                                 Md, 768, H, 256);
        attn_tc<<<gAttnSelf, blk, ATTN_SMEM>>>(qkv, qkv + (size_t)Md * H,
                                               qkv + (size_t)2 * Md * H,
                                               opart, ml, Sd, Sd, 1024);
        attn_combine<<<gComb, 256>>>(opart, ml, ctx, Sd, 2);
        gemm32_tc<true><<<gProj32, blk>>>(ctx, sOw, sOb, h, tmp, Md, 256, 256);
        ln_kernel<<<Md / 8, 256>>>(tmp, lng + (size_t)(i * 3 + 0) * H,
                                   lnb + (size_t)(i * 3 + 0) * H, h);

        // ---- cross attention ----
        gemm32_tc<false><<<gProj32, blk>>>(h, cw, cb, nullptr, q, Md, 256, 256);
        gemm_tc<false, false><<<gCrossKV, blk>>>(xenc, cw + (size_t)H * H, cb + H,
                                                 nullptr, kv, Me, 512, H, 256);
        attn_tc<<<gAttnCross, blk, ATTN_SMEM>>>(q, kv, kv + (size_t)Me * H,
                                                opart, ml, Sd, Se, 1024);
        attn_combine<<<gComb, 256>>>(opart, ml, ctx, Sd, 4);
        gemm32_tc<true><<<gProj32, blk>>>(ctx, cOw, cOb, h, tmp, Md, 256, 256);
        ln_kernel<<<Md / 8, 256>>>(tmp, lng + (size_t)(i * 3 + 1) * H,
                                   lnb + (size_t)(i * 3 + 1) * H, h);

        // ---- FFN ----
        gemm_tc<true, false><<<gFfn1, blk>>>(h, w1, b1, nullptr, ffn,
                                             Md, 1024, H, 1024);
        gemm32_tc<true><<<gProj32, blk>>>(ffn, w2, b2, h, tmp, Md, 256, 1024);
        ln_kernel<<<Md / 8, 256>>>(tmp, lng + (size_t)(i * 3 + 2) * H,
                                   lnb + (size_t)(i * 3 + 2) * H,
                                   (i == L - 1) ? out : h);
    }
}

// round 9
// speedup vs baseline: 1.0762x; 1.0373x over previous
#include <cuda_runtime.h>
#include <math.h>
#include <stdint.h>

// ---------------------------------------------------------------------------
// Problem constants: B=2, Se=4096, Sd=2048, H=256, NH=4, hd=64, F=1024, L=6
// ---------------------------------------------------------------------------
#define C_B   2
#define C_SE  4096
#define C_SD  2048
#define C_H   256
#define C_NH  4
#define C_F   1024
#define C_L   6

// ---------------------------------------------------------------------------
// Scratch (device globals; no allocations allowed)
// ---------------------------------------------------------------------------
__device__ float g_xenc [C_B * C_SE * C_H];
__device__ float g_h    [C_B * C_SD * C_H];
__device__ float g_qkv  [3 * C_B * C_SD * C_H];
__device__ float g_q    [C_B * C_SD * C_H];
__device__ float g_kv   [2 * C_B * C_SE * C_H];
__device__ float g_ctx  [C_B * C_SD * C_H];
__device__ float g_tmp  [C_B * C_SD * C_H];
__device__ float g_ffn  [C_B * C_SD * C_F];
__device__ float g_opart[4 * 8 * C_SD * 64];      // split-K partial O
__device__ float g_ml   [4 * 8 * C_SD * 2];       // split-K per-row (m, l)

// ---------------------------------------------------------------------------
// tf32 mma (m16n8k8 row.col f32 accum), cp.async helpers
// ---------------------------------------------------------------------------
__device__ __forceinline__ uint32_t f2tf(float x) {
    uint32_t u;
    asm("cvt.rna.tf32.f32 %0, %1;" : "=r"(u) : "f"(x));
    return u;
}
__device__ __forceinline__ float4 cvt4(float4 v) {
    return make_float4(__uint_as_float(f2tf(v.x)), __uint_as_float(f2tf(v.y)),
                       __uint_as_float(f2tf(v.z)), __uint_as_float(f2tf(v.w)));
}
__device__ __forceinline__ void mma_tf32(float* c, const uint32_t* a,
                                         uint32_t b0, uint32_t b1) {
    asm volatile(
        "mma.sync.aligned.m16n8k8.row.col.f32.tf32.tf32.f32 "
        "{%0,%1,%2,%3}, {%4,%5,%6,%7}, {%8,%9}, {%0,%1,%2,%3};"
        : "+f"(c[0]), "+f"(c[1]), "+f"(c[2]), "+f"(c[3])
        : "r"(a[0]), "r"(a[1]), "r"(a[2]), "r"(a[3]), "r"(b0), "r"(b1));
}
__device__ __forceinline__ void cp16(float* dst_smem, const float* src) {
    uint32_t d = (uint32_t)__cvta_generic_to_shared(dst_smem);
    asm volatile("cp.async.cg.shared.global [%0], [%1], 16;" :: "r"(d), "l"(src));
}
__device__ __forceinline__ void cp_commit() {
    asm volatile("cp.async.commit_group;");
}
template <int N>
__device__ __forceinline__ void cp_wait() {
    asm volatile("cp.async.wait_group %0;" :: "n"(N));
}

// ---------------------------------------------------------------------------
// x_enc = x + pos_embed
// ---------------------------------------------------------------------------
__global__ void add_pos_kernel(const float* __restrict__ x,
                               const float* __restrict__ pos,
                               float* __restrict__ out, int total, int seh) {
    int i = blockIdx.x * blockDim.x + threadIdx.x;
    if (i < total) out[i] = x[i] + pos[i % seh];
}

__device__ __forceinline__ float gelu_f(float x) {
    float x3 = x * x * x;
    return 0.5f * x * (1.0f + tanhf(0.7978845608028654f * (x + 0.044715f * x3)));
}

// ---------------------------------------------------------------------------
// Tensor-core GEMM (BM=64, BN=64, BK=32, 128 threads, 2x2 warp tiles).
// ---------------------------------------------------------------------------
template <bool GELU, bool RES>
__global__ __launch_bounds__(128) void gemm_tc(
    const float* __restrict__ A, const float* __restrict__ W,
    const float* __restrict__ bias, const float* __restrict__ Res,
    float* __restrict__ C, int M, int N, int K, int nPart) {
    __shared__ float As[2][64 * 36];
    __shared__ float Bs[2][32 * 72];

    const int tid = threadIdx.x;
    const int lane = tid & 31, warp = tid >> 5;
    const int g = lane >> 2, c = lane & 3;
    const int wm = warp >> 1, wn = warp & 1;
    const int m0 = blockIdx.y << 6;
    const int n0 = blockIdx.x << 6;
    const int part = n0 / nPart;
    const int nc = n0 - part * nPart;
    const float* Wp = W + (size_t)part * K * nPart + nc;

    const int arow = tid >> 1, acol = (tid & 1) * 16;
    const int brow = tid >> 2, bcol = (tid & 3) * 16;
    const float* Agp = A + (size_t)(m0 + arow) * K + acol;
    const float* Bgp = Wp + (size_t)brow * nPart + bcol;

    auto stage = [&](int buf, int k0) {
        const float* ag = Agp + k0;
        float* ad = &As[buf][arow * 36 + acol];
#pragma unroll
        for (int j = 0; j < 4; ++j) cp16(ad + 4 * j, ag + 4 * j);
        const float* bg = Bgp + (size_t)k0 * nPart;
        float* bd = &Bs[buf][brow * 72 + bcol];
#pragma unroll
        for (int j = 0; j < 4; ++j) cp16(bd + 4 * j, bg + 4 * j);
    };

    float acc[2][4][4] = {};
    stage(0, 0);
    cp_commit();

    const int KT = K >> 5;
    for (int kt = 0; kt < KT; ++kt) {
        const int buf = kt & 1;
        if (kt + 1 < KT) {
            stage(buf ^ 1, (kt + 1) << 5);
            cp_commit();
            cp_wait<1>();
        } else {
            cp_wait<0>();
        }
        __syncthreads();

        const float* Ab = As[buf];
        const float* Bb = Bs[buf];
#pragma unroll
        for (int kk = 0; kk < 32; kk += 8) {
            uint32_t af[2][4];
#pragma unroll
            for (int mf = 0; mf < 2; ++mf) {
                int rb = wm * 32 + mf * 16;
                af[mf][0] = __float_as_uint(Ab[(rb + g) * 36 + kk + c]);
                af[mf][1] = __float_as_uint(Ab[(rb + g + 8) * 36 + kk + c]);
                af[mf][2] = __float_as_uint(Ab[(rb + g) * 36 + kk + c + 4]);
                af[mf][3] = __float_as_uint(Ab[(rb + g + 8) * 36 + kk + c + 4]);
            }
#pragma unroll
            for (int nf = 0; nf < 4; ++nf) {
                int nb = wn * 32 + nf * 8;
                uint32_t b0 = __float_as_uint(Bb[(kk + c) * 72 + nb + g]);
                uint32_t b1 = __float_as_uint(Bb[(kk + c + 4) * 72 + nb + g]);
                mma_tf32(acc[0][nf], af[0], b0, b1);
                mma_tf32(acc[1][nf], af[1], b0, b1);
            }
        }
        __syncthreads();
    }

    const float* bp = bias + (size_t)part * nPart;
    float* Cp = C + (size_t)part * M * nPart;
    const float* Rp = RES ? (Res + (size_t)part * M * nPart) : nullptr;
#pragma unroll
    for (int mf = 0; mf < 2; ++mf) {
        int r0 = m0 + wm * 32 + mf * 16 + g;
#pragma unroll
        for (int nf = 0; nf < 4; ++nf) {
            int col = nc + wn * 32 + nf * 8 + 2 * c;
            float2 bi = *(const float2*)&bp[col];
            float v00 = acc[mf][nf][0] + bi.x;
            float v01 = acc[mf][nf][1] + bi.y;
            float v10 = acc[mf][nf][2] + bi.x;
            float v11 = acc[mf][nf][3] + bi.y;
            if (GELU) {
                v00 = gelu_f(v00); v01 = gelu_f(v01);
                v10 = gelu_f(v10); v11 = gelu_f(v11);
            }
            if (RES) {
                float2 ra  = *(const float2*)&Rp[(size_t)r0 * nPart + col];
                float2 rb2 = *(const float2*)&Rp[(size_t)(r0 + 8) * nPart + col];
                v00 += ra.x; v01 += ra.y; v10 += rb2.x; v11 += rb2.y;
            }
            *(float2*)&Cp[(size_t)r0 * nPart + col] = make_float2(v00, v01);
            *(float2*)&Cp[(size_t)(r0 + 8) * nPart + col] = make_float2(v10, v11);
        }
    }
}

// ---------------------------------------------------------------------------
// Narrow GEMM (BM=32, BN=64, BK=32, 128 threads).
// ---------------------------------------------------------------------------
template <bool RES>
__global__ __launch_bounds__(128) void gemm32_tc(
    const float* __restrict__ A, const float* __restrict__ W,
    const float* __restrict__ bias, const float* __restrict__ Res,
    float* __restrict__ C, int M, int N, int K) {
    __shared__ float As[2][32 * 36];
    __shared__ float Bs[2][32 * 72];

    const int tid = threadIdx.x;
    const int lane = tid & 31, warp = tid >> 5;
    const int g = lane >> 2, c = lane & 3;
    const int m0 = blockIdx.y << 5;
    const int n0 = blockIdx.x << 6;

    const int arow = tid >> 2, acol = (tid & 3) * 8;
    const int brow = tid >> 2, bcol = (tid & 3) * 16;
    const float* Agp = A + (size_t)(m0 + arow) * K + acol;
    const float* Bgp = W + (size_t)brow * N + n0 + bcol;

    auto stage = [&](int buf, int k0) {
        const float* ag = Agp + k0;
        float* ad = &As[buf][arow * 36 + acol];
        cp16(ad, ag);
        cp16(ad + 4, ag + 4);
        const float* bg = Bgp + (size_t)k0 * N;
        float* bd = &Bs[buf][brow * 72 + bcol];
#pragma unroll
        for (int j = 0; j < 4; ++j) cp16(bd + 4 * j, bg + 4 * j);
    };

    float acc[2][2][4] = {};
    stage(0, 0);
    cp_commit();

    const int KT = K >> 5;
    for (int kt = 0; kt < KT; ++kt) {
        const int buf = kt & 1;
        if (kt + 1 < KT) {
            stage(buf ^ 1, (kt + 1) << 5);
            cp_commit();
            cp_wait<1>();
        } else {
            cp_wait<0>();
        }
        __syncthreads();

        const float* Ab = As[buf];
        const float* Bb = Bs[buf];
#pragma unroll
        for (int kk = 0; kk < 32; kk += 8) {
            uint32_t af[2][4];
#pragma unroll
            for (int mf = 0; mf < 2; ++mf) {
                int rb = mf * 16;
                af[mf][0] = __float_as_uint(Ab[(rb + g) * 36 + kk + c]);
                af[mf][1] = __float_as_uint(Ab[(rb + g + 8) * 36 + kk + c]);
                af[mf][2] = __float_as_uint(Ab[(rb + g) * 36 + kk + c + 4]);
                af[mf][3] = __float_as_uint(Ab[(rb + g + 8) * 36 + kk + c + 4]);
            }
#pragma unroll
            for (int nf = 0; nf < 2; ++nf) {
                int nb = warp * 16 + nf * 8;
                uint32_t b0 = __float_as_uint(Bb[(kk + c) * 72 + nb + g]);
                uint32_t b1 = __float_as_uint(Bb[(kk + c + 4) * 72 + nb + g]);
                mma_tf32(acc[0][nf], af[0], b0, b1);
                mma_tf32(acc[1][nf], af[1], b0, b1);
            }
        }
        __syncthreads();
    }

#pragma unroll
    for (int mf = 0; mf < 2; ++mf) {
        int r0 = m0 + mf * 16 + g;
#pragma unroll
        for (int nf = 0; nf < 2; ++nf) {
            int col = n0 + warp * 16 + nf * 8 + 2 * c;
            float2 bi = *(const float2*)&bias[col];
            float v00 = acc[mf][nf][0] + bi.x;
            float v01 = acc[mf][nf][1] + bi.y;
            float v10 = acc[mf][nf][2] + bi.x;
            float v11 = acc[mf][nf][3] + bi.y;
            if (RES) {
                float2 ra  = *(const float2*)&Res[(size_t)r0 * N + col];
                float2 rb2 = *(const float2*)&Res[(size_t)(r0 + 8) * N + col];
                v00 += ra.x; v01 += ra.y; v10 += rb2.x; v11 += rb2.y;
            }
            *(float2*)&C[(size_t)r0 * N + col] = make_float2(v00, v01);
            *(float2*)&C[(size_t)(r0 + 8) * N + col] = make_float2(v10, v11);
        }
    }
}

// ---------------------------------------------------------------------------
// Split-K flash attention, 256 threads / 8 warps. Warp (wq, wk): wq=warp>>1
// owns q-rows [wq*16, +16); wk=warp&1 owns key-cols [wk*32, +32) for S and
// d-cols [wk*32, +32) for O. Softmax row stats reduced across the wk pair via
// small smem arrays. P aliased onto the K buffer. Dyn smem 74752 B
// (3 blocks/SM -> 24 warps/SM).
// ---------------------------------------------------------------------------
__global__ __launch_bounds__(256) void attn_tc(
    const float* __restrict__ Q, const float* __restrict__ K,
    const float* __restrict__ V, float* __restrict__ Opart,
    float* __restrict__ ml, int Sq, int Sk, int kChunk) {
    const int H = 256;
    extern __shared__ float smp[];
    float* KsBuf[2] = { smp, smp + 64 * 72 };
    float* VsBuf[2] = { smp + 2 * 64 * 72, smp + 3 * 64 * 72 };
    float* redm = smp + 4 * 64 * 72;        // [2][64]
    float* reds = redm + 128;               // [2][64]

    const int tid = threadIdx.x;
    const int lane = tid & 31, warp = tid >> 5;
    const int g = lane >> 2, c = lane & 3;
    const int wq = warp >> 1, wk = warp & 1;
    const int q0 = blockIdx.x << 6;
    const int bh = blockIdx.y;
    const int b  = bh >> 2;
    const int h0 = (bh & 3) << 6;
    const int sp = blockIdx.z;
    const int BH = gridDim.y;
    const int kOff = sp * kChunk;
    const int rb = wq << 4;                 // warp's q-row base (0..48)
    const int r0l = rb + g;                 // local rows r0l, r0l+8
    const int sr = tid >> 2;                // staging row 0..63
    const int sc = (tid & 3) << 4;          // staging col base 0/16/32/48

    const float* Kb = K + (size_t)b * Sk * H + h0;
    const float* Vb = V + (size_t)b * Sk * H + h0;

    // ---- stage Q (RNA tf32) into KsBuf[0], build register fragments ----
    {
        const float* qp = Q + ((size_t)(b * Sq + q0 + sr)) * H + h0 + sc;
        float* qd = &KsBuf[0][sr * 72 + sc];
#pragma unroll
        for (int t = 0; t < 4; ++t)
            *(float4*)(qd + 4 * t) = cvt4(*(const float4*)(qp + 4 * t));
    }
    __syncthreads();
    uint32_t qf[8][4];
#pragma unroll
    for (int dc = 0; dc < 8; ++dc) {
        qf[dc][0] = __float_as_uint(KsBuf[0][r0l * 72 + dc * 8 + c]);
        qf[dc][1] = __float_as_uint(KsBuf[0][(r0l + 8) * 72 + dc * 8 + c]);
        qf[dc][2] = __float_as_uint(KsBuf[0][r0l * 72 + dc * 8 + c + 4]);
        qf[dc][3] = __float_as_uint(KsBuf[0][(r0l + 8) * 72 + dc * 8 + c + 4]);
    }
    __syncthreads();

    auto stage_kv = [&](int buf, int k0) {
        const float* kg = Kb + (size_t)(k0 + sr) * H + sc;
        float* kd = &KsBuf[buf][sr * 72 + sc];
#pragma unroll
        for (int j = 0; j < 4; ++j) cp16(kd + 4 * j, kg + 4 * j);
        const float* vg = Vb + (size_t)(k0 + sr) * H + sc;
        float* vd = &VsBuf[buf][sr * 72 + sc];
#pragma unroll
        for (int j = 0; j < 4; ++j) cp16(vd + 4 * j, vg + 4 * j);
    };

    stage_kv(0, kOff);
    cp_commit();

    float mr0 = -1e30f, mr1 = -1e30f, l0 = 0.0f, l1 = 0.0f;
    float oacc[4][4] = {};

    const int T = kChunk >> 6;
    for (int t = 0; t < T; ++t) {
        const int buf = t & 1;
        if (t + 1 < T) {
            stage_kv(buf ^ 1, kOff + ((t + 1) << 6));
            cp_commit();
            cp_wait<1>();
        } else {
            cp_wait<0>();
        }
        __syncthreads();

        const float* Ks = KsBuf[buf];
        const float* Vs = VsBuf[buf];

        // ---- S chunk: 16 q-rows x 32 key-cols ----
        float sacc[4][4] = {};
#pragma unroll
        for (int dc = 0; dc < 8; ++dc) {
#pragma unroll
            for (int nt = 0; nt < 4; ++nt) {
                int nb = wk * 32 + nt * 8;
                uint32_t b0 = __float_as_uint(Ks[(nb + g) * 72 + dc * 8 + c]);
                uint32_t b1 = __float_as_uint(Ks[(nb + g) * 72 + dc * 8 + c + 4]);
                mma_tf32(sacc[nt], qf[dc], b0, b1);
            }
        }

        // ---- local row max over the warp's 32 cols ----
        const float scale = 0.125f;
        float mx0 = -1e30f, mx1 = -1e30f;
#pragma unroll
        for (int nt = 0; nt < 4; ++nt) {
            sacc[nt][0] *= scale; sacc[nt][1] *= scale;
            sacc[nt][2] *= scale; sacc[nt][3] *= scale;
            mx0 = fmaxf(mx0, fmaxf(sacc[nt][0], sacc[nt][1]));
            mx1 = fmaxf(mx1, fmaxf(sacc[nt][2], sacc[nt][3]));
        }
        mx0 = fmaxf(mx0, __shfl_xor_sync(0xffffffffu, mx0, 1));
        mx0 = fmaxf(mx0, __shfl_xor_sync(0xffffffffu, mx0, 2));
        mx1 = fmaxf(mx1, __shfl_xor_sync(0xffffffffu, mx1, 1));
        mx1 = fmaxf(mx1, __shfl_xor_sync(0xffffffffu, mx1, 2));
        if (c == 0) {
            redm[wk * 64 + r0l]     = mx0;
            redm[wk * 64 + r0l + 8] = mx1;
        }
        __syncthreads();   // all warps done with S (Ks readable as P target)

        // ---- global row max, exp, P write, local sum ----
        float* Ps = KsBuf[buf];
        float gm0 = fmaxf(redm[r0l], redm[64 + r0l]);
        float gm1 = fmaxf(redm[r0l + 8], redm[64 + r0l + 8]);
        float mn0 = fmaxf(mr0, gm0), mn1 = fmaxf(mr1, gm1);
        float corr0 = __expf(mr0 - mn0), corr1 = __expf(mr1 - mn1);
        float s0 = 0.0f, s1 = 0.0f;
#pragma unroll
        for (int nt = 0; nt < 4; ++nt) {
            float p0 = __expf(sacc[nt][0] - mn0);
            float p1 = __expf(sacc[nt][1] - mn0);
            float p2 = __expf(sacc[nt][2] - mn1);
            float p3 = __expf(sacc[nt][3] - mn1);
            s0 += p0 + p1; s1 += p2 + p3;
            int pc = wk * 32 + nt * 8 + 2 * c;
            *(float2*)&Ps[r0l * 72 + pc]       = make_float2(p0, p1);
            *(float2*)&Ps[(r0l + 8) * 72 + pc] = make_float2(p2, p3);
            oacc[nt][0] *= corr0; oacc[nt][1] *= corr0;
            oacc[nt][2] *= corr1; oacc[nt][3] *= corr1;
        }
        s0 += __shfl_xor_sync(0xffffffffu, s0, 1);
        s0 += __shfl_xor_sync(0xffffffffu, s0, 2);
        s1 += __shfl_xor_sync(0xffffffffu, s1, 1);
        s1 += __shfl_xor_sync(0xffffffffu, s1, 2);
        if (c == 0) {
            reds[wk * 64 + r0l]     = s0;
            reds[wk * 64 + r0l + 8] = s1;
        }
        __syncthreads();   // P complete (both halves), sums posted

        l0 = l0 * corr0 + reds[r0l] + reds[64 + r0l];
        l1 = l1 * corr1 + reds[r0l + 8] + reds[64 + r0l + 8];
        mr0 = mn0; mr1 = mn1;

        // ---- O chunk += P (16 x 64) @ V (64 x 32 of warp's d-cols) ----
#pragma unroll
        for (int kc = 0; kc < 8; ++kc) {
            uint32_t pa[4];
            pa[0] = __float_as_uint(Ps[r0l * 72 + kc * 8 + c]);
            pa[1] = __float_as_uint(Ps[(r0l + 8) * 72 + kc * 8 + c]);
            pa[2] = __float_as_uint(Ps[r0l * 72 + kc * 8 + c + 4]);
            pa[3] = __float_as_uint(Ps[(r0l + 8) * 72 + kc * 8 + c + 4]);
#pragma unroll
            for (int nt = 0; nt < 4; ++nt) {
                int nb = wk * 32 + nt * 8;
                uint32_t b0 = __float_as_uint(Vs[(kc * 8 + c) * 72 + nb + g]);
                uint32_t b1 = __float_as_uint(Vs[(kc * 8 + c + 4) * 72 + nb + g]);
                mma_tf32(oacc[nt], pa, b0, b1);
            }
        }
        __syncthreads();   // buf fully consumed before next cp.async
    }

    // ---- write unnormalized partial O (warp's 32 d-cols) and (m, l) ----
    size_t row0 = ((size_t)sp * BH + bh) * Sq + q0 + r0l;
    size_t row1 = row0 + 8;
    float* op0 = Opart + (row0 << 6);
    float* op1 = Opart + (row1 << 6);
#pragma unroll
    for (int nt = 0; nt < 4; ++nt) {
        int pc = wk * 32 + nt * 8 + 2 * c;
        *(float2*)&op0[pc] = make_float2(oacc[nt][0], oacc[nt][1]);
        *(float2*)&op1[pc] = make_float2(oacc[nt][2], oacc[nt][3]);
    }
    if (wk == 0 && c == 0) {
        ml[row0 * 2]     = mr0;
        ml[row0 * 2 + 1] = l0;
        ml[row1 * 2]     = mr1;
        ml[row1 * 2 + 1] = l1;
    }
}

// ---------------------------------------------------------------------------
// Split-K combine.
// ---------------------------------------------------------------------------
__global__ __launch_bounds__(256) void attn_combine(
    const float* __restrict__ Opart, const float* __restrict__ ml,
    float* __restrict__ Ctx, int Sq, int nSplit) {
    const int BH = gridDim.y;
    const int bh = blockIdx.y;
    const int b = bh >> 2, h0 = (bh & 3) << 6;
    const int q = (blockIdx.x << 6) + (threadIdx.x >> 2);
    const int c0 = (threadIdx.x & 3) << 4;
    const size_t slab = (size_t)BH * Sq;
    const size_t rbase = (size_t)bh * Sq + q;

    float M = -1e30f;
    for (int sp = 0; sp < nSplit; ++sp)
        M = fmaxf(M, ml[(sp * slab + rbase) * 2]);

    float L = 0.0f;
    float4 a[4] = {{0,0,0,0},{0,0,0,0},{0,0,0,0},{0,0,0,0}};
    for (int sp = 0; sp < nSplit; ++sp) {
        size_t r = sp * slab + rbase;
        float w = __expf(ml[r * 2] - M);
        L += w * ml[r * 2 + 1];
        const float* p = Opart + (r << 6) + c0;
#pragma unroll
        for (int j = 0; j < 4; ++j) {
            float4 v = *(const float4*)(p + 4 * j);
            a[j].x += w * v.x; a[j].y += w * v.y;
            a[j].z += w * v.z; a[j].w += w * v.w;
        }
    }
    float inv = 1.0f / L;
    float* o = Ctx + ((size_t)(b * Sq + q)) * 256 + h0 + c0;
#pragma unroll
    for (int j = 0; j < 4; ++j)
        *(float4*)(o + 4 * j) = make_float4(a[j].x * inv, a[j].y * inv,
                                            a[j].z * inv, a[j].w * inv);
}

// ---------------------------------------------------------------------------
// LayerNorm over last dim (H=256). Warp per row.
// ---------------------------------------------------------------------------
__global__ __launch_bounds__(256) void ln_kernel(
    const float* __restrict__ in, const float* __restrict__ gamma,
    const float* __restrict__ beta, float* __restrict__ out) {
    const int warp = threadIdx.x >> 5, lane = threadIdx.x & 31;
    const size_t row = (size_t)blockIdx.x * 8 + warp;
    const float* p = in + row * 256 + lane * 8;
    float4 a = *(const float4*)p;
    float4 b = *(const float4*)(p + 4);

    float s = (a.x + a.y) + (a.z + a.w) + (b.x + b.y) + (b.z + b.w);
#pragma unroll
    for (int off = 16; off > 0; off >>= 1)
        s += __shfl_xor_sync(0xffffffffu, s, off);
    float mu = s * (1.0f / 256.0f);

    float dx = a.x - mu, dy = a.y - mu, dz = a.z - mu, dw = a.w - mu;
    float ex = b.x - mu, ey = b.y - mu, ez = b.z - mu, ew = b.w - mu;
    float q = dx * dx + dy * dy + dz * dz + dw * dw +
              ex * ex + ey * ey + ez * ez + ew * ew;
#pragma unroll
    for (int off = 16; off > 0; off >>= 1)
        q += __shfl_xor_sync(0xffffffffu, q, off);
    float inv = rsqrtf(q * (1.0f / 256.0f) + 1e-12f);

    float4 ga = *(const float4*)&gamma[lane * 8];
    float4 gb = *(const float4*)&gamma[lane * 8 + 4];
    float4 ba = *(const float4*)&beta[lane * 8];
    float4 bb = *(const float4*)&beta[lane * 8 + 4];
    float* o = out + row * 256 + lane * 8;
    *(float4*)o = make_float4(dx * inv * ga.x + ba.x, dy * inv * ga.y + ba.y,
                              dz * inv * ga.z + ba.z, dw * inv * ga.w + ba.w);
    *(float4*)(o + 4) = make_float4(ex * inv * gb.x + bb.x, ey * inv * gb.y + bb.y,
                                    ez * inv * gb.z + bb.z, ew * inv * gb.w + bb.w);
}

// ---------------------------------------------------------------------------
// Orchestration
// ---------------------------------------------------------------------------
extern "C" void kernel_launch(void* const* d_in, const int* in_sizes, int n_in,
                              void* d_out, int out_size) {
    const float* x      = (const float*)d_in[0];
    const float* y      = (const float*)d_in[1];
    const float* pos    = (const float*)d_in[2];
    const float* sqkvw  = (const float*)d_in[3];
    const float* sqkvb  = (const float*)d_in[4];
    const float* sow    = (const float*)d_in[5];
    const float* sob    = (const float*)d_in[6];
    const float* cqkvw  = (const float*)d_in[7];
    const float* cqkvb  = (const float*)d_in[8];
    const float* cow    = (const float*)d_in[9];
    const float* cob    = (const float*)d_in[10];
    const float* fw1    = (const float*)d_in[11];
    const float* fb1    = (const float*)d_in[12];
    const float* fw2    = (const float*)d_in[13];
    const float* fb2    = (const float*)d_in[14];
    const float* lng    = (const float*)d_in[15];
    const float* lnb    = (const float*)d_in[16];
    float* out = (float*)d_out;

    const int B = C_B, Se = C_SE, Sd = C_SD, H = C_H, F = C_F, L = C_L, NH = C_NH;
    const int Md = B * Sd;   // 4096
    const int Me = B * Se;   // 8192
    const int ATTN_SMEM = (4 * 64 * 72 + 256) * 4;   // 74752 B

    static bool attr_set = false;
    if (!attr_set) {
        cudaFuncSetAttribute(attn_tc, cudaFuncAttributeMaxDynamicSharedMemorySize,
                             ATTN_SMEM);
        attr_set = true;
    }

    float *xenc, *h, *qkv, *q, *kv, *ctx, *tmp, *ffn, *opart, *ml;
    cudaGetSymbolAddress((void**)&xenc,  g_xenc);
    cudaGetSymbolAddress((void**)&h,     g_h);
    cudaGetSymbolAddress((void**)&qkv,   g_qkv);
    cudaGetSymbolAddress((void**)&q,     g_q);
    cudaGetSymbolAddress((void**)&kv,    g_kv);
    cudaGetSymbolAddress((void**)&ctx,   g_ctx);
    cudaGetSymbolAddress((void**)&tmp,   g_tmp);
    cudaGetSymbolAddress((void**)&ffn,   g_ffn);
    cudaGetSymbolAddress((void**)&opart, g_opart);
    cudaGetSymbolAddress((void**)&ml,    g_ml);

    {
        int total = B * Se * H;
        add_pos_kernel<<<(total + 255) / 256, 256>>>(x, pos, xenc, total, Se * H);
    }
    cudaMemcpyAsync(h, y, sizeof(float) * (size_t)Md * H, cudaMemcpyDeviceToDevice);

    const dim3 blk(128);
    const dim3 blkA(256);
    const dim3 gSelfQKV(768 / 64, Md / 64);
    const dim3 gProj32(256 / 64, Md / 32);
    const dim3 gCrossKV(512 / 64, Me / 64);
    const dim3 gFfn1(1024 / 64, Md / 64);
    const dim3 gAttnSelf(Sd / 64, B * NH, 4);     // kChunk=512,  1024 blocks
    const dim3 gAttnCross(Sd / 64, B * NH, 4);    // kChunk=1024, 1024 blocks
    const dim3 gComb(Sd / 64, B * NH);

    for (int i = 0; i < L; ++i) {
        const float* sw  = sqkvw + (size_t)i * 3 * H * H;
        const float* sb  = sqkvb + (size_t)i * 3 * H;
        const float* sOw = sow + (size_t)i * H * H;
        const float* sOb = sob + (size_t)i * H;
        const float* cw  = cqkvw + (size_t)i * 3 * H * H;
        const float* cb  = cqkvb + (size_t)i * 3 * H;
        const float* cOw = cow + (size_t)i * H * H;
        const float* cOb = cob + (size_t)i * H;
        const float* w1  = fw1 + (size_t)i * H * F;
        const float* b1  = fb1 + (size_t)i * F;
        const float* w2  = fw2 + (size_t)i * F * H;
        const float* b2  = fb2 + (size_t)i * H;

        // ---- self attention ----
        gemm_tc<false, false><<<gSelfQKV, blk>>>(h, sw, sb, nullptr, qkv,
                                                 Md, 768, H, 256);
        attn_tc<<<gAttnSelf, blkA, ATTN_SMEM>>>(qkv, qkv + (size_t)Md * H,
                                                qkv + (size_t)2 * Md * H,
                                                opart, ml, Sd, Sd, 512);
        attn_combine<<<gComb, 256>>>(opart, ml, ctx, Sd, 4);
        gemm32_tc<true><<<gProj32, blk>>>(ctx, sOw, sOb, h, tmp, Md, 256, 256);
        ln_kernel<<<Md / 8, 256>>>(tmp, lng + (size_t)(i * 3 + 0) * H,
                                   lnb + (size_t)(i * 3 + 0) * H, h);

        // ---- cross attention ----
        gemm32_tc<false><<<gProj32, blk>>>(h, cw, cb, nullptr, q, Md, 256, 256);
        gemm_tc<false, false><<<gCrossKV, blk>>>(xenc, cw + (size_t)H * H, cb + H,
                                                 nullptr, kv, Me, 512, H, 256);
        attn_tc<<<gAttnCross, blkA, ATTN_SMEM>>>(q, kv, kv + (size_t)Me * H,
                                                 opart, ml, Sd, Se, 1024);
        attn_combine<<<gComb, 256>>>(opart, ml, ctx, Sd, 4);
        gemm32_tc<true><<<gProj32, blk>>>(ctx, cOw, cOb, h, tmp, Md, 256, 256);
        ln_kernel<<<Md / 8, 256>>>(tmp, lng + (size_t)(i * 3 + 1) * H,
                                   lnb + (size_t)(i * 3 + 1) * H, h);

        // ---- FFN ----
        gemm_tc<true, false><<<gFfn1, blk>>>(h, w1, b1, nullptr, ffn,
                                             Md, 1024, H, 1024);
        gemm32_tc<true><<<gProj32, blk>>>(ffn, w2, b2, h, tmp, Md, 256, 1024);
        ln_kernel<<<Md / 8, 256>>>(tmp, lng + (size_t)(i * 3 + 2) * H,
                                   lnb + (size_t)(i * 3 + 2) * H,
                                   (i == L - 1) ? out : h);
    }
}

// round 10
// speedup vs baseline: 1.2202x; 1.1338x over previous
#include <cuda_runtime.h>
#include <math.h>
#include <stdint.h>

// ---------------------------------------------------------------------------
// Problem constants: B=2, Se=4096, Sd=2048, H=256, NH=4, hd=64, F=1024, L=6
// ---------------------------------------------------------------------------
#define C_B   2
#define C_SE  4096
#define C_SD  2048
#define C_H   256
#define C_NH  4
#define C_F   1024
#define C_L   6

// ---------------------------------------------------------------------------
// Scratch (device globals; no allocations allowed)
// ---------------------------------------------------------------------------
__device__ float g_xenc [C_B * C_SE * C_H];
__device__ float g_h    [C_B * C_SD * C_H];
__device__ float g_qkv  [3 * C_B * C_SD * C_H];
__device__ float g_q    [C_B * C_SD * C_H];
__device__ float g_kv6  [C_L * 2 * C_B * C_SE * C_H];   // per-layer cross K,V
__device__ float g_ctx  [C_B * C_SD * C_H];
__device__ float g_tmp  [C_B * C_SD * C_H];
__device__ float g_ffn  [C_B * C_SD * C_F];
__device__ float g_opart[4 * 8 * C_SD * 64];            // split-K partial O
__device__ float g_ml   [4 * 8 * C_SD * 2];             // split-K (m, l)

// ---------------------------------------------------------------------------
// tf32 mma (m16n8k8 row.col f32 accum), cp.async helpers
// ---------------------------------------------------------------------------
__device__ __forceinline__ uint32_t f2tf(float x) {
    uint32_t u;
    asm("cvt.rna.tf32.f32 %0, %1;" : "=r"(u) : "f"(x));
    return u;
}
__device__ __forceinline__ float4 cvt4(float4 v) {
    return make_float4(__uint_as_float(f2tf(v.x)), __uint_as_float(f2tf(v.y)),
                       __uint_as_float(f2tf(v.z)), __uint_as_float(f2tf(v.w)));
}
__device__ __forceinline__ void mma_tf32(float* c, const uint32_t* a,
                                         uint32_t b0, uint32_t b1) {
    asm volatile(
        "mma.sync.aligned.m16n8k8.row.col.f32.tf32.tf32.f32 "
        "{%0,%1,%2,%3}, {%4,%5,%6,%7}, {%8,%9}, {%0,%1,%2,%3};"
        : "+f"(c[0]), "+f"(c[1]), "+f"(c[2]), "+f"(c[3])
        : "r"(a[0]), "r"(a[1]), "r"(a[2]), "r"(a[3]), "r"(b0), "r"(b1));
}
__device__ __forceinline__ void cp16(float* dst_smem, const float* src) {
    uint32_t d = (uint32_t)__cvta_generic_to_shared(dst_smem);
    asm volatile("cp.async.cg.shared.global [%0], [%1], 16;" :: "r"(d), "l"(src));
}
__device__ __forceinline__ void cp_commit() {
    asm volatile("cp.async.commit_group;");
}
template <int N>
__device__ __forceinline__ void cp_wait() {
    asm volatile("cp.async.wait_group %0;" :: "n"(N));
}

// ---------------------------------------------------------------------------
// x_enc = x + pos_embed
// ---------------------------------------------------------------------------
__global__ void add_pos_kernel(const float* __restrict__ x,
                               const float* __restrict__ pos,
                               float* __restrict__ out, int total, int seh) {
    int i = blockIdx.x * blockDim.x + threadIdx.x;
    if (i < total) out[i] = x[i] + pos[i % seh];
}

__device__ __forceinline__ float gelu_f(float x) {
    float x3 = x * x * x;
    return 0.5f * x * (1.0f + tanhf(0.7978845608028654f * (x + 0.044715f * x3)));
}

// ---------------------------------------------------------------------------
// Tensor-core GEMM (BM=64, BN=64, BK=32, 128 threads, 2x2 warp tiles).
// ---------------------------------------------------------------------------
template <bool GELU, bool RES>
__global__ __launch_bounds__(128) void gemm_tc(
    const float* __restrict__ A, const float* __restrict__ W,
    const float* __restrict__ bias, const float* __restrict__ Res,
    float* __restrict__ C, int M, int N, int K, int nPart) {
    __shared__ float As[2][64 * 36];
    __shared__ float Bs[2][32 * 72];

    const int tid = threadIdx.x;
    const int lane = tid & 31, warp = tid >> 5;
    const int g = lane >> 2, c = lane & 3;
    const int wm = warp >> 1, wn = warp & 1;
    const int m0 = blockIdx.y << 6;
    const int n0 = blockIdx.x << 6;
    const int part = n0 / nPart;
    const int nc = n0 - part * nPart;
    const float* Wp = W + (size_t)part * K * nPart + nc;

    const int arow = tid >> 1, acol = (tid & 1) * 16;
    const int brow = tid >> 2, bcol = (tid & 3) * 16;
    const float* Agp = A + (size_t)(m0 + arow) * K + acol;
    const float* Bgp = Wp + (size_t)brow * nPart + bcol;

    auto stage = [&](int buf, int k0) {
        const float* ag = Agp + k0;
        float* ad = &As[buf][arow * 36 + acol];
#pragma unroll
        for (int j = 0; j < 4; ++j) cp16(ad + 4 * j, ag + 4 * j);
        const float* bg = Bgp + (size_t)k0 * nPart;
        float* bd = &Bs[buf][brow * 72 + bcol];
#pragma unroll
        for (int j = 0; j < 4; ++j) cp16(bd + 4 * j, bg + 4 * j);
    };

    float acc[2][4][4] = {};
    stage(0, 0);
    cp_commit();

    const int KT = K >> 5;
    for (int kt = 0; kt < KT; ++kt) {
        const int buf = kt & 1;
        if (kt + 1 < KT) {
            stage(buf ^ 1, (kt + 1) << 5);
            cp_commit();
            cp_wait<1>();
        } else {
            cp_wait<0>();
        }
        __syncthreads();

        const float* Ab = As[buf];
        const float* Bb = Bs[buf];
#pragma unroll
        for (int kk = 0; kk < 32; kk += 8) {
            uint32_t af[2][4];
#pragma unroll
            for (int mf = 0; mf < 2; ++mf) {
                int rb = wm * 32 + mf * 16;
                af[mf][0] = __float_as_uint(Ab[(rb + g) * 36 + kk + c]);
                af[mf][1] = __float_as_uint(Ab[(rb + g + 8) * 36 + kk + c]);
                af[mf][2] = __float_as_uint(Ab[(rb + g) * 36 + kk + c + 4]);
                af[mf][3] = __float_as_uint(Ab[(rb + g + 8) * 36 + kk + c + 4]);
            }
#pragma unroll
            for (int nf = 0; nf < 4; ++nf) {
                int nb = wn * 32 + nf * 8;
                uint32_t b0 = __float_as_uint(Bb[(kk + c) * 72 + nb + g]);
                uint32_t b1 = __float_as_uint(Bb[(kk + c + 4) * 72 + nb + g]);
                mma_tf32(acc[0][nf], af[0], b0, b1);
                mma_tf32(acc[1][nf], af[1], b0, b1);
            }
        }
        __syncthreads();
    }

    const float* bp = bias + (size_t)part * nPart;
    float* Cp = C + (size_t)part * M * nPart;
    const float* Rp = RES ? (Res + (size_t)part * M * nPart) : nullptr;
#pragma unroll
    for (int mf = 0; mf < 2; ++mf) {
        int r0 = m0 + wm * 32 + mf * 16 + g;
#pragma unroll
        for (int nf = 0; nf < 4; ++nf) {
            int col = nc + wn * 32 + nf * 8 + 2 * c;
            float2 bi = *(const float2*)&bp[col];
            float v00 = acc[mf][nf][0] + bi.x;
            float v01 = acc[mf][nf][1] + bi.y;
            float v10 = acc[mf][nf][2] + bi.x;
            float v11 = acc[mf][nf][3] + bi.y;
            if (GELU) {
                v00 = gelu_f(v00); v01 = gelu_f(v01);
                v10 = gelu_f(v10); v11 = gelu_f(v11);
            }
            if (RES) {
                float2 ra  = *(const float2*)&Rp[(size_t)r0 * nPart + col];
                float2 rb2 = *(const float2*)&Rp[(size_t)(r0 + 8) * nPart + col];
                v00 += ra.x; v01 += ra.y; v10 += rb2.x; v11 += rb2.y;
            }
            *(float2*)&Cp[(size_t)r0 * nPart + col] = make_float2(v00, v01);
            *(float2*)&Cp[(size_t)(r0 + 8) * nPart + col] = make_float2(v10, v11);
        }
    }
}

// ---------------------------------------------------------------------------
// Narrow GEMM (BM=32, BN=64, BK=32, 128 threads).
// ---------------------------------------------------------------------------
template <bool RES>
__global__ __launch_bounds__(128) void gemm32_tc(
    const float* __restrict__ A, const float* __restrict__ W,
    const float* __restrict__ bias, const float* __restrict__ Res,
    float* __restrict__ C, int M, int N, int K) {
    __shared__ float As[2][32 * 36];
    __shared__ float Bs[2][32 * 72];

    const int tid = threadIdx.x;
    const int lane = tid & 31, warp = tid >> 5;
    const int g = lane >> 2, c = lane & 3;
    const int m0 = blockIdx.y << 5;
    const int n0 = blockIdx.x << 6;

    const int arow = tid >> 2, acol = (tid & 3) * 8;
    const int brow = tid >> 2, bcol = (tid & 3) * 16;
    const float* Agp = A + (size_t)(m0 + arow) * K + acol;
    const float* Bgp = W + (size_t)brow * N + n0 + bcol;

    auto stage = [&](int buf, int k0) {
        const float* ag = Agp + k0;
        float* ad = &As[buf][arow * 36 + acol];
        cp16(ad, ag);
        cp16(ad + 4, ag + 4);
        const float* bg = Bgp + (size_t)k0 * N;
        float* bd = &Bs[buf][brow * 72 + bcol];
#pragma unroll
        for (int j = 0; j < 4; ++j) cp16(bd + 4 * j, bg + 4 * j);
    };

    float acc[2][2][4] = {};
    stage(0, 0);
    cp_commit();

    const int KT = K >> 5;
    for (int kt = 0; kt < KT; ++kt) {
        const int buf = kt & 1;
        if (kt + 1 < KT) {
            stage(buf ^ 1, (kt + 1) << 5);
            cp_commit();
            cp_wait<1>();
        } else {
            cp_wait<0>();
        }
        __syncthreads();

        const float* Ab = As[buf];
        const float* Bb = Bs[buf];
#pragma unroll
        for (int kk = 0; kk < 32; kk += 8) {
            uint32_t af[2][4];
#pragma unroll
            for (int mf = 0; mf < 2; ++mf) {
                int rb = mf * 16;
                af[mf][0] = __float_as_uint(Ab[(rb + g) * 36 + kk + c]);
                af[mf][1] = __float_as_uint(Ab[(rb + g + 8) * 36 + kk + c]);
                af[mf][2] = __float_as_uint(Ab[(rb + g) * 36 + kk + c + 4]);
                af[mf][3] = __float_as_uint(Ab[(rb + g + 8) * 36 + kk + c + 4]);
            }
#pragma unroll
            for (int nf = 0; nf < 2; ++nf) {
                int nb = warp * 16 + nf * 8;
                uint32_t b0 = __float_as_uint(Bb[(kk + c) * 72 + nb + g]);
                uint32_t b1 = __float_as_uint(Bb[(kk + c + 4) * 72 + nb + g]);
                mma_tf32(acc[0][nf], af[0], b0, b1);
                mma_tf32(acc[1][nf], af[1], b0, b1);
            }
        }
        __syncthreads();
    }

#pragma unroll
    for (int mf = 0; mf < 2; ++mf) {
        int r0 = m0 + mf * 16 + g;
#pragma unroll
        for (int nf = 0; nf < 2; ++nf) {
            int col = n0 + warp * 16 + nf * 8 + 2 * c;
            float2 bi = *(const float2*)&bias[col];
            float v00 = acc[mf][nf][0] + bi.x;
            float v01 = acc[mf][nf][1] + bi.y;
            float v10 = acc[mf][nf][2] + bi.x;
            float v11 = acc[mf][nf][3] + bi.y;
            if (RES) {
                float2 ra  = *(const float2*)&Res[(size_t)r0 * N + col];
                float2 rb2 = *(const float2*)&Res[(size_t)(r0 + 8) * N + col];
                v00 += ra.x; v01 += ra.y; v10 += rb2.x; v11 += rb2.y;
            }
            *(float2*)&C[(size_t)r0 * N + col] = make_float2(v00, v01);
            *(float2*)&C[(size_t)(r0 + 8) * N + col] = make_float2(v10, v11);
        }
    }
}

// ---------------------------------------------------------------------------
// Split-K flash attention, 256 threads / 8 warps, q-tile 128.
// Warp w owns q-rows [16w, 16w+16) over ALL 64 keys of each tile:
//  - softmax row stats are intra-quad shuffles only (no cross-warp smem)
//  - P stays in registers; S C-fragments are remapped to PV A-fragments by
//    intra-quad shuffles (exact lane permutation)
//  - 2 syncthreads per tile (cp.async double-buffer hazards only)
// Dynamic smem: 4*64*72*4 = 73728 B. __launch_bounds__(256,2).
// ---------------------------------------------------------------------------
__global__ __launch_bounds__(256, 2) void attn_tc(
    const float* __restrict__ Q, const float* __restrict__ K,
    const float* __restrict__ V, float* __restrict__ Opart,
    float* __restrict__ ml, int Sq, int Sk, int kChunk) {
    const int H = 256;
    extern __shared__ float smp[];
    float* KsBuf[2] = { smp, smp + 64 * 72 };
    float* VsBuf[2] = { smp + 2 * 64 * 72, smp + 3 * 64 * 72 };

    const int tid = threadIdx.x;
    const int lane = tid & 31, warp = tid >> 5;
    const int g = lane >> 2, c = lane & 3;
    const int q0 = blockIdx.x << 7;          // 128 q rows per block
    const int bh = blockIdx.y;
    const int b  = bh >> 2;
    const int h0 = (bh & 3) << 6;
    const int sp = blockIdx.z;
    const int BH = gridDim.y;
    const int kOff = sp * kChunk;
    const int rql = (warp << 4) + g;         // local q row (0..127)
    const int sr = tid >> 2;                 // staging row 0..63
    const int sc = (tid & 3) << 4;           // staging col base

    const float* Kb = K + (size_t)b * Sk * H + h0;
    const float* Vb = V + (size_t)b * Sk * H + h0;

    // ---- stage 128 Q rows (RNA tf32) across KsBuf[0..1], build fragments ----
#pragma unroll
    for (int half = 0; half < 2; ++half) {
        const float* qp = Q + ((size_t)(b * Sq + q0 + half * 64 + sr)) * H + h0 + sc;
        float* qd = &smp[half * 64 * 72 + sr * 72 + sc];
#pragma unroll
        for (int t = 0; t < 4; ++t)
            *(float4*)(qd + 4 * t) = cvt4(*(const float4*)(qp + 4 * t));
    }
    __syncthreads();
    uint32_t qf[8][4];
#pragma unroll
    for (int dc = 0; dc < 8; ++dc) {
        qf[dc][0] = __float_as_uint(smp[rql * 72 + dc * 8 + c]);
        qf[dc][1] = __float_as_uint(smp[(rql + 8) * 72 + dc * 8 + c]);
        qf[dc][2] = __float_as_uint(smp[rql * 72 + dc * 8 + c + 4]);
        qf[dc][3] = __float_as_uint(smp[(rql + 8) * 72 + dc * 8 + c + 4]);
    }
    __syncthreads();

    auto stage_kv = [&](int buf, int k0) {
        const float* kg = Kb + (size_t)(k0 + sr) * H + sc;
        float* kd = &KsBuf[buf][sr * 72 + sc];
#pragma unroll
        for (int j = 0; j < 4; ++j) cp16(kd + 4 * j, kg + 4 * j);
        const float* vg = Vb + (size_t)(k0 + sr) * H + sc;
        float* vd = &VsBuf[buf][sr * 72 + sc];
#pragma unroll
        for (int j = 0; j < 4; ++j) cp16(vd + 4 * j, vg + 4 * j);
    };

    stage_kv(0, kOff);
    cp_commit();

    float mr0 = -1e30f, mr1 = -1e30f, l0 = 0.0f, l1 = 0.0f;
    float oacc[8][4] = {};

    const int T = kChunk >> 6;
    for (int t = 0; t < T; ++t) {
        const int buf = t & 1;
        if (t + 1 < T) {
            stage_kv(buf ^ 1, kOff + ((t + 1) << 6));
            cp_commit();
            cp_wait<1>();
        } else {
            cp_wait<0>();
        }
        __syncthreads();

        const float* Ks = KsBuf[buf];
        const float* Vs = VsBuf[buf];

        // ---- S = Q @ K^T : 16 q-rows x 64 keys per warp ----
        float sacc[8][4] = {};
#pragma unroll
        for (int dc = 0; dc < 8; ++dc) {
#pragma unroll
            for (int nt = 0; nt < 8; ++nt) {
                uint32_t b0 = __float_as_uint(Ks[(nt * 8 + g) * 72 + dc * 8 + c]);
                uint32_t b1 = __float_as_uint(Ks[(nt * 8 + g) * 72 + dc * 8 + c + 4]);
                mma_tf32(sacc[nt], qf[dc], b0, b1);
            }
        }

        // ---- online softmax, fully in registers (quad shuffles) ----
        const float scale = 0.125f;
        float mx0 = -1e30f, mx1 = -1e30f;
#pragma unroll
        for (int nt = 0; nt < 8; ++nt) {
            sacc[nt][0] *= scale; sacc[nt][1] *= scale;
            sacc[nt][2] *= scale; sacc[nt][3] *= scale;
            mx0 = fmaxf(mx0, fmaxf(sacc[nt][0], sacc[nt][1]));
            mx1 = fmaxf(mx1, fmaxf(sacc[nt][2], sacc[nt][3]));
        }
        mx0 = fmaxf(mx0, __shfl_xor_sync(0xffffffffu, mx0, 1));
        mx0 = fmaxf(mx0, __shfl_xor_sync(0xffffffffu, mx0, 2));
        mx1 = fmaxf(mx1, __shfl_xor_sync(0xffffffffu, mx1, 1));
        mx1 = fmaxf(mx1, __shfl_xor_sync(0xffffffffu, mx1, 2));
        float mn0 = fmaxf(mr0, mx0), mn1 = fmaxf(mr1, mx1);
        float corr0 = __expf(mr0 - mn0), corr1 = __expf(mr1 - mn1);
        float s0 = 0.0f, s1 = 0.0f;
#pragma unroll
        for (int nt = 0; nt < 8; ++nt) {
            sacc[nt][0] = __expf(sacc[nt][0] - mn0);
            sacc[nt][1] = __expf(sacc[nt][1] - mn0);
            sacc[nt][2] = __expf(sacc[nt][2] - mn1);
            sacc[nt][3] = __expf(sacc[nt][3] - mn1);
            s0 += sacc[nt][0] + sacc[nt][1];
            s1 += sacc[nt][2] + sacc[nt][3];
            oacc[nt][0] *= corr0; oacc[nt][1] *= corr0;
            oacc[nt][2] *= corr1; oacc[nt][3] *= corr1;
        }
        s0 += __shfl_xor_sync(0xffffffffu, s0, 1);
        s0 += __shfl_xor_sync(0xffffffffu, s0, 2);
        s1 += __shfl_xor_sync(0xffffffffu, s1, 1);
        s1 += __shfl_xor_sync(0xffffffffu, s1, 2);
        l0 = l0 * corr0 + s0;
        l1 = l1 * corr1 + s1;
        mr0 = mn0; mr1 = mn1;

        // ---- O += P @ V, P remapped C-frag -> A-frag via quad shuffles ----
        const int srcA = (lane & ~3) | (c >> 1);
        const int srcB = srcA + 2;
        const bool odd = (c & 1);
#pragma unroll
        for (int kc = 0; kc < 8; ++kc) {
            float t0 = __shfl_sync(0xffffffffu, sacc[kc][0], srcA);
            float t1 = __shfl_sync(0xffffffffu, sacc[kc][1], srcA);
            float t2 = __shfl_sync(0xffffffffu, sacc[kc][2], srcA);
            float t3 = __shfl_sync(0xffffffffu, sacc[kc][3], srcA);
            float u0 = __shfl_sync(0xffffffffu, sacc[kc][0], srcB);
            float u1 = __shfl_sync(0xffffffffu, sacc[kc][1], srcB);
            float u2 = __shfl_sync(0xffffffffu, sacc[kc][2], srcB);
            float u3 = __shfl_sync(0xffffffffu, sacc[kc][3], srcB);
            uint32_t pa[4];
            pa[0] = __float_as_uint(odd ? t1 : t0);
            pa[1] = __float_as_uint(odd ? t3 : t2);
            pa[2] = __float_as_uint(odd ? u1 : u0);
            pa[3] = __float_as_uint(odd ? u3 : u2);
#pragma unroll
            for (int nt = 0; nt < 8; ++nt) {
                uint32_t b0 = __float_as_uint(Vs[(kc * 8 + c) * 72 + nt * 8 + g]);
                uint32_t b1 = __float_as_uint(Vs[(kc * 8 + c + 4) * 72 + nt * 8 + g]);
                mma_tf32(oacc[nt], pa, b0, b1);
            }
        }
        __syncthreads();   // buf fully consumed before next cp.async overwrite
    }

    // ---- write unnormalized partial O and (m, l) ----
    size_t row0 = ((size_t)sp * BH + bh) * Sq + q0 + rql;
    size_t row1 = row0 + 8;
    float* op0 = Opart + (row0 << 6);
    float* op1 = Opart + (row1 << 6);
#pragma unroll
    for (int nt = 0; nt < 8; ++nt) {
        *(float2*)&op0[nt * 8 + 2 * c] = make_float2(oacc[nt][0], oacc[nt][1]);
        *(float2*)&op1[nt * 8 + 2 * c] = make_float2(oacc[nt][2], oacc[nt][3]);
    }
    if (c == 0) {
        ml[row0 * 2]     = mr0;
        ml[row0 * 2 + 1] = l0;
        ml[row1 * 2]     = mr1;
        ml[row1 * 2 + 1] = l1;
    }
}

// ---------------------------------------------------------------------------
// Split-K combine.
// ---------------------------------------------------------------------------
__global__ __launch_bounds__(256) void attn_combine(
    const float* __restrict__ Opart, const float* __restrict__ ml,
    float* __restrict__ Ctx, int Sq, int nSplit) {
    const int BH = gridDim.y;
    const int bh = blockIdx.y;
    const int b = bh >> 2, h0 = (bh & 3) << 6;
    const int q = (blockIdx.x << 6) + (threadIdx.x >> 2);
    const int c0 = (threadIdx.x & 3) << 4;
    const size_t slab = (size_t)BH * Sq;
    const size_t rbase = (size_t)bh * Sq + q;

    float M = -1e30f;
    for (int sp = 0; sp < nSplit; ++sp)
        M = fmaxf(M, ml[(sp * slab + rbase) * 2]);

    float L = 0.0f;
    float4 a[4] = {{0,0,0,0},{0,0,0,0},{0,0,0,0},{0,0,0,0}};
    for (int sp = 0; sp < nSplit; ++sp) {
        size_t r = sp * slab + rbase;
        float w = __expf(ml[r * 2] - M);
        L += w * ml[r * 2 + 1];
        const float* p = Opart + (r << 6) + c0;
#pragma unroll
        for (int j = 0; j < 4; ++j) {
            float4 v = *(const float4*)(p + 4 * j);
            a[j].x += w * v.x; a[j].y += w * v.y;
            a[j].z += w * v.z; a[j].w += w * v.w;
        }
    }
    float inv = 1.0f / L;
    float* o = Ctx + ((size_t)(b * Sq + q)) * 256 + h0 + c0;
#pragma unroll
    for (int j = 0; j < 4; ++j)
        *(float4*)(o + 4 * j) = make_float4(a[j].x * inv, a[j].y * inv,
                                            a[j].z * inv, a[j].w * inv);
}

// ---------------------------------------------------------------------------
// LayerNorm over last dim (H=256). Warp per row.
// ---------------------------------------------------------------------------
__global__ __launch_bounds__(256) void ln_kernel(
    const float* __restrict__ in, const float* __restrict__ gamma,
    const float* __restrict__ beta, float* __restrict__ out) {
    const int warp = threadIdx.x >> 5, lane = threadIdx.x & 31;
    const size_t row = (size_t)blockIdx.x * 8 + warp;
    const float* p = in + row * 256 + lane * 8;
    float4 a = *(const float4*)p;
    float4 b = *(const float4*)(p + 4);

    float s = (a.x + a.y) + (a.z + a.w) + (b.x + b.y) + (b.z + b.w);
#pragma unroll
    for (int off = 16; off > 0; off >>= 1)
        s += __shfl_xor_sync(0xffffffffu, s, off);
    float mu = s * (1.0f / 256.0f);

    float dx = a.x - mu, dy = a.y - mu, dz = a.z - mu, dw = a.w - mu;
    float ex = b.x - mu, ey = b.y - mu, ez = b.z - mu, ew = b.w - mu;
    float q = dx * dx + dy * dy + dz * dz + dw * dw +
              ex * ex + ey * ey + ez * ez + ew * ew;
#pragma unroll
    for (int off = 16; off > 0; off >>= 1)
        q += __shfl_xor_sync(0xffffffffu, q, off);
    float inv = rsqrtf(q * (1.0f / 256.0f) + 1e-12f);

    float4 ga = *(const float4*)&gamma[lane * 8];
    float4 gb = *(const float4*)&gamma[lane * 8 + 4];
    float4 ba = *(const float4*)&beta[lane * 8];
    float4 bb = *(const float4*)&beta[lane * 8 + 4];
    float* o = out + row * 256 + lane * 8;
    *(float4*)o = make_float4(dx * inv * ga.x + ba.x, dy * inv * ga.y + ba.y,
                              dz * inv * ga.z + ba.z, dw * inv * ga.w + ba.w);
    *(float4*)(o + 4) = make_float4(ex * inv * gb.x + bb.x, ey * inv * gb.y + bb.y,
                                    ez * inv * gb.z + bb.z, ew * inv * gb.w + bb.w);
}

// ---------------------------------------------------------------------------
// Orchestration. Cross-KV projections depend only on xenc: they run on a
// forked stream and are joined per-layer via events.
// ---------------------------------------------------------------------------
extern "C" void kernel_launch(void* const* d_in, const int* in_sizes, int n_in,
                              void* d_out, int out_size) {
    const float* x      = (const float*)d_in[0];
    const float* y      = (const float*)d_in[1];
    const float* pos    = (const float*)d_in[2];
    const float* sqkvw  = (const float*)d_in[3];
    const float* sqkvb  = (const float*)d_in[4];
    const float* sow    = (const float*)d_in[5];
    const float* sob    = (const float*)d_in[6];
    const float* cqkvw  = (const float*)d_in[7];
    const float* cqkvb  = (const float*)d_in[8];
    const float* cow    = (const float*)d_in[9];
    const float* cob    = (const float*)d_in[10];
    const float* fw1    = (const float*)d_in[11];
    const float* fb1    = (const float*)d_in[12];
    const float* fw2    = (const float*)d_in[13];
    const float* fb2    = (const float*)d_in[14];
    const float* lng    = (const float*)d_in[15];
    const float* lnb    = (const float*)d_in[16];
    float* out = (float*)d_out;

    const int B = C_B, Se = C_SE, Sd = C_SD, H = C_H, F = C_F, L = C_L, NH = C_NH;
    const int Md = B * Sd;   // 4096
    const int Me = B * Se;   // 8192
    const int ATTN_SMEM = 4 * 64 * 72 * 4;   // 73728 B

    static bool init_done = false;
    static cudaStream_t s2;
    static cudaEvent_t evRoot, evKV[C_L];
    if (!init_done) {
        cudaFuncSetAttribute(attn_tc, cudaFuncAttributeMaxDynamicSharedMemorySize,
                             ATTN_SMEM);
        cudaStreamCreateWithFlags(&s2, cudaStreamNonBlocking);
        cudaEventCreateWithFlags(&evRoot, cudaEventDisableTiming);
        for (int i = 0; i < C_L; ++i)
            cudaEventCreateWithFlags(&evKV[i], cudaEventDisableTiming);
        init_done = true;
    }

    float *xenc, *h, *qkv, *q, *kv6, *ctx, *tmp, *ffn, *opart, *ml;
    cudaGetSymbolAddress((void**)&xenc,  g_xenc);
    cudaGetSymbolAddress((void**)&h,     g_h);
    cudaGetSymbolAddress((void**)&qkv,   g_qkv);
    cudaGetSymbolAddress((void**)&q,     g_q);
    cudaGetSymbolAddress((void**)&kv6,   g_kv6);
    cudaGetSymbolAddress((void**)&ctx,   g_ctx);
    cudaGetSymbolAddress((void**)&tmp,   g_tmp);
    cudaGetSymbolAddress((void**)&ffn,   g_ffn);
    cudaGetSymbolAddress((void**)&opart, g_opart);
    cudaGetSymbolAddress((void**)&ml,    g_ml);

    {
        int total = B * Se * H;
        add_pos_kernel<<<(total + 255) / 256, 256>>>(x, pos, xenc, total, Se * H);
    }
    cudaMemcpyAsync(h, y, sizeof(float) * (size_t)Md * H, cudaMemcpyDeviceToDevice);

    const dim3 blk(128);
    const dim3 blkA(256);
    const dim3 gSelfQKV(768 / 64, Md / 64);
    const dim3 gProj32(256 / 64, Md / 32);
    const dim3 gCrossKV(512 / 64, Me / 64);
    const dim3 gFfn1(1024 / 64, Md / 64);
    const dim3 gAttnSelf(Sd / 128, B * NH, 4);    // kChunk=512,  512 blocks
    const dim3 gAttnCross(Sd / 128, B * NH, 4);   // kChunk=1024, 512 blocks
    const dim3 gComb(Sd / 64, B * NH);

    // fork: all 6 cross-KV projections (depend only on xenc) on s2
    cudaEventRecord(evRoot, 0);
    cudaStreamWaitEvent(s2, evRoot, 0);
    for (int i = 0; i < L; ++i) {
        const float* cw = cqkvw + (size_t)i * 3 * H * H;
        const float* cb = cqkvb + (size_t)i * 3 * H;
        float* kvDst = kv6 + (size_t)i * 2 * Me * H;
        gemm_tc<false, false><<<gCrossKV, blk, 0, s2>>>(
            xenc, cw + (size_t)H * H, cb + H, nullptr, kvDst, Me, 512, H, 256);
        cudaEventRecord(evKV[i], s2);
    }

    for (int i = 0; i < L; ++i) {
        const float* sw  = sqkvw + (size_t)i * 3 * H * H;
        const float* sb  = sqkvb + (size_t)i * 3 * H;
        const float* sOw = sow + (size_t)i * H * H;
        const float* sOb = sob + (size_t)i * H;
        const float* cw  = cqkvw + (size_t)i * 3 * H * H;
        const float* cb  = cqkvb + (size_t)i * 3 * H;
        const float* cOw = cow + (size_t)i * H * H;
        const float* cOb = cob + (size_t)i * H;
        const float* w1  = fw1 + (size_t)i * H * F;
        const float* b1  = fb1 + (size_t)i * F;
        const float* w2  = fw2 + (size_t)i * F * H;
        const float* b2  = fb2 + (size_t)i * H;
        float* kvL = kv6 + (size_t)i * 2 * Me * H;

        // ---- self attention ----
        gemm_tc<false, false><<<gSelfQKV, blk>>>(h, sw, sb, nullptr, qkv,
                                                 Md, 768, H, 256);
        attn_tc<<<gAttnSelf, blkA, ATTN_SMEM>>>(qkv, qkv + (size_t)Md * H,
                                                qkv + (size_t)2 * Md * H,
                                                opart, ml, Sd, Sd, 512);
        attn_combine<<<gComb, 256>>>(opart, ml, ctx, Sd, 4);
        gemm32_tc<true><<<gProj32, blk>>>(ctx, sOw, sOb, h, tmp, Md, 256, 256);
        ln_kernel<<<Md / 8, 256>>>(tmp, lng + (size_t)(i * 3 + 0) * H,
                                   lnb + (size_t)(i * 3 + 0) * H, h);

        // ---- cross attention ----
        gemm32_tc<false><<<gProj32, blk>>>(h, cw, cb, nullptr, q, Md, 256, 256);
        cudaStreamWaitEvent(0, evKV[i], 0);
        attn_tc<<<gAttnCross, blkA, ATTN_SMEM>>>(q, kvL, kvL + (size_t)Me * H,
                                                 opart, ml, Sd, Se, 1024);
        attn_combine<<<gComb, 256>>>(opart, ml, ctx, Sd, 4);
        gemm32_tc<true><<<gProj32, blk>>>(ctx, cOw, cOb, h, tmp, Md, 256, 256);
        ln_kernel<<<Md / 8, 256>>>(tmp, lng + (size_t)(i * 3 + 1) * H,
                                   lnb + (size_t)(i * 3 + 1) * H, h);

        // ---- FFN ----
        gemm_tc<true, false><<<gFfn1, blk>>>(h, w1, b1, nullptr, ffn,
                                             Md, 1024, H, 1024);
        gemm32_tc<true><<<gProj32, blk>>>(ffn, w2, b2, h, tmp, Md, 256, 1024);
        ln_kernel<<<Md / 8, 256>>>(tmp, lng + (size_t)(i * 3 + 2) * H,
                                   lnb + (size_t)(i * 3 + 2) * H,
                                   (i == L - 1) ? out : h);
    }
}

// round 12
// speedup vs baseline: 1.2420x; 1.0179x over previous
#include <cuda_runtime.h>
#include <math.h>
#include <stdint.h>

// ---------------------------------------------------------------------------
// Problem constants: B=2, Se=4096, Sd=2048, H=256, NH=4, hd=64, F=1024, L=6
// ---------------------------------------------------------------------------
#define C_B   2
#define C_SE  4096
#define C_SD  2048
#define C_H   256
#define C_NH  4
#define C_F   1024
#define C_L   6

// ---------------------------------------------------------------------------
// Scratch (device globals; no allocations allowed)
// ---------------------------------------------------------------------------
__device__ float g_xenc [C_B * C_SE * C_H];
__device__ float g_h    [C_B * C_SD * C_H];
__device__ float g_qkv  [3 * C_B * C_SD * C_H];
__device__ float g_q    [C_B * C_SD * C_H];
__device__ float g_kv6  [C_L * 2 * C_B * C_SE * C_H];   // per-layer cross K,V
__device__ float g_ctx  [C_B * C_SD * C_H];
__device__ float g_tmp  [C_B * C_SD * C_H];
__device__ float g_ffn  [C_B * C_SD * C_F];
__device__ float g_opart[4 * 8 * C_SD * 64];            // split-K partial O
__device__ float g_ml   [4 * 8 * C_SD * 2];             // split-K (m, l)

// ---------------------------------------------------------------------------
// tf32 mma (m16n8k8 row.col f32 accum), cp.async helpers
// ---------------------------------------------------------------------------
__device__ __forceinline__ uint32_t f2tf(float x) {
    uint32_t u;
    asm("cvt.rna.tf32.f32 %0, %1;" : "=r"(u) : "f"(x));
    return u;
}
__device__ __forceinline__ float4 cvt4(float4 v) {
    return make_float4(__uint_as_float(f2tf(v.x)), __uint_as_float(f2tf(v.y)),
                       __uint_as_float(f2tf(v.z)), __uint_as_float(f2tf(v.w)));
}
__device__ __forceinline__ void mma_tf32(float* c, const uint32_t* a,
                                         uint32_t b0, uint32_t b1) {
    asm volatile(
        "mma.sync.aligned.m16n8k8.row.col.f32.tf32.tf32.f32 "
        "{%0,%1,%2,%3}, {%4,%5,%6,%7}, {%8,%9}, {%0,%1,%2,%3};"
        : "+f"(c[0]), "+f"(c[1]), "+f"(c[2]), "+f"(c[3])
        : "r"(a[0]), "r"(a[1]), "r"(a[2]), "r"(a[3]), "r"(b0), "r"(b1));
}
__device__ __forceinline__ void cp16(float* dst_smem, const float* src) {
    uint32_t d = (uint32_t)__cvta_generic_to_shared(dst_smem);
    asm volatile("cp.async.cg.shared.global [%0], [%1], 16;" :: "r"(d), "l"(src));
}
__device__ __forceinline__ void cp_commit() {
    asm volatile("cp.async.commit_group;");
}
template <int N>
__device__ __forceinline__ void cp_wait() {
    asm volatile("cp.async.wait_group %0;" :: "n"(N));
}

// ---------------------------------------------------------------------------
// x_enc = x + pos_embed
// ---------------------------------------------------------------------------
__global__ void add_pos_kernel(const float* __restrict__ x,
                               const float* __restrict__ pos,
                               float* __restrict__ out, int total, int seh) {
    int i = blockIdx.x * blockDim.x + threadIdx.x;
    if (i < total) out[i] = x[i] + pos[i % seh];
}

__device__ __forceinline__ float gelu_f(float x) {
    float x3 = x * x * x;
    return 0.5f * x * (1.0f + tanhf(0.7978845608028654f * (x + 0.044715f * x3)));
}

// ---------------------------------------------------------------------------
// Big tensor-core GEMM: BM=128, BN=64, BK=32, 256 threads (8 warps, 4x2 of
// 32x32 warp tiles). Halves L2 tile-redundancy vs BM=64 and raises per-SM
// warp count. W may be a stack of part matrices (each K x nPart); block n0
// uses part = n0/nPart; output written at C + part*M*nPart.
// Dynamic smem: (2*128*36 + 2*32*72)*4 = 55296 B.
// ---------------------------------------------------------------------------
template <bool GELU, bool RES>
__global__ __launch_bounds__(256) void gemm128_tc(
    const float* __restrict__ A, const float* __restrict__ W,
    const float* __restrict__ bias, const float* __restrict__ Res,
    float* __restrict__ C, int M, int N, int K, int nPart) {
    extern __shared__ float sm[];
    float* AsB[2] = { sm, sm + 128 * 36 };
    float* BsB[2] = { sm + 2 * 128 * 36, sm + 2 * 128 * 36 + 32 * 72 };

    const int tid = threadIdx.x;
    const int lane = tid & 31, warp = tid >> 5;
    const int g = lane >> 2, c = lane & 3;
    const int wm = warp >> 1, wn = warp & 1;        // 4x2 warp grid
    const int m0 = blockIdx.y << 7;
    const int n0 = blockIdx.x << 6;
    const int part = n0 / nPart;
    const int nc = n0 - part * nPart;
    const float* Wp = W + (size_t)part * K * nPart + nc;

    // staging: A tile 128x32 (2 thr/row, 16 floats each);
    //          B tile 32x64 (8 thr/row, 8 floats each)
    const int arow = tid >> 1, acol = (tid & 1) * 16;
    const int brow = tid >> 3, bcol = (tid & 7) * 8;
    const float* Agp = A + (size_t)(m0 + arow) * K + acol;
    const float* Bgp = Wp + (size_t)brow * nPart + bcol;

    auto stage = [&](int buf, int k0) {
        const float* ag = Agp + k0;
        float* ad = &AsB[buf][arow * 36 + acol];
#pragma unroll
        for (int j = 0; j < 4; ++j) cp16(ad + 4 * j, ag + 4 * j);
        const float* bg = Bgp + (size_t)k0 * nPart;
        float* bd = &BsB[buf][brow * 72 + bcol];
        cp16(bd, bg);
        cp16(bd + 4, bg + 4);
    };

    float acc[2][4][4] = {};
    stage(0, 0);
    cp_commit();

    const int KT = K >> 5;
    for (int kt = 0; kt < KT; ++kt) {
        const int buf = kt & 1;
        if (kt + 1 < KT) {
            stage(buf ^ 1, (kt + 1) << 5);
            cp_commit();
            cp_wait<1>();
        } else {
            cp_wait<0>();
        }
        __syncthreads();

        const float* Ab = AsB[buf];
        const float* Bb = BsB[buf];
#pragma unroll
        for (int kk = 0; kk < 32; kk += 8) {
            uint32_t af[2][4];
#pragma unroll
            for (int mf = 0; mf < 2; ++mf) {
                int rb = wm * 32 + mf * 16;
                af[mf][0] = __float_as_uint(Ab[(rb + g) * 36 + kk + c]);
                af[mf][1] = __float_as_uint(Ab[(rb + g + 8) * 36 + kk + c]);
                af[mf][2] = __float_as_uint(Ab[(rb + g) * 36 + kk + c + 4]);
                af[mf][3] = __float_as_uint(Ab[(rb + g + 8) * 36 + kk + c + 4]);
            }
#pragma unroll
            for (int nf = 0; nf < 4; ++nf) {
                int nb = wn * 32 + nf * 8;
                uint32_t b0 = __float_as_uint(Bb[(kk + c) * 72 + nb + g]);
                uint32_t b1 = __float_as_uint(Bb[(kk + c + 4) * 72 + nb + g]);
                mma_tf32(acc[0][nf], af[0], b0, b1);
                mma_tf32(acc[1][nf], af[1], b0, b1);
            }
        }
        __syncthreads();
    }

    const float* bp = bias + (size_t)part * nPart;
    float* Cp = C + (size_t)part * M * nPart;
    const float* Rp = RES ? (Res + (size_t)part * M * nPart) : nullptr;
#pragma unroll
    for (int mf = 0; mf < 2; ++mf) {
        int r0 = m0 + wm * 32 + mf * 16 + g;
#pragma unroll
        for (int nf = 0; nf < 4; ++nf) {
            int col = nc + wn * 32 + nf * 8 + 2 * c;
            float2 bi = *(const float2*)&bp[col];
            float v00 = acc[mf][nf][0] + bi.x;
            float v01 = acc[mf][nf][1] + bi.y;
            float v10 = acc[mf][nf][2] + bi.x;
            float v11 = acc[mf][nf][3] + bi.y;
            if (GELU) {
                v00 = gelu_f(v00); v01 = gelu_f(v01);
                v10 = gelu_f(v10); v11 = gelu_f(v11);
            }
            if (RES) {
                float2 ra  = *(const float2*)&Rp[(size_t)r0 * nPart + col];
                float2 rb2 = *(const float2*)&Rp[(size_t)(r0 + 8) * nPart + col];
                v00 += ra.x; v01 += ra.y; v10 += rb2.x; v11 += rb2.y;
            }
            *(float2*)&Cp[(size_t)r0 * nPart + col] = make_float2(v00, v01);
            *(float2*)&Cp[(size_t)(r0 + 8) * nPart + col] = make_float2(v10, v11);
        }
    }
}

// ---------------------------------------------------------------------------
// Narrow GEMM (BM=32, BN=64, BK=32, 128 threads) — used for the small K=256
// N=256 projections where grid size matters more than tile reuse.
// ---------------------------------------------------------------------------
template <bool RES>
__global__ __launch_bounds__(128) void gemm32_tc(
    const float* __restrict__ A, const float* __restrict__ W,
    const float* __restrict__ bias, const float* __restrict__ Res,
    float* __restrict__ C, int M, int N, int K) {
    __shared__ float As[2][32 * 36];
    __shared__ float Bs[2][32 * 72];

    const int tid = threadIdx.x;
    const int lane = tid & 31, warp = tid >> 5;
    const int g = lane >> 2, c = lane & 3;
    const int m0 = blockIdx.y << 5;
    const int n0 = blockIdx.x << 6;

    const int arow = tid >> 2, acol = (tid & 3) * 8;
    const int brow = tid >> 2, bcol = (tid & 3) * 16;
    const float* Agp = A + (size_t)(m0 + arow) * K + acol;
    const float* Bgp = W + (size_t)brow * N + n0 + bcol;

    auto stage = [&](int buf, int k0) {
        const float* ag = Agp + k0;
        float* ad = &As[buf][arow * 36 + acol];
        cp16(ad, ag);
        cp16(ad + 4, ag + 4);
        const float* bg = Bgp + (size_t)k0 * N;
        float* bd = &Bs[buf][brow * 72 + bcol];
#pragma unroll
        for (int j = 0; j < 4; ++j) cp16(bd + 4 * j, bg + 4 * j);
    };

    float acc[2][2][4] = {};
    stage(0, 0);
    cp_commit();

    const int KT = K >> 5;
    for (int kt = 0; kt < KT; ++kt) {
        const int buf = kt & 1;
        if (kt + 1 < KT) {
            stage(buf ^ 1, (kt + 1) << 5);
            cp_commit();
            cp_wait<1>();
        } else {
            cp_wait<0>();
        }
        __syncthreads();

        const float* Ab = As[buf];
        const float* Bb = Bs[buf];
#pragma unroll
        for (int kk = 0; kk < 32; kk += 8) {
            uint32_t af[2][4];
#pragma unroll
            for (int mf = 0; mf < 2; ++mf) {
                int rb = mf * 16;
                af[mf][0] = __float_as_uint(Ab[(rb + g) * 36 + kk + c]);
                af[mf][1] = __float_as_uint(Ab[(rb + g + 8) * 36 + kk + c]);
                af[mf][2] = __float_as_uint(Ab[(rb + g) * 36 + kk + c + 4]);
                af[mf][3] = __float_as_uint(Ab[(rb + g + 8) * 36 + kk + c + 4]);
            }
#pragma unroll
            for (int nf = 0; nf < 2; ++nf) {
                int nb = warp * 16 + nf * 8;
                uint32_t b0 = __float_as_uint(Bb[(kk + c) * 72 + nb + g]);
                uint32_t b1 = __float_as_uint(Bb[(kk + c + 4) * 72 + nb + g]);
                mma_tf32(acc[0][nf], af[0], b0, b1);
                mma_tf32(acc[1][nf], af[1], b0, b1);
            }
        }
        __syncthreads();
    }

#pragma unroll
    for (int mf = 0; mf < 2; ++mf) {
        int r0 = m0 + mf * 16 + g;
#pragma unroll
        for (int nf = 0; nf < 2; ++nf) {
            int col = n0 + warp * 16 + nf * 8 + 2 * c;
            float2 bi = *(const float2*)&bias[col];
            float v00 = acc[mf][nf][0] + bi.x;
            float v01 = acc[mf][nf][1] + bi.y;
            float v10 = acc[mf][nf][2] + bi.x;
            float v11 = acc[mf][nf][3] + bi.y;
            if (RES) {
                float2 ra  = *(const float2*)&Res[(size_t)r0 * N + col];
                float2 rb2 = *(const float2*)&Res[(size_t)(r0 + 8) * N + col];
                v00 += ra.x; v01 += ra.y; v10 += rb2.x; v11 += rb2.y;
            }
            *(float2*)&C[(size_t)r0 * N + col] = make_float2(v00, v01);
            *(float2*)&C[(size_t)(r0 + 8) * N + col] = make_float2(v10, v11);
        }
    }
}

// ---------------------------------------------------------------------------
// Split-K flash attention, 256 threads / 8 warps, q-tile 128.
// Warp w owns q-rows [16w, 16w+16) over ALL 64 keys of each tile; softmax is
// intra-quad shuffles only; P stays in registers (C-frag -> A-frag remap via
// quad shuffles). 2 syncthreads per tile. Dyn smem 73728 B, 2 blocks/SM.
// ---------------------------------------------------------------------------
__global__ __launch_bounds__(256, 2) void attn_tc(
    const float* __restrict__ Q, const float* __restrict__ K,
    const float* __restrict__ V, float* __restrict__ Opart,
    float* __restrict__ ml, int Sq, int Sk, int kChunk) {
    const int H = 256;
    extern __shared__ float smp[];
    float* KsBuf[2] = { smp, smp + 64 * 72 };
    float* VsBuf[2] = { smp + 2 * 64 * 72, smp + 3 * 64 * 72 };

    const int tid = threadIdx.x;
    const int lane = tid & 31, warp = tid >> 5;
    const int g = lane >> 2, c = lane & 3;
    const int q0 = blockIdx.x << 7;          // 128 q rows per block
    const int bh = blockIdx.y;
    const int b  = bh >> 2;
    const int h0 = (bh & 3) << 6;
    const int sp = blockIdx.z;
    const int BH = gridDim.y;
    const int kOff = sp * kChunk;
    const int rql = (warp << 4) + g;         // local q row (0..127)
    const int sr = tid >> 2;                 // staging row 0..63
    const int sc = (tid & 3) << 4;           // staging col base

    const float* Kb = K + (size_t)b * Sk * H + h0;
    const float* Vb = V + (size_t)b * Sk * H + h0;

    // ---- stage 128 Q rows (RNA tf32) across smem, build fragments ----
#pragma unroll
    for (int half = 0; half < 2; ++half) {
        const float* qp = Q + ((size_t)(b * Sq + q0 + half * 64 + sr)) * H + h0 + sc;
        float* qd = &smp[half * 64 * 72 + sr * 72 + sc];
#pragma unroll
        for (int t = 0; t < 4; ++t)
            *(float4*)(qd + 4 * t) = cvt4(*(const float4*)(qp + 4 * t));
    }
    __syncthreads();
    uint32_t qf[8][4];
#pragma unroll
    for (int dc = 0; dc < 8; ++dc) {
        qf[dc][0] = __float_as_uint(smp[rql * 72 + dc * 8 + c]);
        qf[dc][1] = __float_as_uint(smp[(rql + 8) * 72 + dc * 8 + c]);
        qf[dc][2] = __float_as_uint(smp[rql * 72 + dc * 8 + c + 4]);
        qf[dc][3] = __float_as_uint(smp[(rql + 8) * 72 + dc * 8 + c + 4]);
    }
    __syncthreads();

    auto stage_kv = [&](int buf, int k0) {
        const float* kg = Kb + (size_t)(k0 + sr) * H + sc;
        float* kd = &KsBuf[buf][sr * 72 + sc];
#pragma unroll
        for (int j = 0; j < 4; ++j) cp16(kd + 4 * j, kg + 4 * j);
        const float* vg = Vb + (size_t)(k0 + sr) * H + sc;
        float* vd = &VsBuf[buf][sr * 72 + sc];
#pragma unroll
        for (int j = 0; j < 4; ++j) cp16(vd + 4 * j, vg + 4 * j);
    };

    stage_kv(0, kOff);
    cp_commit();

    float mr0 = -1e30f, mr1 = -1e30f, l0 = 0.0f, l1 = 0.0f;
    float oacc[8][4] = {};

    const int T = kChunk >> 6;
    for (int t = 0; t < T; ++t) {
        const int buf = t & 1;
        if (t + 1 < T) {
            stage_kv(buf ^ 1, kOff + ((t + 1) << 6));
            cp_commit();
            cp_wait<1>();
        } else {
            cp_wait<0>();
        }
        __syncthreads();

        const float* Ks = KsBuf[buf];
        const float* Vs = VsBuf[buf];

        // ---- S = Q @ K^T : 16 q-rows x 64 keys per warp ----
        float sacc[8][4] = {};
#pragma unroll
        for (int dc = 0; dc < 8; ++dc) {
#pragma unroll
            for (int nt = 0; nt < 8; ++nt) {
                uint32_t b0 = __float_as_uint(Ks[(nt * 8 + g) * 72 + dc * 8 + c]);
                uint32_t b1 = __float_as_uint(Ks[(nt * 8 + g) * 72 + dc * 8 + c + 4]);
                mma_tf32(sacc[nt], qf[dc], b0, b1);
            }
        }

        // ---- online softmax, fully in registers (quad shuffles) ----
        const float scale = 0.125f;
        float mx0 = -1e30f, mx1 = -1e30f;
#pragma unroll
        for (int nt = 0; nt < 8; ++nt) {
            sacc[nt][0] *= scale; sacc[nt][1] *= scale;
            sacc[nt][2] *= scale; sacc[nt][3] *= scale;
            mx0 = fmaxf(mx0, fmaxf(sacc[nt][0], sacc[nt][1]));
            mx1 = fmaxf(mx1, fmaxf(sacc[nt][2], sacc[nt][3]));
        }
        mx0 = fmaxf(mx0, __shfl_xor_sync(0xffffffffu, mx0, 1));
        mx0 = fmaxf(mx0, __shfl_xor_sync(0xffffffffu, mx0, 2));
        mx1 = fmaxf(mx1, __shfl_xor_sync(0xffffffffu, mx1, 1));
        mx1 = fmaxf(mx1, __shfl_xor_sync(0xffffffffu, mx1, 2));
        float mn0 = fmaxf(mr0, mx0), mn1 = fmaxf(mr1, mx1);
        float corr0 = __expf(mr0 - mn0), corr1 = __expf(mr1 - mn1);
        float s0 = 0.0f, s1 = 0.0f;
#pragma unroll
        for (int nt = 0; nt < 8; ++nt) {
            sacc[nt][0] = __expf(sacc[nt][0] - mn0);
            sacc[nt][1] = __expf(sacc[nt][1] - mn0);
            sacc[nt][2] = __expf(sacc[nt][2] - mn1);
            sacc[nt][3] = __expf(sacc[nt][3] - mn1);
            s0 += sacc[nt][0] + sacc[nt][1];
            s1 += sacc[nt][2] + sacc[nt][3];
            oacc[nt][0] *= corr0; oacc[nt][1] *= corr0;
            oacc[nt][2] *= corr1; oacc[nt][3] *= corr1;
        }
        s0 += __shfl_xor_sync(0xffffffffu, s0, 1);
        s0 += __shfl_xor_sync(0xffffffffu, s0, 2);
        s1 += __shfl_xor_sync(0xffffffffu, s1, 1);
        s1 += __shfl_xor_sync(0xffffffffu, s1, 2);
        l0 = l0 * corr0 + s0;
        l1 = l1 * corr1 + s1;
        mr0 = mn0; mr1 = mn1;

        // ---- O += P @ V, P remapped C-frag -> A-frag via quad shuffles ----
        const int srcA = (lane & ~3) | (c >> 1);
        const int srcB = srcA + 2;
        const bool odd = (c & 1);
#pragma unroll
        for (int kc = 0; kc < 8; ++kc) {
            float t0 = __shfl_sync(0xffffffffu, sacc[kc][0], srcA);
            float t1 = __shfl_sync(0xffffffffu, sacc[kc][1], srcA);
            float t2 = __shfl_sync(0xffffffffu, sacc[kc][2], srcA);
            float t3 = __shfl_sync(0xffffffffu, sacc[kc][3], srcA);
            float u0 = __shfl_sync(0xffffffffu, sacc[kc][0], srcB);
            float u1 = __shfl_sync(0xffffffffu, sacc[kc][1], srcB);
            float u2 = __shfl_sync(0xffffffffu, sacc[kc][2], srcB);
            float u3 = __shfl_sync(0xffffffffu, sacc[kc][3], srcB);
            uint32_t pa[4];
            pa[0] = __float_as_uint(odd ? t1 : t0);
            pa[1] = __float_as_uint(odd ? t3 : t2);
            pa[2] = __float_as_uint(odd ? u1 : u0);
            pa[3] = __float_as_uint(odd ? u3 : u2);
#pragma unroll
            for (int nt = 0; nt < 8; ++nt) {
                uint32_t b0 = __float_as_uint(Vs[(kc * 8 + c) * 72 + nt * 8 + g]);
                uint32_t b1 = __float_as_uint(Vs[(kc * 8 + c + 4) * 72 + nt * 8 + g]);
                mma_tf32(oacc[nt], pa, b0, b1);
            }
        }
        __syncthreads();   // buf fully consumed before next cp.async overwrite
    }

    // ---- write unnormalized partial O and (m, l) ----
    size_t row0 = ((size_t)sp * BH + bh) * Sq + q0 + rql;
    size_t row1 = row0 + 8;
    float* op0 = Opart + (row0 << 6);
    float* op1 = Opart + (row1 << 6);
#pragma unroll
    for (int nt = 0; nt < 8; ++nt) {
        *(float2*)&op0[nt * 8 + 2 * c] = make_float2(oacc[nt][0], oacc[nt][1]);
        *(float2*)&op1[nt * 8 + 2 * c] = make_float2(oacc[nt][2], oacc[nt][3]);
    }
    if (c == 0) {
        ml[row0 * 2]     = mr0;
        ml[row0 * 2 + 1] = l0;
        ml[row1 * 2]     = mr1;
        ml[row1 * 2 + 1] = l1;
    }
}

// ---------------------------------------------------------------------------
// Split-K combine.
// ---------------------------------------------------------------------------
__global__ __launch_bounds__(256) void attn_combine(
    const float* __restrict__ Opart, const float* __restrict__ ml,
    float* __restrict__ Ctx, int Sq, int nSplit) {
    const int BH = gridDim.y;
    const int bh = blockIdx.y;
    const int b = bh >> 2, h0 = (bh & 3) << 6;
    const int q = (blockIdx.x << 6) + (threadIdx.x >> 2);
    const int c0 = (threadIdx.x & 3) << 4;
    const size_t slab = (size_t)BH * Sq;
    const size_t rbase = (size_t)bh * Sq + q;

    float M = -1e30f;
    for (int sp = 0; sp < nSplit; ++sp)
        M = fmaxf(M, ml[(sp * slab + rbase) * 2]);

    float L = 0.0f;
    float4 a[4] = {{0,0,0,0},{0,0,0,0},{0,0,0,0},{0,0,0,0}};
    for (int sp = 0; sp < nSplit; ++sp) {
        size_t r = sp * slab + rbase;
        float w = __expf(ml[r * 2] - M);
        L += w * ml[r * 2 + 1];
        const float* p = Opart + (r << 6) + c0;
#pragma unroll
        for (int j = 0; j < 4; ++j) {
            float4 v = *(const float4*)(p + 4 * j);
            a[j].x += w * v.x; a[j].y += w * v.y;
            a[j].z += w * v.z; a[j].w += w * v.w;
        }
    }
    float inv = 1.0f / L;
    float* o = Ctx + ((size_t)(b * Sq + q)) * 256 + h0 + c0;
#pragma unroll
    for (int j = 0; j < 4; ++j)
        *(float4*)(o + 4 * j) = make_float4(a[j].x * inv, a[j].y * inv,
                                            a[j].z * inv, a[j].w * inv);
}

// ---------------------------------------------------------------------------
// LayerNorm over last dim (H=256). Warp per row.
// ---------------------------------------------------------------------------
__global__ __launch_bounds__(256) void ln_kernel(
    const float* __restrict__ in, const float* __restrict__ gamma,
    const float* __restrict__ beta, float* __restrict__ out) {
    const int warp = threadIdx.x >> 5, lane = threadIdx.x & 31;
    const size_t row = (size_t)blockIdx.x * 8 + warp;
    const float* p = in + row * 256 + lane * 8;
    float4 a = *(const float4*)p;
    float4 b = *(const float4*)(p + 4);

    float s = (a.x + a.y) + (a.z + a.w) + (b.x + b.y) + (b.z + b.w);
#pragma unroll
    for (int off = 16; off > 0; off >>= 1)
        s += __shfl_xor_sync(0xffffffffu, s, off);
    float mu = s * (1.0f / 256.0f);

    float dx = a.x - mu, dy = a.y - mu, dz = a.z - mu, dw = a.w - mu;
    float ex = b.x - mu, ey = b.y - mu, ez = b.z - mu, ew = b.w - mu;
    float q = dx * dx + dy * dy + dz * dz + dw * dw +
              ex * ex + ey * ey + ez * ez + ew * ew;
#pragma unroll
    for (int off = 16; off > 0; off >>= 1)
        q += __shfl_xor_sync(0xffffffffu, q, off);
    float inv = rsqrtf(q * (1.0f / 256.0f) + 1e-12f);

    float4 ga = *(const float4*)&gamma[lane * 8];
    float4 gb = *(const float4*)&gamma[lane * 8 + 4];
    float4 ba = *(const float4*)&beta[lane * 8];
    float4 bb = *(const float4*)&beta[lane * 8 + 4];
    float* o = out + row * 256 + lane * 8;
    *(float4*)o = make_float4(dx * inv * ga.x + ba.x, dy * inv * ga.y + ba.y,
                              dz * inv * ga.z + ba.z, dw * inv * ga.w + ba.w);
    *(float4*)(o + 4) = make_float4(ex * inv * gb.x + bb.x, ey * inv * gb.y + bb.y,
                                    ez * inv * gb.z + bb.z, ew * inv * gb.w + bb.w);
}

// ---------------------------------------------------------------------------
// Orchestration. Cross-KV projections depend only on xenc: forked stream,
// joined per-layer via events.
// ---------------------------------------------------------------------------
extern "C" void kernel_launch(void* const* d_in, const int* in_sizes, int n_in,
                              void* d_out, int out_size) {
    const float* x      = (const float*)d_in[0];
    const float* y      = (const float*)d_in[1];
    const float* pos    = (const float*)d_in[2];
    const float* sqkvw  = (const float*)d_in[3];
    const float* sqkvb  = (const float*)d_in[4];
    const float* sow    = (const float*)d_in[5];
    const float* sob    = (const float*)d_in[6];
    const float* cqkvw  = (const float*)d_in[7];
    const float* cqkvb  = (const float*)d_in[8];
    const float* cow    = (const float*)d_in[9];
    const float* cob    = (const float*)d_in[10];
    const float* fw1    = (const float*)d_in[11];
    const float* fb1    = (const float*)d_in[12];
    const float* fw2    = (const float*)d_in[13];
    const float* fb2    = (const float*)d_in[14];
    const float* lng    = (const float*)d_in[15];
    const float* lnb    = (const float*)d_in[16];
    float* out = (float*)d_out;

    const int B = C_B, Se = C_SE, Sd = C_SD, H = C_H, F = C_F, L = C_L, NH = C_NH;
    const int Md = B * Sd;   // 4096
    const int Me = B * Se;   // 8192
    const int ATTN_SMEM = 4 * 64 * 72 * 4;                  // 73728 B
    const int G128_SMEM = (2 * 128 * 36 + 2 * 32 * 72) * 4; // 55296 B

    static bool init_done = false;
    static cudaStream_t s2;
    static cudaEvent_t evRoot, evKV[C_L];
    if (!init_done) {
        cudaFuncSetAttribute(attn_tc, cudaFuncAttributeMaxDynamicSharedMemorySize,
                             ATTN_SMEM);
        cudaFuncSetAttribute(gemm128_tc<false, false>,
                             cudaFuncAttributeMaxDynamicSharedMemorySize, G128_SMEM);
        cudaFuncSetAttribute(gemm128_tc<true, false>,
                             cudaFuncAttributeMaxDynamicSharedMemorySize, G128_SMEM);
        cudaFuncSetAttribute(gemm128_tc<false, true>,
                             cudaFuncAttributeMaxDynamicSharedMemorySize, G128_SMEM);
        cudaStreamCreateWithFlags(&s2, cudaStreamNonBlocking);
        cudaEventCreateWithFlags(&evRoot, cudaEventDisableTiming);
        for (int i = 0; i < C_L; ++i)
            cudaEventCreateWithFlags(&evKV[i], cudaEventDisableTiming);
        init_done = true;
    }

    float *xenc, *h, *qkv, *q, *kv6, *ctx, *tmp, *ffn, *opart, *ml;
    cudaGetSymbolAddress((void**)&xenc,  g_xenc);
    cudaGetSymbolAddress((void**)&h,     g_h);
    cudaGetSymbolAddress((void**)&qkv,   g_qkv);
    cudaGetSymbolAddress((void**)&q,     g_q);
    cudaGetSymbolAddress((void**)&kv6,   g_kv6);
    cudaGetSymbolAddress((void**)&ctx,   g_ctx);
    cudaGetSymbolAddress((void**)&tmp,   g_tmp);
    cudaGetSymbolAddress((void**)&ffn,   g_ffn);
    cudaGetSymbolAddress((void**)&opart, g_opart);
    cudaGetSymbolAddress((void**)&ml,    g_ml);

    {
        int total = B * Se * H;
        add_pos_kernel<<<(total + 255) / 256, 256>>>(x, pos, xenc, total, Se * H);
    }
    cudaMemcpyAsync(h, y, sizeof(float) * (size_t)Md * H, cudaMemcpyDeviceToDevice);

    const dim3 blk128(128);
    const dim3 blk256(256);
    const dim3 gSelfQKV(768 / 64, Md / 128);      // 12 x 32 = 384 blocks
    const dim3 gProj32(256 / 64, Md / 32);        // 512 blocks
    const dim3 gCrossKV(512 / 64, Me / 128);      // 8 x 64 = 512 blocks
    const dim3 gFfn1(1024 / 64, Md / 128);        // 16 x 32 = 512 blocks
    const dim3 gFfn2(256 / 64, Md / 128);         // 4 x 32 = 128 blocks
    const dim3 gAttnSelf(Sd / 128, B * NH, 4);    // kChunk=512,  512 blocks
    const dim3 gAttnCross(Sd / 128, B * NH, 4);   // kChunk=1024, 512 blocks
    const dim3 gComb(Sd / 64, B * NH);

    // fork: all 6 cross-KV projections (depend only on xenc) on s2
    cudaEventRecord(evRoot, 0);
    cudaStreamWaitEvent(s2, evRoot, 0);
    for (int i = 0; i < L; ++i) {
        const float* cw = cqkvw + (size_t)i * 3 * H * H;
        const float* cb = cqkvb + (size_t)i * 3 * H;
        float* kvDst = kv6 + (size_t)i * 2 * Me * H;
        gemm128_tc<false, false><<<gCrossKV, blk256, G128_SMEM, s2>>>(
            xenc, cw + (size_t)H * H, cb + H, nullptr, kvDst, Me, 512, H, 256);
        cudaEventRecord(evKV[i], s2);
    }

    for (int i = 0; i < L; ++i) {
        const float* sw  = sqkvw + (size_t)i * 3 * H * H;
        const float* sb  = sqkvb + (size_t)i * 3 * H;
        const float* sOw = sow + (size_t)i * H * H;
        const float* sOb = sob + (size_t)i * H;
        const float* cw  = cqkvw + (size_t)i * 3 * H * H;
        const float* cb  = cqkvb + (size_t)i * 3 * H;
        const float* cOw = cow + (size_t)i * H * H;
        const float* cOb = cob + (size_t)i * H;
        const float* w1  = fw1 + (size_t)i * H * F;
        const float* b1  = fb1 + (size_t)i * F;
        const float* w2  = fw2 + (size_t)i * F * H;
        const float* b2  = fb2 + (size_t)i * H;
        float* kvL = kv6 + (size_t)i * 2 * Me * H;

        // ---- self attention ----
        gemm128_tc<false, false><<<gSelfQKV, blk256, G128_SMEM>>>(
            h, sw, sb, nullptr, qkv, Md, 768, H, 256);
        attn_tc<<<gAttnSelf, blk256, ATTN_SMEM>>>(qkv, qkv + (size_t)Md * H,
                                                  qkv + (size_t)2 * Md * H,
                                                  opart, ml, Sd, Sd, 512);
        attn_combine<<<gComb, 256>>>(opart, ml, ctx, Sd, 4);
        gemm32_tc<true><<<gProj32, blk128>>>(ctx, sOw, sOb, h, tmp, Md, 256, 256);
        ln_kernel<<<Md / 8, 256>>>(tmp, lng + (size_t)(i * 3 + 0) * H,
                                   lnb + (size_t)(i * 3 + 0) * H, h);

        // ---- cross attention ----
        gemm32_tc<false><<<gProj32, blk128>>>(h, cw, cb, nullptr, q, Md, 256, 256);
        cudaStreamWaitEvent(0, evKV[i], 0);
        attn_tc<<<gAttnCross, blk256, ATTN_SMEM>>>(q, kvL, kvL + (size_t)Me * H,
                                                   opart, ml, Sd, Se, 1024);
        attn_combine<<<gComb, 256>>>(opart, ml, ctx, Sd, 4);
        gemm32_tc<true><<<gProj32, blk128>>>(ctx, cOw, cOb, h, tmp, Md, 256, 256);
        ln_kernel<<<Md / 8, 256>>>(tmp, lng + (size_t)(i * 3 + 1) * H,
                                   lnb + (size_t)(i * 3 + 1) * H, h);

        // ---- FFN ----
        gemm128_tc<true, false><<<gFfn1, blk256, G128_SMEM>>>(
            h, w1, b1, nullptr, ffn, Md, 1024, H, 1024);
        gemm128_tc<false, true><<<gFfn2, blk256, G128_SMEM>>>(
            ffn, w2, b2, h, tmp, Md, 256, F, 256);
        ln_kernel<<<Md / 8, 256>>>(tmp, lng + (size_t)(i * 3 + 2) * H,
                                   lnb + (size_t)(i * 3 + 2) * H,
                                   (i == L - 1) ? out : h);
    }
}

// round 16
// speedup vs baseline: 1.5219x; 1.2253x over previous
#include <cuda_runtime.h>
#include <cuda_bf16.h>
#include <math.h>
#include <stdint.h>

// ---------------------------------------------------------------------------
// Problem constants: B=2, Se=4096, Sd=2048, H=256, NH=4, hd=64, F=1024, L=6
// ---------------------------------------------------------------------------
#define C_B   2
#define C_SE  4096
#define C_SD  2048
#define C_H   256
#define C_NH  4
#define C_F   1024
#define C_L   6

// ---------------------------------------------------------------------------
// Scratch (device globals; no allocations allowed)
// ---------------------------------------------------------------------------
__device__ float g_xenc [C_B * C_SE * C_H];
__device__ float g_h    [C_B * C_SD * C_H];
__device__ float g_qkv  [3 * C_B * C_SD * C_H];
__device__ float g_q    [C_B * C_SD * C_H];
__device__ float g_kv6  [C_L * 2 * C_B * C_SE * C_H];   // per-layer cross K,V
__device__ float g_ctx  [C_B * C_SD * C_H];
__device__ float g_tmp  [C_B * C_SD * C_H];
__device__ float g_ffn  [C_B * C_SD * C_F];
__device__ float g_opart[4 * 8 * C_SD * 64];            // split-K partial O
__device__ float g_ml   [4 * 8 * C_SD * 2];             // split-K (m, l)
__device__ __nv_bfloat16 g_vts[8 * 64 * C_SD];          // self V^T bf16
__device__ __nv_bfloat16 g_vtc[C_L * 8 * 64 * C_SE];    // cross V^T bf16

// ---------------------------------------------------------------------------
// mma wrappers + cp.async helpers
// ---------------------------------------------------------------------------
__device__ __forceinline__ uint32_t f2tf(float x) {
    uint32_t u;
    asm("cvt.rna.tf32.f32 %0, %1;" : "=r"(u) : "f"(x));
    return u;
}
__device__ __forceinline__ float4 cvt4(float4 v) {
    return make_float4(__uint_as_float(f2tf(v.x)), __uint_as_float(f2tf(v.y)),
                       __uint_as_float(f2tf(v.z)), __uint_as_float(f2tf(v.w)));
}
__device__ __forceinline__ void mma_tf32(float* c, const uint32_t* a,
                                         uint32_t b0, uint32_t b1) {
    asm volatile(
        "mma.sync.aligned.m16n8k8.row.col.f32.tf32.tf32.f32 "
        "{%0,%1,%2,%3}, {%4,%5,%6,%7}, {%8,%9}, {%0,%1,%2,%3};"
        : "+f"(c[0]), "+f"(c[1]), "+f"(c[2]), "+f"(c[3])
        : "r"(a[0]), "r"(a[1]), "r"(a[2]), "r"(a[3]), "r"(b0), "r"(b1));
}
__device__ __forceinline__ void mma_bf16(float* c, const uint32_t* a,
                                         uint32_t b0, uint32_t b1) {
    asm volatile(
        "mma.sync.aligned.m16n8k16.row.col.f32.bf16.bf16.f32 "
        "{%0,%1,%2,%3}, {%4,%5,%6,%7}, {%8,%9}, {%0,%1,%2,%3};"
        : "+f"(c[0]), "+f"(c[1]), "+f"(c[2]), "+f"(c[3])
        : "r"(a[0]), "r"(a[1]), "r"(a[2]), "r"(a[3]), "r"(b0), "r"(b1));
}
// pack {lo, hi} floats -> bf16x2 (PTX: first source = HIGH half)
__device__ __forceinline__ uint32_t packbf(float lo, float hi) {
    uint32_t r;
    asm("cvt.rn.bf16x2.f32 %0, %1, %2;" : "=r"(r) : "f"(hi), "f"(lo));
    return r;
}
__device__ __forceinline__ void cp16(void* dst_smem, const void* src) {
    uint32_t d = (uint32_t)__cvta_generic_to_shared(dst_smem);
    asm volatile("cp.async.cg.shared.global [%0], [%1], 16;" :: "r"(d), "l"(src));
}
__device__ __forceinline__ void cp_commit() {
    asm volatile("cp.async.commit_group;");
}
template <int N>
__device__ __forceinline__ void cp_wait() {
    asm volatile("cp.async.wait_group %0;" :: "n"(N));
}

// ---------------------------------------------------------------------------
// x_enc = x + pos_embed
// ---------------------------------------------------------------------------
__global__ void add_pos_kernel(const float* __restrict__ x,
                               const float* __restrict__ pos,
                               float* __restrict__ out, int total, int seh) {
    int i = blockIdx.x * blockDim.x + threadIdx.x;
    if (i < total) out[i] = x[i] + pos[i % seh];
}

__device__ __forceinline__ float gelu_f(float x) {
    float x3 = x * x * x;
    return 0.5f * x * (1.0f + tanhf(0.7978845608028654f * (x + 0.044715f * x3)));
}

// ---------------------------------------------------------------------------
// V transpose + bf16 convert: V fp32 [B*S][256] -> Vt bf16 [B*NH*64][S].
// One (64 t x 64 d) tile per block; coalesced both directions.
// ---------------------------------------------------------------------------
__global__ __launch_bounds__(256) void vt_kernel(
    const float* __restrict__ V, __nv_bfloat16* __restrict__ Vt, int S) {
    __shared__ __nv_bfloat16 tile[64][72];
    const int tid = threadIdx.x;
    const int t0 = blockIdx.x << 6;
    const int bh = blockIdx.y;
    const int b = bh >> 2, h = bh & 3;

    {
        const int t = tid >> 2, dq = (tid & 3) << 4;
        const float* src = V + ((size_t)(b * S + t0 + t)) * 256 + h * 64 + dq;
#pragma unroll
        for (int j = 0; j < 4; ++j) {
            float4 v = *(const float4*)(src + 4 * j);
            tile[dq + 4 * j + 0][t] = __float2bfloat16(v.x);
            tile[dq + 4 * j + 1][t] = __float2bfloat16(v.y);
            tile[dq + 4 * j + 2][t] = __float2bfloat16(v.z);
            tile[dq + 4 * j + 3][t] = __float2bfloat16(v.w);
        }
    }
    __syncthreads();
    {
        const int d = tid >> 2, tq = (tid & 3) << 4;
        __nv_bfloat16* dst = Vt + ((size_t)(bh * 64 + d)) * S + t0 + tq;
        *(uint4*)dst = *(uint4*)&tile[d][tq];
        *(uint4*)(dst + 8) = *(uint4*)&tile[d][tq + 8];
    }
}

// ---------------------------------------------------------------------------
// Big tensor-core GEMM: BM=128, BN=64, BK=32, 256 threads (8 warps, 4x2).
// ---------------------------------------------------------------------------
template <bool GELU, bool RES>
__global__ __launch_bounds__(256) void gemm128_tc(
    const float* __restrict__ A, const float* __restrict__ W,
    const float* __restrict__ bias, const float* __restrict__ Res,
    float* __restrict__ C, int M, int N, int K, int nPart) {
    extern __shared__ float sm[];
    float* AsB[2] = { sm, sm + 128 * 36 };
    float* BsB[2] = { sm + 2 * 128 * 36, sm + 2 * 128 * 36 + 32 * 72 };

    const int tid = threadIdx.x;
    const int lane = tid & 31, warp = tid >> 5;
    const int g = lane >> 2, c = lane & 3;
    const int wm = warp >> 1, wn = warp & 1;
    const int m0 = blockIdx.y << 7;
    const int n0 = blockIdx.x << 6;
    const int part = n0 / nPart;
    const int nc = n0 - part * nPart;
    const float* Wp = W + (size_t)part * K * nPart + nc;

    const int arow = tid >> 1, acol = (tid & 1) * 16;
    const int brow = tid >> 3, bcol = (tid & 7) * 8;
    const float* Agp = A + (size_t)(m0 + arow) * K + acol;
    const float* Bgp = Wp + (size_t)brow * nPart + bcol;

    auto stage = [&](int buf, int k0) {
        const float* ag = Agp + k0;
        float* ad = &AsB[buf][arow * 36 + acol];
#pragma unroll
        for (int j = 0; j < 4; ++j) cp16(ad + 4 * j, ag + 4 * j);
        const float* bg = Bgp + (size_t)k0 * nPart;
        float* bd = &BsB[buf][brow * 72 + bcol];
        cp16(bd, bg);
        cp16(bd + 4, bg + 4);
    };

    float acc[2][4][4] = {};
    stage(0, 0);
    cp_commit();

    const int KT = K >> 5;
    for (int kt = 0; kt < KT; ++kt) {
        const int buf = kt & 1;
        if (kt + 1 < KT) {
            stage(buf ^ 1, (kt + 1) << 5);
            cp_commit();
            cp_wait<1>();
        } else {
            cp_wait<0>();
        }
        __syncthreads();

        const float* Ab = AsB[buf];
        const float* Bb = BsB[buf];
#pragma unroll
        for (int kk = 0; kk < 32; kk += 8) {
            uint32_t af[2][4];
#pragma unroll
            for (int mf = 0; mf < 2; ++mf) {
                int rb = wm * 32 + mf * 16;
                af[mf][0] = __float_as_uint(Ab[(rb + g) * 36 + kk + c]);
                af[mf][1] = __float_as_uint(Ab[(rb + g + 8) * 36 + kk + c]);
                af[mf][2] = __float_as_uint(Ab[(rb + g) * 36 + kk + c + 4]);
                af[mf][3] = __float_as_uint(Ab[(rb + g + 8) * 36 + kk + c + 4]);
            }
#pragma unroll
            for (int nf = 0; nf < 4; ++nf) {
                int nb = wn * 32 + nf * 8;
                uint32_t b0 = __float_as_uint(Bb[(kk + c) * 72 + nb + g]);
                uint32_t b1 = __float_as_uint(Bb[(kk + c + 4) * 72 + nb + g]);
                mma_tf32(acc[0][nf], af[0], b0, b1);
                mma_tf32(acc[1][nf], af[1], b0, b1);
            }
        }
        __syncthreads();
    }

    const float* bp = bias + (size_t)part * nPart;
    float* Cp = C + (size_t)part * M * nPart;
    const float* Rp = RES ? (Res + (size_t)part * M * nPart) : nullptr;
#pragma unroll
    for (int mf = 0; mf < 2; ++mf) {
        int r0 = m0 + wm * 32 + mf * 16 + g;
#pragma unroll
        for (int nf = 0; nf < 4; ++nf) {
            int col = nc + wn * 32 + nf * 8 + 2 * c;
            float2 bi = *(const float2*)&bp[col];
            float v00 = acc[mf][nf][0] + bi.x;
            float v01 = acc[mf][nf][1] + bi.y;
            float v10 = acc[mf][nf][2] + bi.x;
            float v11 = acc[mf][nf][3] + bi.y;
            if (GELU) {
                v00 = gelu_f(v00); v01 = gelu_f(v01);
                v10 = gelu_f(v10); v11 = gelu_f(v11);
            }
            if (RES) {
                float2 ra  = *(const float2*)&Rp[(size_t)r0 * nPart + col];
                float2 rb2 = *(const float2*)&Rp[(size_t)(r0 + 8) * nPart + col];
                v00 += ra.x; v01 += ra.y; v10 += rb2.x; v11 += rb2.y;
            }
            *(float2*)&Cp[(size_t)r0 * nPart + col] = make_float2(v00, v01);
            *(float2*)&Cp[(size_t)(r0 + 8) * nPart + col] = make_float2(v10, v11);
        }
    }
}

// ---------------------------------------------------------------------------
// Narrow GEMM (BM=32, BN=64, BK=32, 128 threads).
// ---------------------------------------------------------------------------
template <bool RES>
__global__ __launch_bounds__(128) void gemm32_tc(
    const float* __restrict__ A, const float* __restrict__ W,
    const float* __restrict__ bias, const float* __restrict__ Res,
    float* __restrict__ C, int M, int N, int K) {
    __shared__ float As[2][32 * 36];
    __shared__ float Bs[2][32 * 72];

    const int tid = threadIdx.x;
    const int lane = tid & 31, warp = tid >> 5;
    const int g = lane >> 2, c = lane & 3;
    const int m0 = blockIdx.y << 5;
    const int n0 = blockIdx.x << 6;

    const int arow = tid >> 2, acol = (tid & 3) * 8;
    const int brow = tid >> 2, bcol = (tid & 3) * 16;
    const float* Agp = A + (size_t)(m0 + arow) * K + acol;
    const float* Bgp = W + (size_t)brow * N + n0 + bcol;

    auto stage = [&](int buf, int k0) {
        const float* ag = Agp + k0;
        float* ad = &As[buf][arow * 36 + acol];
        cp16(ad, ag);
        cp16(ad + 4, ag + 4);
        const float* bg = Bgp + (size_t)k0 * N;
        float* bd = &Bs[buf][brow * 72 + bcol];
#pragma unroll
        for (int j = 0; j < 4; ++j) cp16(bd + 4 * j, bg + 4 * j);
    };

    float acc[2][2][4] = {};
    stage(0, 0);
    cp_commit();

    const int KT = K >> 5;
    for (int kt = 0; kt < KT; ++kt) {
        const int buf = kt & 1;
        if (kt + 1 < KT) {
            stage(buf ^ 1, (kt + 1) << 5);
            cp_commit();
            cp_wait<1>();
        } else {
            cp_wait<0>();
        }
        __syncthreads();

        const float* Ab = As[buf];
        const float* Bb = Bs[buf];
#pragma unroll
        for (int kk = 0; kk < 32; kk += 8) {
            uint32_t af[2][4];
#pragma unroll
            for (int mf = 0; mf < 2; ++mf) {
                int rb = mf * 16;
                af[mf][0] = __float_as_uint(Ab[(rb + g) * 36 + kk + c]);
                af[mf][1] = __float_as_uint(Ab[(rb + g + 8) * 36 + kk + c]);
                af[mf][2] = __float_as_uint(Ab[(rb + g) * 36 + kk + c + 4]);
                af[mf][3] = __float_as_uint(Ab[(rb + g + 8) * 36 + kk + c + 4]);
            }
#pragma unroll
            for (int nf = 0; nf < 2; ++nf) {
                int nb = warp * 16 + nf * 8;
                uint32_t b0 = __float_as_uint(Bb[(kk + c) * 72 + nb + g]);
                uint32_t b1 = __float_as_uint(Bb[(kk + c + 4) * 72 + nb + g]);
                mma_tf32(acc[0][nf], af[0], b0, b1);
                mma_tf32(acc[1][nf], af[1], b0, b1);
            }
        }
        __syncthreads();
    }

#pragma unroll
    for (int mf = 0; mf < 2; ++mf) {
        int r0 = m0 + mf * 16 + g;
#pragma unroll
        for (int nf = 0; nf < 2; ++nf) {
            int col = n0 + warp * 16 + nf * 8 + 2 * c;
            float2 bi = *(const float2*)&bias[col];
            float v00 = acc[mf][nf][0] + bi.x;
            float v01 = acc[mf][nf][1] + bi.y;
            float v10 = acc[mf][nf][2] + bi.x;
            float v11 = acc[mf][nf][3] + bi.y;
            if (RES) {
                float2 ra  = *(const float2*)&Res[(size_t)r0 * N + col];
                float2 rb2 = *(const float2*)&Res[(size_t)(r0 + 8) * N + col];
                v00 += ra.x; v01 += ra.y; v10 += rb2.x; v11 += rb2.y;
            }
            *(float2*)&C[(size_t)r0 * N + col] = make_float2(v00, v01);
            *(float2*)&C[(size_t)(r0 + 8) * N + col] = make_float2(v10, v11);
        }
    }
}

// ---------------------------------------------------------------------------
// Split-K flash attention, 256 threads / 8 warps, q-tile 128.
// S = QK^T in tf32 (K fp32 smem). P@V in bf16 m16n8k16: V pre-transposed
// bf16 (Vt[d][k]) so B-fragments are single LDS.32 bf16x2 loads; the S
// C-fragment layout IS the bf16 A-fragment layout, so P packs in-place with
// cvt.rn.bf16x2 (no shuffles). Dyn smem: 2*18432 (K fp32) + 2*9216 (Vt bf16)
// = 55296 B. 2 blocks/SM.
// ---------------------------------------------------------------------------
__global__ __launch_bounds__(256, 2) void attn_tc(
    const float* __restrict__ Q, const float* __restrict__ K,
    const __nv_bfloat16* __restrict__ Vt, float* __restrict__ Opart,
    float* __restrict__ ml, int Sq, int Sk, int kChunk) {
    const int H = 256;
    extern __shared__ float smp[];
    float* KsBuf[2] = { smp, smp + 64 * 72 };
    __nv_bfloat16* VtB[2] = { (__nv_bfloat16*)(smp + 2 * 64 * 72),
                              (__nv_bfloat16*)(smp + 2 * 64 * 72) + 64 * 72 };

    const int tid = threadIdx.x;
    const int lane = tid & 31, warp = tid >> 5;
    const int g = lane >> 2, c = lane & 3;
    const int q0 = blockIdx.x << 7;          // 128 q rows per block
    const int bh = blockIdx.y;
    const int b  = bh >> 2;
    const int h0 = (bh & 3) << 6;
    const int sp = blockIdx.z;
    const int BH = gridDim.y;
    const int kOff = sp * kChunk;
    const int rql = (warp << 4) + g;         // local q row (0..127)
    const int sr = tid >> 2;                 // staging row 0..63
    const int sc = (tid & 3) << 4;           // staging col base (fp32)

    const float* Kb = K + (size_t)b * Sk * H + h0;
    const __nv_bfloat16* Vtb = Vt + (size_t)bh * 64 * Sk;

    // ---- stage 128 Q rows (RNA tf32) across K-buffer smem, build frags ----
#pragma unroll
    for (int half = 0; half < 2; ++half) {
        const float* qp = Q + ((size_t)(b * Sq + q0 + half * 64 + sr)) * H + h0 + sc;
        float* qd = &smp[half * 64 * 72 + sr * 72 + sc];
#pragma unroll
        for (int t = 0; t < 4; ++t)
            *(float4*)(qd + 4 * t) = cvt4(*(const float4*)(qp + 4 * t));
    }
    __syncthreads();
    uint32_t qf[8][4];
#pragma unroll
    for (int dc = 0; dc < 8; ++dc) {
        qf[dc][0] = __float_as_uint(smp[rql * 72 + dc * 8 + c]);
        qf[dc][1] = __float_as_uint(smp[(rql + 8) * 72 + dc * 8 + c]);
        qf[dc][2] = __float_as_uint(smp[rql * 72 + dc * 8 + c + 4]);
        qf[dc][3] = __float_as_uint(smp[(rql + 8) * 72 + dc * 8 + c + 4]);
    }
    __syncthreads();

    auto stage_kv = [&](int buf, int k0) {
        const float* kg = Kb + (size_t)(k0 + sr) * H + sc;
        float* kd = &KsBuf[buf][sr * 72 + sc];
#pragma unroll
        for (int j = 0; j < 4; ++j) cp16(kd + 4 * j, kg + 4 * j);
        // Vt tile: 64 d-rows x 64 keys bf16; 4 threads/row, 2 x 16B each
        const int vq = (tid & 3) << 4;       // bf16 col base 0/16/32/48
        const __nv_bfloat16* vg = Vtb + (size_t)sr * Sk + k0 + vq;
        __nv_bfloat16* vd = VtB[buf] + sr * 72 + vq;
        cp16(vd, vg);
        cp16(vd + 8, vg + 8);
    };

    stage_kv(0, kOff);
    cp_commit();

    float mr0 = -1e30f, mr1 = -1e30f, l0 = 0.0f, l1 = 0.0f;
    float oacc[8][4] = {};

    const int T = kChunk >> 6;
    for (int t = 0; t < T; ++t) {
        const int buf = t & 1;
        if (t + 1 < T) {
            stage_kv(buf ^ 1, kOff + ((t + 1) << 6));
            cp_commit();
            cp_wait<1>();
        } else {
            cp_wait<0>();
        }
        __syncthreads();

        const float* Ks = KsBuf[buf];
        const __nv_bfloat16* Vs = VtB[buf];

        // ---- S = Q @ K^T : 16 q-rows x 64 keys per warp (tf32) ----
        float sacc[8][4] = {};
#pragma unroll
        for (int dc = 0; dc < 8; ++dc) {
#pragma unroll
            for (int nt = 0; nt < 8; ++nt) {
                uint32_t b0 = __float_as_uint(Ks[(nt * 8 + g) * 72 + dc * 8 + c]);
                uint32_t b1 = __float_as_uint(Ks[(nt * 8 + g) * 72 + dc * 8 + c + 4]);
                mma_tf32(sacc[nt], qf[dc], b0, b1);
            }
        }

        // ---- online softmax, fully in registers (quad shuffles) ----
        const float scale = 0.125f;
        float mx0 = -1e30f, mx1 = -1e30f;
#pragma unroll
        for (int nt = 0; nt < 8; ++nt) {
            sacc[nt][0] *= scale; sacc[nt][1] *= scale;
            sacc[nt][2] *= scale; sacc[nt][3] *= scale;
            mx0 = fmaxf(mx0, fmaxf(sacc[nt][0], sacc[nt][1]));
            mx1 = fmaxf(mx1, fmaxf(sacc[nt][2], sacc[nt][3]));
        }
        mx0 = fmaxf(mx0, __shfl_xor_sync(0xffffffffu, mx0, 1));
        mx0 = fmaxf(mx0, __shfl_xor_sync(0xffffffffu, mx0, 2));
        mx1 = fmaxf(mx1, __shfl_xor_sync(0xffffffffu, mx1, 1));
        mx1 = fmaxf(mx1, __shfl_xor_sync(0xffffffffu, mx1, 2));
        float mn0 = fmaxf(mr0, mx0), mn1 = fmaxf(mr1, mx1);
        float corr0 = __expf(mr0 - mn0), corr1 = __expf(mr1 - mn1);
        float s0 = 0.0f, s1 = 0.0f;
#pragma unroll
        for (int nt = 0; nt < 8; ++nt) {
            sacc[nt][0] = __expf(sacc[nt][0] - mn0);
            sacc[nt][1] = __expf(sacc[nt][1] - mn0);
            sacc[nt][2] = __expf(sacc[nt][2] - mn1);
            sacc[nt][3] = __expf(sacc[nt][3] - mn1);
            s0 += sacc[nt][0] + sacc[nt][1];
            s1 += sacc[nt][2] + sacc[nt][3];
            oacc[nt][0] *= corr0; oacc[nt][1] *= corr0;
            oacc[nt][2] *= corr1; oacc[nt][3] *= corr1;
        }
        s0 += __shfl_xor_sync(0xffffffffu, s0, 1);
        s0 += __shfl_xor_sync(0xffffffffu, s0, 2);
        s1 += __shfl_xor_sync(0xffffffffu, s1, 1);
        s1 += __shfl_xor_sync(0xffffffffu, s1, 2);
        l0 = l0 * corr0 + s0;
        l1 = l1 * corr1 + s1;
        mr0 = mn0; mr1 = mn1;

        // ---- O += P @ V in bf16 m16n8k16; P packs in-place, V from Vt ----
#pragma unroll
        for (int kc = 0; kc < 4; ++kc) {
            uint32_t pa[4];
            pa[0] = packbf(sacc[2 * kc][0], sacc[2 * kc][1]);
            pa[1] = packbf(sacc[2 * kc][2], sacc[2 * kc][3]);
            pa[2] = packbf(sacc[2 * kc + 1][0], sacc[2 * kc + 1][1]);
            pa[3] = packbf(sacc[2 * kc + 1][2], sacc[2 * kc + 1][3]);
#pragma unroll
            for (int nt = 0; nt < 8; ++nt) {
                const __nv_bfloat16* vp = Vs + (nt * 8 + g) * 72 + kc * 16 + 2 * c;
                uint32_t b0 = *(const uint32_t*)vp;
                uint32_t b1 = *(const uint32_t*)(vp + 8);
                mma_bf16(oacc[nt], pa, b0, b1);
            }
        }
        __syncthreads();   // buf fully consumed before next cp.async overwrite
    }

    // ---- write unnormalized partial O and (m, l) ----
    size_t row0 = ((size_t)sp * BH + bh) * Sq + q0 + rql;
    size_t row1 = row0 + 8;
    float* op0 = Opart + (row0 << 6);
    float* op1 = Opart + (row1 << 6);
#pragma unroll
    for (int nt = 0; nt < 8; ++nt) {
        *(float2*)&op0[nt * 8 + 2 * c] = make_float2(oacc[nt][0], oacc[nt][1]);
        *(float2*)&op1[nt * 8 + 2 * c] = make_float2(oacc[nt][2], oacc[nt][3]);
    }
    if (c == 0) {
        ml[row0 * 2]     = mr0;
        ml[row0 * 2 + 1] = l0;
        ml[row1 * 2]     = mr1;
        ml[row1 * 2 + 1] = l1;
    }
}

// ---------------------------------------------------------------------------
// Split-K combine.
// ---------------------------------------------------------------------------
__global__ __launch_bounds__(256) void attn_combine(
    const float* __restrict__ Opart, const float* __restrict__ ml,
    float* __restrict__ Ctx, int Sq, int nSplit) {
    const int BH = gridDim.y;
    const int bh = blockIdx.y;
    const int b = bh >> 2, h0 = (bh & 3) << 6;
    const int q = (blockIdx.x << 6) + (threadIdx.x >> 2);
    const int c0 = (threadIdx.x & 3) << 4;
    const size_t slab = (size_t)BH * Sq;
    const size_t rbase = (size_t)bh * Sq + q;

    float M = -1e30f;
    for (int sp = 0; sp < nSplit; ++sp)
        M = fmaxf(M, ml[(sp * slab + rbase) * 2]);

    float L = 0.0f;
    float4 a[4] = {{0,0,0,0},{0,0,0,0},{0,0,0,0},{0,0,0,0}};
    for (int sp = 0; sp < nSplit; ++sp) {
        size_t r = sp * slab + rbase;
        float w = __expf(ml[r * 2] - M);
        L += w * ml[r * 2 + 1];
        const float* p = Opart + (r << 6) + c0;
#pragma unroll
        for (int j = 0; j < 4; ++j) {
            float4 v = *(const float4*)(p + 4 * j);
            a[j].x += w * v.x; a[j].y += w * v.y;
            a[j].z += w * v.z; a[j].w += w * v.w;
        }
    }
    float inv = 1.0f / L;
    float* o = Ctx + ((size_t)(b * Sq + q)) * 256 + h0 + c0;
#pragma unroll
    for (int j = 0; j < 4; ++j)
        *(float4*)(o + 4 * j) = make_float4(a[j].x * inv, a[j].y * inv,
                                            a[j].z * inv, a[j].w * inv);
}

// ---------------------------------------------------------------------------
// LayerNorm over last dim (H=256). Warp per row.
// ---------------------------------------------------------------------------
__global__ __launch_bounds__(256) void ln_kernel(
    const float* __restrict__ in, const float* __restrict__ gamma,
    const float* __restrict__ beta, float* __restrict__ out) {
    const int warp = threadIdx.x >> 5, lane = threadIdx.x & 31;
    const size_t row = (size_t)blockIdx.x * 8 + warp;
    const float* p = in + row * 256 + lane * 8;
    float4 a = *(const float4*)p;
    float4 b = *(const float4*)(p + 4);

    float s = (a.x + a.y) + (a.z + a.w) + (b.x + b.y) + (b.z + b.w);
#pragma unroll
    for (int off = 16; off > 0; off >>= 1)
        s += __shfl_xor_sync(0xffffffffu, s, off);
    float mu = s * (1.0f / 256.0f);

    float dx = a.x - mu, dy = a.y - mu, dz = a.z - mu, dw = a.w - mu;
    float ex = b.x - mu, ey = b.y - mu, ez = b.z - mu, ew = b.w - mu;
    float q = dx * dx + dy * dy + dz * dz + dw * dw +
              ex * ex + ey * ey + ez * ez + ew * ew;
#pragma unroll
    for (int off = 16; off > 0; off >>= 1)
        q += __shfl_xor_sync(0xffffffffu, q, off);
    float inv = rsqrtf(q * (1.0f / 256.0f) + 1e-12f);

    float4 ga = *(const float4*)&gamma[lane * 8];
    float4 gb = *(const float4*)&gamma[lane * 8 + 4];
    float4 ba = *(const float4*)&beta[lane * 8];
    float4 bb = *(const float4*)&beta[lane * 8 + 4];
    float* o = out + row * 256 + lane * 8;
    *(float4*)o = make_float4(dx * inv * ga.x + ba.x, dy * inv * ga.y + ba.y,
                              dz * inv * ga.z + ba.z, dw * inv * ga.w + ba.w);
    *(float4*)(o + 4) = make_float4(ex * inv * gb.x + bb.x, ey * inv * gb.y + bb.y,
                                    ez * inv * gb.z + bb.z, ew * inv * gb.w + bb.w);
}

// ---------------------------------------------------------------------------
// Orchestration. Cross-KV projections + V transposes (depend only on xenc)
// run on a forked stream, joined per-layer via events.
// ---------------------------------------------------------------------------
extern "C" void kernel_launch(void* const* d_in, const int* in_sizes, int n_in,
                              void* d_out, int out_size) {
    const float* x      = (const float*)d_in[0];
    const float* y      = (const float*)d_in[1];
    const float* pos    = (const float*)d_in[2];
    const float* sqkvw  = (const float*)d_in[3];
    const float* sqkvb  = (const float*)d_in[4];
    const float* sow    = (const float*)d_in[5];
    const float* sob    = (const float*)d_in[6];
    const float* cqkvw  = (const float*)d_in[7];
    const float* cqkvb  = (const float*)d_in[8];
    const float* cow    = (const float*)d_in[9];
    const float* cob    = (const float*)d_in[10];
    const float* fw1    = (const float*)d_in[11];
    const float* fb1    = (const float*)d_in[12];
    const float* fw2    = (const float*)d_in[13];
    const float* fb2    = (const float*)d_in[14];
    const float* lng    = (const float*)d_in[15];
    const float* lnb    = (const float*)d_in[16];
    float* out = (float*)d_out;

    const int B = C_B, Se = C_SE, Sd = C_SD, H = C_H, F = C_F, L = C_L, NH = C_NH;
    const int Md = B * Sd;   // 4096
    const int Me = B * Se;   // 8192
    const int ATTN_SMEM = (2 * 64 * 72) * 4 + (2 * 64 * 72) * 2;   // 55296 B
    const int G128_SMEM = (2 * 128 * 36 + 2 * 32 * 72) * 4;        // 55296 B

    static bool init_done = false;
    static cudaStream_t s2;
    static cudaEvent_t evRoot, evKV[C_L];
    if (!init_done) {
        cudaFuncSetAttribute(attn_tc, cudaFuncAttributeMaxDynamicSharedMemorySize,
                             ATTN_SMEM);
        cudaFuncSetAttribute(gemm128_tc<false, false>,
                             cudaFuncAttributeMaxDynamicSharedMemorySize, G128_SMEM);
        cudaFuncSetAttribute(gemm128_tc<true, false>,
                             cudaFuncAttributeMaxDynamicSharedMemorySize, G128_SMEM);
        cudaFuncSetAttribute(gemm128_tc<false, true>,
                             cudaFuncAttributeMaxDynamicSharedMemorySize, G128_SMEM);
        cudaStreamCreateWithFlags(&s2, cudaStreamNonBlocking);
        cudaEventCreateWithFlags(&evRoot, cudaEventDisableTiming);
        for (int i = 0; i < C_L; ++i)
            cudaEventCreateWithFlags(&evKV[i], cudaEventDisableTiming);
        init_done = true;
    }

    float *xenc, *h, *qkv, *q, *kv6, *ctx, *tmp, *ffn, *opart, *ml;
    __nv_bfloat16 *vts, *vtc;
    cudaGetSymbolAddress((void**)&xenc,  g_xenc);
    cudaGetSymbolAddress((void**)&h,     g_h);
    cudaGetSymbolAddress((void**)&qkv,   g_qkv);
    cudaGetSymbolAddress((void**)&q,     g_q);
    cudaGetSymbolAddress((void**)&kv6,   g_kv6);
    cudaGetSymbolAddress((void**)&ctx,   g_ctx);
    cudaGetSymbolAddress((void**)&tmp,   g_tmp);
    cudaGetSymbolAddress((void**)&ffn,   g_ffn);
    cudaGetSymbolAddress((void**)&opart, g_opart);
    cudaGetSymbolAddress((void**)&ml,    g_ml);
    cudaGetSymbolAddress((void**)&vts,   g_vts);
    cudaGetSymbolAddress((void**)&vtc,   g_vtc);

    {
        int total = B * Se * H;
        add_pos_kernel<<<(total + 255) / 256, 256>>>(x, pos, xenc, total, Se * H);
    }
    cudaMemcpyAsync(h, y, sizeof(float) * (size_t)Md * H, cudaMemcpyDeviceToDevice);

    const dim3 blk128(128);
    const dim3 blk256(256);
    const dim3 gSelfQKV(768 / 64, Md / 128);
    const dim3 gProj32(256 / 64, Md / 32);
    const dim3 gCrossKV(512 / 64, Me / 128);
    const dim3 gFfn1(1024 / 64, Md / 128);
    const dim3 gFfn2(256 / 64, Md / 128);
    const dim3 gVtSelf(Sd / 64, B * NH);
    const dim3 gVtCross(Se / 64, B * NH);
    const dim3 gAttnSelf(Sd / 128, B * NH, 4);    // kChunk=512
    const dim3 gAttnCross(Sd / 128, B * NH, 4);   // kChunk=1024
    const dim3 gComb(Sd / 64, B * NH);

    // fork: cross-KV projections + V transposes on s2
    cudaEventRecord(evRoot, 0);
    cudaStreamWaitEvent(s2, evRoot, 0);
    for (int i = 0; i < L; ++i) {
        const float* cw = cqkvw + (size_t)i * 3 * H * H;
        const float* cb = cqkvb + (size_t)i * 3 * H;
        float* kvDst = kv6 + (size_t)i * 2 * Me * H;
        gemm128_tc<false, false><<<gCrossKV, blk256, G128_SMEM, s2>>>(
            xenc, cw + (size_t)H * H, cb + H, nullptr, kvDst, Me, 512, H, 256);
        vt_kernel<<<gVtCross, blk256, 0, s2>>>(
            kvDst + (size_t)Me * H, vtc + (size_t)i * 8 * 64 * Se, Se);
        cudaEventRecord(evKV[i], s2);
    }

    for (int i = 0; i < L; ++i) {
        const float* sw  = sqkvw + (size_t)i * 3 * H * H;
        const float* sb  = sqkvb + (size_t)i * 3 * H;
        const float* sOw = sow + (size_t)i * H * H;
        const float* sOb = sob + (size_t)i * H;
        const float* cw  = cqkvw + (size_t)i * 3 * H * H;
        const float* cb  = cqkvb + (size_t)i * 3 * H;
        const float* cOw = cow + (size_t)i * H * H;
        const float* cOb = cob + (size_t)i * H;
        const float* w1  = fw1 + (size_t)i * H * F;
        const float* b1  = fb1 + (size_t)i * F;
        const float* w2  = fw2 + (size_t)i * F * H;
        const float* b2  = fb2 + (size_t)i * H;
        float* kvL = kv6 + (size_t)i * 2 * Me * H;
        __nv_bfloat16* vtcL = vtc + (size_t)i * 8 * 64 * Se;

        // ---- self attention ----
        gemm128_tc<false, false><<<gSelfQKV, blk256, G128_SMEM>>>(
            h, sw, sb, nullptr, qkv, Md, 768, H, 256);
        vt_kernel<<<gVtSelf, blk256>>>(qkv + (size_t)2 * Md * H, vts, Sd);
        attn_tc<<<gAttnSelf, blk256, ATTN_SMEM>>>(qkv, qkv + (size_t)Md * H,
                                                  vts, opart, ml, Sd, Sd, 512);
        attn_combine<<<gComb, 256>>>(opart, ml, ctx, Sd, 4);
        gemm32_tc<true><<<gProj32, blk128>>>(ctx, sOw, sOb, h, tmp, Md, 256, 256);
        ln_kernel<<<Md / 8, 256>>>(tmp, lng + (size_t)(i * 3 + 0) * H,
                                   lnb + (size_t)(i * 3 + 0) * H, h);

        // ---- cross attention ----
        gemm32_tc<false><<<gProj32, blk128>>>(h, cw, cb, nullptr, q, Md, 256, 256);
        cudaStreamWaitEvent(0, evKV[i], 0);
        attn_tc<<<gAttnCross, blk256, ATTN_SMEM>>>(q, kvL, vtcL,
                                                   opart, ml, Sd, Se, 1024);
        attn_combine<<<gComb, 256>>>(opart, ml, ctx, Sd, 4);
        gemm32_tc<true><<<gProj32, blk128>>>(ctx, cOw, cOb, h, tmp, Md, 256, 256);
        ln_kernel<<<Md / 8, 256>>>(tmp, lng + (size_t)(i * 3 + 1) * H,
                                   lnb + (size_t)(i * 3 + 1) * H, h);

        // ---- FFN ----
        gemm128_tc<true, false><<<gFfn1, blk256, G128_SMEM>>>(
            h, w1, b1, nullptr, ffn, Md, 1024, H, 1024);
        gemm128_tc<false, true><<<gFfn2, blk256, G128_SMEM>>>(
            ffn, w2, b2, h, tmp, Md, 256, F, 256);
        ln_kernel<<<Md / 8, 256>>>(tmp, lng + (size_t)(i * 3 + 2) * H,
                                   lnb + (size_t)(i * 3 + 2) * H,
                                   (i == L - 1) ? out : h);
    }
}

// round 17
// speedup vs baseline: 1.8897x; 1.2417x over previous
#include <cuda_runtime.h>
#include <cuda_bf16.h>
#include <math.h>
#include <stdint.h>

// ---------------------------------------------------------------------------
// Problem constants: B=2, Se=4096, Sd=2048, H=256, NH=4, hd=64, F=1024, L=6
// ---------------------------------------------------------------------------
#define C_B   2
#define C_SE  4096
#define C_SD  2048
#define C_H   256
#define C_NH  4
#define C_F   1024
#define C_L   6

// ---------------------------------------------------------------------------
// Scratch (device globals; no allocations allowed)
// ---------------------------------------------------------------------------
__device__ float g_xenc [C_B * C_SE * C_H];
__device__ float g_h    [C_B * C_SD * C_H];
__device__ float g_qkv  [3 * C_B * C_SD * C_H];
__device__ float g_q    [C_B * C_SD * C_H];
__device__ float g_kv6  [C_L * 2 * C_B * C_SE * C_H];   // per-layer cross K,V
__device__ float g_ctx  [C_B * C_SD * C_H];
__device__ float g_tmp  [C_B * C_SD * C_H];
__device__ float g_ffn  [C_B * C_SD * C_F];
__device__ float g_opart[4 * 8 * C_SD * 64];            // split-K partial O
__device__ float g_ml   [4 * 8 * C_SD * 2];             // split-K (m, l)
__device__ __nv_bfloat16 g_vts[8 * 64 * C_SD];          // self V^T bf16
__device__ __nv_bfloat16 g_vtc[C_L * 8 * 64 * C_SE];    // cross V^T bf16
__device__ __nv_bfloat16 g_kbs[8 * C_SD * 64];          // self K bf16 [bh][k][d]
__device__ __nv_bfloat16 g_kbc[C_L * 8 * C_SE * 64];    // cross K bf16

// ---------------------------------------------------------------------------
// mma wrappers + cp.async helpers
// ---------------------------------------------------------------------------
__device__ __forceinline__ uint32_t f2tf(float x) {
    uint32_t u;
    asm("cvt.rna.tf32.f32 %0, %1;" : "=r"(u) : "f"(x));
    return u;
}
__device__ __forceinline__ void mma_tf32(float* c, const uint32_t* a,
                                         uint32_t b0, uint32_t b1) {
    asm volatile(
        "mma.sync.aligned.m16n8k8.row.col.f32.tf32.tf32.f32 "
        "{%0,%1,%2,%3}, {%4,%5,%6,%7}, {%8,%9}, {%0,%1,%2,%3};"
        : "+f"(c[0]), "+f"(c[1]), "+f"(c[2]), "+f"(c[3])
        : "r"(a[0]), "r"(a[1]), "r"(a[2]), "r"(a[3]), "r"(b0), "r"(b1));
}
__device__ __forceinline__ void mma_bf16(float* c, const uint32_t* a,
                                         uint32_t b0, uint32_t b1) {
    asm volatile(
        "mma.sync.aligned.m16n8k16.row.col.f32.bf16.bf16.f32 "
        "{%0,%1,%2,%3}, {%4,%5,%6,%7}, {%8,%9}, {%0,%1,%2,%3};"
        : "+f"(c[0]), "+f"(c[1]), "+f"(c[2]), "+f"(c[3])
        : "r"(a[0]), "r"(a[1]), "r"(a[2]), "r"(a[3]), "r"(b0), "r"(b1));
}
// pack {lo, hi} floats -> bf16x2 (PTX: first source = HIGH half)
__device__ __forceinline__ uint32_t packbf(float lo, float hi) {
    uint32_t r;
    asm("cvt.rn.bf16x2.f32 %0, %1, %2;" : "=r"(r) : "f"(hi), "f"(lo));
    return r;
}
__device__ __forceinline__ void cp16(void* dst_smem, const void* src) {
    uint32_t d = (uint32_t)__cvta_generic_to_shared(dst_smem);
    asm volatile("cp.async.cg.shared.global [%0], [%1], 16;" :: "r"(d), "l"(src));
}
__device__ __forceinline__ void cp_commit() {
    asm volatile("cp.async.commit_group;");
}
template <int N>
__device__ __forceinline__ void cp_wait() {
    asm volatile("cp.async.wait_group %0;" :: "n"(N));
}

// ---------------------------------------------------------------------------
// x_enc = x + pos_embed
// ---------------------------------------------------------------------------
__global__ void add_pos_kernel(const float* __restrict__ x,
                               const float* __restrict__ pos,
                               float* __restrict__ out, int total, int seh) {
    int i = blockIdx.x * blockDim.x + threadIdx.x;
    if (i < total) out[i] = x[i] + pos[i % seh];
}

__device__ __forceinline__ float gelu_f(float x) {
    float x3 = x * x * x;
    return 0.5f * x * (1.0f + tanhf(0.7978845608028654f * (x + 0.044715f * x3)));
}

// ---------------------------------------------------------------------------
// V transpose + bf16: V fp32 [B*S][256] -> Vt bf16 [bh][d][S].
// ---------------------------------------------------------------------------
__global__ __launch_bounds__(256) void vt_kernel(
    const float* __restrict__ V, __nv_bfloat16* __restrict__ Vt, int S) {
    __shared__ __nv_bfloat16 tile[64][72];
    const int tid = threadIdx.x;
    const int t0 = blockIdx.x << 6;
    const int bh = blockIdx.y;
    const int b = bh >> 2, h = bh & 3;

    {
        const int t = tid >> 2, dq = (tid & 3) << 4;
        const float* src = V + ((size_t)(b * S + t0 + t)) * 256 + h * 64 + dq;
#pragma unroll
        for (int j = 0; j < 4; ++j) {
            float4 v = *(const float4*)(src + 4 * j);
            tile[dq + 4 * j + 0][t] = __float2bfloat16(v.x);
            tile[dq + 4 * j + 1][t] = __float2bfloat16(v.y);
            tile[dq + 4 * j + 2][t] = __float2bfloat16(v.z);
            tile[dq + 4 * j + 3][t] = __float2bfloat16(v.w);
        }
    }
    __syncthreads();
    {
        const int d = tid >> 2, tq = (tid & 3) << 4;
        __nv_bfloat16* dst = Vt + ((size_t)(bh * 64 + d)) * S + t0 + tq;
        *(uint4*)dst = *(uint4*)&tile[d][tq];
        *(uint4*)(dst + 8) = *(uint4*)&tile[d][tq + 8];
    }
}

// ---------------------------------------------------------------------------
// K bf16 convert (no transpose): K fp32 [B*S][256] -> Kb bf16 [bh][k][64].
// ---------------------------------------------------------------------------
__global__ __launch_bounds__(256) void kcvt_kernel(
    const float* __restrict__ K, __nv_bfloat16* __restrict__ Kb, int S) {
    const int tid = threadIdx.x;
    const int t0 = blockIdx.x << 6;
    const int bh = blockIdx.y;
    const int b = bh >> 2, h = bh & 3;
    const int k = t0 + (tid >> 2), dq = (tid & 3) << 4;

    const float* src = K + ((size_t)(b * S + k)) * 256 + h * 64 + dq;
    __nv_bfloat16* dst = Kb + ((size_t)bh * S + k) * 64 + dq;
    __nv_bfloat16 tmp[16];
#pragma unroll
    for (int j = 0; j < 4; ++j) {
        float4 v = *(const float4*)(src + 4 * j);
        tmp[4 * j + 0] = __float2bfloat16(v.x);
        tmp[4 * j + 1] = __float2bfloat16(v.y);
        tmp[4 * j + 2] = __float2bfloat16(v.z);
        tmp[4 * j + 3] = __float2bfloat16(v.w);
    }
    *(uint4*)dst = *(uint4*)tmp;
    *(uint4*)(dst + 8) = *(uint4*)(tmp + 8);
}

// ---------------------------------------------------------------------------
// Big tensor-core GEMM: BM=128, BN=64, BK=32, 256 threads (8 warps, 4x2).
// ---------------------------------------------------------------------------
template <bool GELU, bool RES>
__global__ __launch_bounds__(256) void gemm128_tc(
    const float* __restrict__ A, const float* __restrict__ W,
    const float* __restrict__ bias, const float* __restrict__ Res,
    float* __restrict__ C, int M, int N, int K, int nPart) {
    extern __shared__ float sm[];
    float* AsB[2] = { sm, sm + 128 * 36 };
    float* BsB[2] = { sm + 2 * 128 * 36, sm + 2 * 128 * 36 + 32 * 72 };

    const int tid = threadIdx.x;
    const int lane = tid & 31, warp = tid >> 5;
    const int g = lane >> 2, c = lane & 3;
    const int wm = warp >> 1, wn = warp & 1;
    const int m0 = blockIdx.y << 7;
    const int n0 = blockIdx.x << 6;
    const int part = n0 / nPart;
    const int nc = n0 - part * nPart;
    const float* Wp = W + (size_t)part * K * nPart + nc;

    const int arow = tid >> 1, acol = (tid & 1) * 16;
    const int brow = tid >> 3, bcol = (tid & 7) * 8;
    const float* Agp = A + (size_t)(m0 + arow) * K + acol;
    const float* Bgp = Wp + (size_t)brow * nPart + bcol;

    auto stage = [&](int buf, int k0) {
        const float* ag = Agp + k0;
        float* ad = &AsB[buf][arow * 36 + acol];
#pragma unroll
        for (int j = 0; j < 4; ++j) cp16(ad + 4 * j, ag + 4 * j);
        const float* bg = Bgp + (size_t)k0 * nPart;
        float* bd = &BsB[buf][brow * 72 + bcol];
        cp16(bd, bg);
        cp16(bd + 4, bg + 4);
    };

    float acc[2][4][4] = {};
    stage(0, 0);
    cp_commit();

    const int KT = K >> 5;
    for (int kt = 0; kt < KT; ++kt) {
        const int buf = kt & 1;
        if (kt + 1 < KT) {
            stage(buf ^ 1, (kt + 1) << 5);
            cp_commit();
            cp_wait<1>();
        } else {
            cp_wait<0>();
        }
        __syncthreads();

        const float* Ab = AsB[buf];
        const float* Bb = BsB[buf];
#pragma unroll
        for (int kk = 0; kk < 32; kk += 8) {
            uint32_t af[2][4];
#pragma unroll
            for (int mf = 0; mf < 2; ++mf) {
                int rb = wm * 32 + mf * 16;
                af[mf][0] = __float_as_uint(Ab[(rb + g) * 36 + kk + c]);
                af[mf][1] = __float_as_uint(Ab[(rb + g + 8) * 36 + kk + c]);
                af[mf][2] = __float_as_uint(Ab[(rb + g) * 36 + kk + c + 4]);
                af[mf][3] = __float_as_uint(Ab[(rb + g + 8) * 36 + kk + c + 4]);
            }
#pragma unroll
            for (int nf = 0; nf < 4; ++nf) {
                int nb = wn * 32 + nf * 8;
                uint32_t b0 = __float_as_uint(Bb[(kk + c) * 72 + nb + g]);
                uint32_t b1 = __float_as_uint(Bb[(kk + c + 4) * 72 + nb + g]);
                mma_tf32(acc[0][nf], af[0], b0, b1);
                mma_tf32(acc[1][nf], af[1], b0, b1);
            }
        }
        __syncthreads();
    }

    const float* bp = bias + (size_t)part * nPart;
    float* Cp = C + (size_t)part * M * nPart;
    const float* Rp = RES ? (Res + (size_t)part * M * nPart) : nullptr;
#pragma unroll
    for (int mf = 0; mf < 2; ++mf) {
        int r0 = m0 + wm * 32 + mf * 16 + g;
#pragma unroll
        for (int nf = 0; nf < 4; ++nf) {
            int col = nc + wn * 32 + nf * 8 + 2 * c;
            float2 bi = *(const float2*)&bp[col];
            float v00 = acc[mf][nf][0] + bi.x;
            float v01 = acc[mf][nf][1] + bi.y;
            float v10 = acc[mf][nf][2] + bi.x;
            float v11 = acc[mf][nf][3] + bi.y;
            if (GELU) {
                v00 = gelu_f(v00); v01 = gelu_f(v01);
                v10 = gelu_f(v10); v11 = gelu_f(v11);
            }
            if (RES) {
                float2 ra  = *(const float2*)&Rp[(size_t)r0 * nPart + col];
                float2 rb2 = *(const float2*)&Rp[(size_t)(r0 + 8) * nPart + col];
                v00 += ra.x; v01 += ra.y; v10 += rb2.x; v11 += rb2.y;
            }
            *(float2*)&Cp[(size_t)r0 * nPart + col] = make_float2(v00, v01);
            *(float2*)&Cp[(size_t)(r0 + 8) * nPart + col] = make_float2(v10, v11);
        }
    }
}

// ---------------------------------------------------------------------------
// Narrow GEMM (BM=32, BN=64, BK=32, 128 threads).
// ---------------------------------------------------------------------------
template <bool RES>
__global__ __launch_bounds__(128) void gemm32_tc(
    const float* __restrict__ A, const float* __restrict__ W,
    const float* __restrict__ bias, const float* __restrict__ Res,
    float* __restrict__ C, int M, int N, int K) {
    __shared__ float As[2][32 * 36];
    __shared__ float Bs[2][32 * 72];

    const int tid = threadIdx.x;
    const int lane = tid & 31, warp = tid >> 5;
    const int g = lane >> 2, c = lane & 3;
    const int m0 = blockIdx.y << 5;
    const int n0 = blockIdx.x << 6;

    const int arow = tid >> 2, acol = (tid & 3) * 8;
    const int brow = tid >> 2, bcol = (tid & 3) * 16;
    const float* Agp = A + (size_t)(m0 + arow) * K + acol;
    const float* Bgp = W + (size_t)brow * N + n0 + bcol;

    auto stage = [&](int buf, int k0) {
        const float* ag = Agp + k0;
        float* ad = &As[buf][arow * 36 + acol];
        cp16(ad, ag);
        cp16(ad + 4, ag + 4);
        const float* bg = Bgp + (size_t)k0 * N;
        float* bd = &Bs[buf][brow * 72 + bcol];
#pragma unroll
        for (int j = 0; j < 4; ++j) cp16(bd + 4 * j, bg + 4 * j);
    };

    float acc[2][2][4] = {};
    stage(0, 0);
    cp_commit();

    const int KT = K >> 5;
    for (int kt = 0; kt < KT; ++kt) {
        const int buf = kt & 1;
        if (kt + 1 < KT) {
            stage(buf ^ 1, (kt + 1) << 5);
            cp_commit();
            cp_wait<1>();
        } else {
            cp_wait<0>();
        }
        __syncthreads();

        const float* Ab = As[buf];
        const float* Bb = Bs[buf];
#pragma unroll
        for (int kk = 0; kk < 32; kk += 8) {
            uint32_t af[2][4];
#pragma unroll
            for (int mf = 0; mf < 2; ++mf) {
                int rb = mf * 16;
                af[mf][0] = __float_as_uint(Ab[(rb + g) * 36 + kk + c]);
                af[mf][1] = __float_as_uint(Ab[(rb + g + 8) * 36 + kk + c]);
                af[mf][2] = __float_as_uint(Ab[(rb + g) * 36 + kk + c + 4]);
                af[mf][3] = __float_as_uint(Ab[(rb + g + 8) * 36 + kk + c + 4]);
            }
#pragma unroll
            for (int nf = 0; nf < 2; ++nf) {
                int nb = warp * 16 + nf * 8;
                uint32_t b0 = __float_as_uint(Bb[(kk + c) * 72 + nb + g]);
                uint32_t b1 = __float_as_uint(Bb[(kk + c + 4) * 72 + nb + g]);
                mma_tf32(acc[0][nf], af[0], b0, b1);
                mma_tf32(acc[1][nf], af[1], b0, b1);
            }
        }
        __syncthreads();
    }

#pragma unroll
    for (int mf = 0; mf < 2; ++mf) {
        int r0 = m0 + mf * 16 + g;
#pragma unroll
        for (int nf = 0; nf < 2; ++nf) {
            int col = n0 + warp * 16 + nf * 8 + 2 * c;
            float2 bi = *(const float2*)&bias[col];
            float v00 = acc[mf][nf][0] + bi.x;
            float v01 = acc[mf][nf][1] + bi.y;
            float v10 = acc[mf][nf][2] + bi.x;
            float v11 = acc[mf][nf][3] + bi.y;
            if (RES) {
                float2 ra  = *(const float2*)&Res[(size_t)r0 * N + col];
                float2 rb2 = *(const float2*)&Res[(size_t)(r0 + 8) * N + col];
                v00 += ra.x; v01 += ra.y; v10 += rb2.x; v11 += rb2.y;
            }
            *(float2*)&C[(size_t)r0 * N + col] = make_float2(v00, v01);
            *(float2*)&C[(size_t)(r0 + 8) * N + col] = make_float2(v10, v11);
        }
    }
}

// ---------------------------------------------------------------------------
// Split-K flash attention, 256 threads / 8 warps, q-tile 128, all-bf16 MMAs.
// S = QK^T in bf16 m16n8k16 (K pre-converted bf16 [bh][k][64]); P@V in bf16
// with V pre-transposed bf16 [bh][d][S]. Q packs to bf16 fragments once at
// staging. All smem tiles stride 72 bf16 = 36 words (== 4 mod 32) ->
// conflict-free fragment reads. Dyn smem: 4 * 64*72 bf16 = 36864 B.
// ---------------------------------------------------------------------------
__global__ __launch_bounds__(256, 2) void attn_tc(
    const float* __restrict__ Q, const __nv_bfloat16* __restrict__ Kb,
    const __nv_bfloat16* __restrict__ Vt, float* __restrict__ Opart,
    float* __restrict__ ml, int Sq, int Sk, int kChunk) {
    const int H = 256;
    extern __shared__ float smp[];
    __nv_bfloat16* bbase = (__nv_bfloat16*)smp;
    __nv_bfloat16* KsB[2] = { bbase, bbase + 64 * 72 };
    __nv_bfloat16* VsB[2] = { bbase + 2 * 64 * 72, bbase + 3 * 64 * 72 };

    const int tid = threadIdx.x;
    const int lane = tid & 31, warp = tid >> 5;
    const int g = lane >> 2, c = lane & 3;
    const int q0 = blockIdx.x << 7;          // 128 q rows per block
    const int bh = blockIdx.y;
    const int b  = bh >> 2;
    const int h0 = (bh & 3) << 6;
    const int sp = blockIdx.z;
    const int BH = gridDim.y;
    const int kOff = sp * kChunk;
    const int rql = (warp << 4) + g;         // local q row (0..127)
    const int sr = tid >> 2;                 // staging row 0..63
    const int sq4 = (tid & 3) << 4;          // staging col base

    const __nv_bfloat16* Kbh = Kb + (size_t)bh * Sk * 64;
    const __nv_bfloat16* Vtb = Vt + (size_t)bh * 64 * Sk;

    // ---- stage 128 Q rows fp32 into smem (stride 72), build bf16 frags ----
#pragma unroll
    for (int half = 0; half < 2; ++half) {
        const float* qp = Q + ((size_t)(b * Sq + q0 + half * 64 + sr)) * H + h0 + sq4;
        float* qd = &smp[(half * 64 + sr) * 72 + sq4];
#pragma unroll
        for (int t = 0; t < 4; ++t)
            *(float4*)(qd + 4 * t) = *(const float4*)(qp + 4 * t);
    }
    __syncthreads();
    uint32_t qf[4][4];
#pragma unroll
    for (int kc = 0; kc < 4; ++kc) {
        float2 v0 = *(const float2*)&smp[rql * 72 + kc * 16 + 2 * c];
        float2 v1 = *(const float2*)&smp[(rql + 8) * 72 + kc * 16 + 2 * c];
        float2 v2 = *(const float2*)&smp[rql * 72 + kc * 16 + 8 + 2 * c];
        float2 v3 = *(const float2*)&smp[(rql + 8) * 72 + kc * 16 + 8 + 2 * c];
        qf[kc][0] = packbf(v0.x, v0.y);
        qf[kc][1] = packbf(v1.x, v1.y);
        qf[kc][2] = packbf(v2.x, v2.y);
        qf[kc][3] = packbf(v3.x, v3.y);
    }
    __syncthreads();   // frags built before cp.async overwrites smem

    auto stage_kv = [&](int buf, int k0) {
        const __nv_bfloat16* kg = Kbh + (size_t)(k0 + sr) * 64 + sq4;
        __nv_bfloat16* kd = KsB[buf] + sr * 72 + sq4;
        cp16(kd, kg);
        cp16(kd + 8, kg + 8);
        const __nv_bfloat16* vg = Vtb + (size_t)sr * Sk + k0 + sq4;
        __nv_bfloat16* vd = VsB[buf] + sr * 72 + sq4;
        cp16(vd, vg);
        cp16(vd + 8, vg + 8);
    };

    stage_kv(0, kOff);
    cp_commit();

    float mr0 = -1e30f, mr1 = -1e30f, l0 = 0.0f, l1 = 0.0f;
    float oacc[8][4] = {};

    const int T = kChunk >> 6;
    for (int t = 0; t < T; ++t) {
        const int buf = t & 1;
        if (t + 1 < T) {
            stage_kv(buf ^ 1, kOff + ((t + 1) << 6));
            cp_commit();
            cp_wait<1>();
        } else {
            cp_wait<0>();
        }
        __syncthreads();

        const __nv_bfloat16* Ks = KsB[buf];
        const __nv_bfloat16* Vs = VsB[buf];

        // ---- S = Q @ K^T : bf16 m16n8k16, 16 q-rows x 64 keys per warp ----
        float sacc[8][4] = {};
#pragma unroll
        for (int kc = 0; kc < 4; ++kc) {
#pragma unroll
            for (int nt = 0; nt < 8; ++nt) {
                const __nv_bfloat16* kp = Ks + (nt * 8 + g) * 72 + kc * 16 + 2 * c;
                uint32_t b0 = *(const uint32_t*)kp;
                uint32_t b1 = *(const uint32_t*)(kp + 8);
                mma_bf16(sacc[nt], qf[kc], b0, b1);
            }
        }

        // ---- online softmax, fully in registers (quad shuffles) ----
        const float scale = 0.125f;
        float mx0 = -1e30f, mx1 = -1e30f;
#pragma unroll
        for (int nt = 0; nt < 8; ++nt) {
            sacc[nt][0] *= scale; sacc[nt][1] *= scale;
            sacc[nt][2] *= scale; sacc[nt][3] *= scale;
            mx0 = fmaxf(mx0, fmaxf(sacc[nt][0], sacc[nt][1]));
            mx1 = fmaxf(mx1, fmaxf(sacc[nt][2], sacc[nt][3]));
        }
        mx0 = fmaxf(mx0, __shfl_xor_sync(0xffffffffu, mx0, 1));
        mx0 = fmaxf(mx0, __shfl_xor_sync(0xffffffffu, mx0, 2));
        mx1 = fmaxf(mx1, __shfl_xor_sync(0xffffffffu, mx1, 1));
        mx1 = fmaxf(mx1, __shfl_xor_sync(0xffffffffu, mx1, 2));
        float mn0 = fmaxf(mr0, mx0), mn1 = fmaxf(mr1, mx1);
        float corr0 = __expf(mr0 - mn0), corr1 = __expf(mr1 - mn1);
        float s0 = 0.0f, s1 = 0.0f;
#pragma unroll
        for (int nt = 0; nt < 8; ++nt) {
            sacc[nt][0] = __expf(sacc[nt][0] - mn0);
            sacc[nt][1] = __expf(sacc[nt][1] - mn0);
            sacc[nt][2] = __expf(sacc[nt][2] - mn1);
            sacc[nt][3] = __expf(sacc[nt][3] - mn1);
            s0 += sacc[nt][0] + sacc[nt][1];
            s1 += sacc[nt][2] + sacc[nt][3];
            oacc[nt][0] *= corr0; oacc[nt][1] *= corr0;
            oacc[nt][2] *= corr1; oacc[nt][3] *= corr1;
        }
        s0 += __shfl_xor_sync(0xffffffffu, s0, 1);
        s0 += __shfl_xor_sync(0xffffffffu, s0, 2);
        s1 += __shfl_xor_sync(0xffffffffu, s1, 1);
        s1 += __shfl_xor_sync(0xffffffffu, s1, 2);
        l0 = l0 * corr0 + s0;
        l1 = l1 * corr1 + s1;
        mr0 = mn0; mr1 = mn1;

        // ---- O += P @ V in bf16; P packs in-place, V from Vt ----
#pragma unroll
        for (int kc = 0; kc < 4; ++kc) {
            uint32_t pa[4];
            pa[0] = packbf(sacc[2 * kc][0], sacc[2 * kc][1]);
            pa[1] = packbf(sacc[2 * kc][2], sacc[2 * kc][3]);
            pa[2] = packbf(sacc[2 * kc + 1][0], sacc[2 * kc + 1][1]);
            pa[3] = packbf(sacc[2 * kc + 1][2], sacc[2 * kc + 1][3]);
#pragma unroll
            for (int nt = 0; nt < 8; ++nt) {
                const __nv_bfloat16* vp = Vs + (nt * 8 + g) * 72 + kc * 16 + 2 * c;
                uint32_t b0 = *(const uint32_t*)vp;
                uint32_t b1 = *(const uint32_t*)(vp + 8);
                mma_bf16(oacc[nt], pa, b0, b1);
            }
        }
        __syncthreads();   // buf fully consumed before next cp.async overwrite
    }

    // ---- write unnormalized partial O and (m, l) ----
    size_t row0 = ((size_t)sp * BH + bh) * Sq + q0 + rql;
    size_t row1 = row0 + 8;
    float* op0 = Opart + (row0 << 6);
    float* op1 = Opart + (row1 << 6);
#pragma unroll
    for (int nt = 0; nt < 8; ++nt) {
        *(float2*)&op0[nt * 8 + 2 * c] = make_float2(oacc[nt][0], oacc[nt][1]);
        *(float2*)&op1[nt * 8 + 2 * c] = make_float2(oacc[nt][2], oacc[nt][3]);
    }
    if (c == 0) {
        ml[row0 * 2]     = mr0;
        ml[row0 * 2 + 1] = l0;
        ml[row1 * 2]     = mr1;
        ml[row1 * 2 + 1] = l1;
    }
}

// ---------------------------------------------------------------------------
// Split-K combine.
// ---------------------------------------------------------------------------
__global__ __launch_bounds__(256) void attn_combine(
    const float* __restrict__ Opart, const float* __restrict__ ml,
    float* __restrict__ Ctx, int Sq, int nSplit) {
    const int BH = gridDim.y;
    const int bh = blockIdx.y;
    const int b = bh >> 2, h0 = (bh & 3) << 6;
    const int q = (blockIdx.x << 6) + (threadIdx.x >> 2);
    const int c0 = (threadIdx.x & 3) << 4;
    const size_t slab = (size_t)BH * Sq;
    const size_t rbase = (size_t)bh * Sq + q;

    float M = -1e30f;
    for (int sp = 0; sp < nSplit; ++sp)
        M = fmaxf(M, ml[(sp * slab + rbase) * 2]);

    float L = 0.0f;
    float4 a[4] = {{0,0,0,0},{0,0,0,0},{0,0,0,0},{0,0,0,0}};
    for (int sp = 0; sp < nSplit; ++sp) {
        size_t r = sp * slab + rbase;
        float w = __expf(ml[r * 2] - M);
        L += w * ml[r * 2 + 1];
        const float* p = Opart + (r << 6) + c0;
#pragma unroll
        for (int j = 0; j < 4; ++j) {
            float4 v = *(const float4*)(p + 4 * j);
            a[j].x += w * v.x; a[j].y += w * v.y;
            a[j].z += w * v.z; a[j].w += w * v.w;
        }
    }
    float inv = 1.0f / L;
    float* o = Ctx + ((size_t)(b * Sq + q)) * 256 + h0 + c0;
#pragma unroll
    for (int j = 0; j < 4; ++j)
        *(float4*)(o + 4 * j) = make_float4(a[j].x * inv, a[j].y * inv,
                                            a[j].z * inv, a[j].w * inv);
}

// ---------------------------------------------------------------------------
// LayerNorm over last dim (H=256). Warp per row.
// ---------------------------------------------------------------------------
__global__ __launch_bounds__(256) void ln_kernel(
    const float* __restrict__ in, const float* __restrict__ gamma,
    const float* __restrict__ beta, float* __restrict__ out) {
    const int warp = threadIdx.x >> 5, lane = threadIdx.x & 31;
    const size_t row = (size_t)blockIdx.x * 8 + warp;
    const float* p = in + row * 256 + lane * 8;
    float4 a = *(const float4*)p;
    float4 b = *(const float4*)(p + 4);

    float s = (a.x + a.y) + (a.z + a.w) + (b.x + b.y) + (b.z + b.w);
#pragma unroll
    for (int off = 16; off > 0; off >>= 1)
        s += __shfl_xor_sync(0xffffffffu, s, off);
    float mu = s * (1.0f / 256.0f);

    float dx = a.x - mu, dy = a.y - mu, dz = a.z - mu, dw = a.w - mu;
    float ex = b.x - mu, ey = b.y - mu, ez = b.z - mu, ew = b.w - mu;
    float q = dx * dx + dy * dy + dz * dz + dw * dw +
              ex * ex + ey * ey + ez * ez + ew * ew;
#pragma unroll
    for (int off = 16; off > 0; off >>= 1)
        q += __shfl_xor_sync(0xffffffffu, q, off);
    float inv = rsqrtf(q * (1.0f / 256.0f) + 1e-12f);

    float4 ga = *(const float4*)&gamma[lane * 8];
    float4 gb = *(const float4*)&gamma[lane * 8 + 4];
    float4 ba = *(const float4*)&beta[lane * 8];
    float4 bb = *(const float4*)&beta[lane * 8 + 4];
    float* o = out + row * 256 + lane * 8;
    *(float4*)o = make_float4(dx * inv * ga.x + ba.x, dy * inv * ga.y + ba.y,
                              dz * inv * ga.z + ba.z, dw * inv * ga.w + ba.w);
    *(float4*)(o + 4) = make_float4(ex * inv * gb.x + bb.x, ey * inv * gb.y + bb.y,
                                    ez * inv * gb.z + bb.z, ew * inv * gb.w + bb.w);
}

// ---------------------------------------------------------------------------
// Orchestration. Cross-KV projections + K/V conversions (depend only on
// xenc) run on a forked stream, joined per-layer via events.
// ---------------------------------------------------------------------------
extern "C" void kernel_launch(void* const* d_in, const int* in_sizes, int n_in,
                              void* d_out, int out_size) {
    const float* x      = (const float*)d_in[0];
    const float* y      = (const float*)d_in[1];
    const float* pos    = (const float*)d_in[2];
    const float* sqkvw  = (const float*)d_in[3];
    const float* sqkvb  = (const float*)d_in[4];
    const float* sow    = (const float*)d_in[5];
    const float* sob    = (const float*)d_in[6];
    const float* cqkvw  = (const float*)d_in[7];
    const float* cqkvb  = (const float*)d_in[8];
    const float* cow    = (const float*)d_in[9];
    const float* cob    = (const float*)d_in[10];
    const float* fw1    = (const float*)d_in[11];
    const float* fb1    = (const float*)d_in[12];
    const float* fw2    = (const float*)d_in[13];
    const float* fb2    = (const float*)d_in[14];
    const float* lng    = (const float*)d_in[15];
    const float* lnb    = (const float*)d_in[16];
    float* out = (float*)d_out;

    const int B = C_B, Se = C_SE, Sd = C_SD, H = C_H, F = C_F, L = C_L, NH = C_NH;
    const int Md = B * Sd;   // 4096
    const int Me = B * Se;   // 8192
    const int ATTN_SMEM = 4 * 64 * 72 * 2;                  // 36864 B
    const int G128_SMEM = (2 * 128 * 36 + 2 * 32 * 72) * 4; // 55296 B

    static bool init_done = false;
    static cudaStream_t s2;
    static cudaEvent_t evRoot, evKV[C_L];
    if (!init_done) {
        cudaFuncSetAttribute(attn_tc, cudaFuncAttributeMaxDynamicSharedMemorySize,
                             ATTN_SMEM);
        cudaFuncSetAttribute(gemm128_tc<false, false>,
                             cudaFuncAttributeMaxDynamicSharedMemorySize, G128_SMEM);
        cudaFuncSetAttribute(gemm128_tc<true, false>,
                             cudaFuncAttributeMaxDynamicSharedMemorySize, G128_SMEM);
        cudaFuncSetAttribute(gemm128_tc<false, true>,
                             cudaFuncAttributeMaxDynamicSharedMemorySize, G128_SMEM);
        cudaStreamCreateWithFlags(&s2, cudaStreamNonBlocking);
        cudaEventCreateWithFlags(&evRoot, cudaEventDisableTiming);
        for (int i = 0; i < C_L; ++i)
            cudaEventCreateWithFlags(&evKV[i], cudaEventDisableTiming);
        init_done = true;
    }

    float *xenc, *h, *qkv, *q, *kv6, *ctx, *tmp, *ffn, *opart, *ml;
    __nv_bfloat16 *vts, *vtc, *kbs, *kbc;
    cudaGetSymbolAddress((void**)&xenc,  g_xenc);
    cudaGetSymbolAddress((void**)&h,     g_h);
    cudaGetSymbolAddress((void**)&qkv,   g_qkv);
    cudaGetSymbolAddress((void**)&q,     g_q);
    cudaGetSymbolAddress((void**)&kv6,   g_kv6);
    cudaGetSymbolAddress((void**)&ctx,   g_ctx);
    cudaGetSymbolAddress((void**)&tmp,   g_tmp);
    cudaGetSymbolAddress((void**)&ffn,   g_ffn);
    cudaGetSymbolAddress((void**)&opart, g_opart);
    cudaGetSymbolAddress((void**)&ml,    g_ml);
    cudaGetSymbolAddress((void**)&vts,   g_vts);
    cudaGetSymbolAddress((void**)&vtc,   g_vtc);
    cudaGetSymbolAddress((void**)&kbs,   g_kbs);
    cudaGetSymbolAddress((void**)&kbc,   g_kbc);

    {
        int total = B * Se * H;
        add_pos_kernel<<<(total + 255) / 256, 256>>>(x, pos, xenc, total, Se * H);
    }
    cudaMemcpyAsync(h, y, sizeof(float) * (size_t)Md * H, cudaMemcpyDeviceToDevice);

    const dim3 blk128(128);
    const dim3 blk256(256);
    const dim3 gSelfQKV(768 / 64, Md / 128);
    const dim3 gProj32(256 / 64, Md / 32);
    const dim3 gCrossKV(512 / 64, Me / 128);
    const dim3 gFfn1(1024 / 64, Md / 128);
    const dim3 gFfn2(256 / 64, Md / 128);
    const dim3 gCvtSelf(Sd / 64, B * NH);
    const dim3 gCvtCross(Se / 64, B * NH);
    const dim3 gAttnSelf(Sd / 128, B * NH, 4);    // kChunk=512
    const dim3 gAttnCross(Sd / 128, B * NH, 4);   // kChunk=1024
    const dim3 gComb(Sd / 64, B * NH);

    // fork: cross-KV projections + K/V conversions on s2
    cudaEventRecord(evRoot, 0);
    cudaStreamWaitEvent(s2, evRoot, 0);
    for (int i = 0; i < L; ++i) {
        const float* cw = cqkvw + (size_t)i * 3 * H * H;
        const float* cb = cqkvb + (size_t)i * 3 * H;
        float* kvDst = kv6 + (size_t)i * 2 * Me * H;
        gemm128_tc<false, false><<<gCrossKV, blk256, G128_SMEM, s2>>>(
            xenc, cw + (size_t)H * H, cb + H, nullptr, kvDst, Me, 512, H, 256);
        kcvt_kernel<<<gCvtCross, blk256, 0, s2>>>(
            kvDst, kbc + (size_t)i * 8 * Se * 64, Se);
        vt_kernel<<<gCvtCross, blk256, 0, s2>>>(
            kvDst + (size_t)Me * H, vtc + (size_t)i * 8 * 64 * Se, Se);
        cudaEventRecord(evKV[i], s2);
    }

    for (int i = 0; i < L; ++i) {
        const float* sw  = sqkvw + (size_t)i * 3 * H * H;
        const float* sb  = sqkvb + (size_t)i * 3 * H;
        const float* sOw = sow + (size_t)i * H * H;
        const float* sOb = sob + (size_t)i * H;
        const float* cw  = cqkvw + (size_t)i * 3 * H * H;
        const float* cb  = cqkvb + (size_t)i * 3 * H;
        const float* cOw = cow + (size_t)i * H * H;
        const float* cOb = cob + (size_t)i * H;
        const float* w1  = fw1 + (size_t)i * H * F;
        const float* b1  = fb1 + (size_t)i * F;
        const float* w2  = fw2 + (size_t)i * F * H;
        const float* b2  = fb2 + (size_t)i * H;
        __nv_bfloat16* kbcL = kbc + (size_t)i * 8 * Se * 64;
        __nv_bfloat16* vtcL = vtc + (size_t)i * 8 * 64 * Se;

        // ---- self attention ----
        gemm128_tc<false, false><<<gSelfQKV, blk256, G128_SMEM>>>(
            h, sw, sb, nullptr, qkv, Md, 768, H, 256);
        kcvt_kernel<<<gCvtSelf, blk256>>>(qkv + (size_t)Md * H, kbs, Sd);
        vt_kernel<<<gCvtSelf, blk256>>>(qkv + (size_t)2 * Md * H, vts, Sd);
        attn_tc<<<gAttnSelf, blk256, ATTN_SMEM>>>(qkv, kbs, vts,
                                                  opart, ml, Sd, Sd, 512);
        attn_combine<<<gComb, 256>>>(opart, ml, ctx, Sd, 4);
        gemm32_tc<true><<<gProj32, blk128>>>(ctx, sOw, sOb, h, tmp, Md, 256, 256);
        ln_kernel<<<Md / 8, 256>>>(tmp, lng + (size_t)(i * 3 + 0) * H,
                                   lnb + (size_t)(i * 3 + 0) * H, h);

        // ---- cross attention ----
        gemm32_tc<false><<<gProj32, blk128>>>(h, cw, cb, nullptr, q, Md, 256, 256);
        cudaStreamWaitEvent(0, evKV[i], 0);
        attn_tc<<<gAttnCross, blk256, ATTN_SMEM>>>(q, kbcL, vtcL,
                                                   opart, ml, Sd, Se, 1024);
        attn_combine<<<gComb, 256>>>(opart, ml, ctx, Sd, 4);
        gemm32_tc<true><<<gProj32, blk128>>>(ctx, cOw, cOb, h, tmp, Md, 256, 256);
        ln_kernel<<<Md / 8, 256>>>(tmp, lng + (size_t)(i * 3 + 1) * H,
                                   lnb + (size_t)(i * 3 + 1) * H, h);

        // ---- FFN ----
        gemm128_tc<true, false><<<gFfn1, blk256, G128_SMEM>>>(
            h, w1, b1, nullptr, ffn, Md, 1024, H, 1024);
        gemm128_tc<false, true><<<gFfn2, blk256, G128_SMEM>>>(
            ffn, w2, b2, h, tmp, Md, 256, F, 256);
        ln_kernel<<<Md / 8, 256>>>(tmp, lng + (size_t)(i * 3 + 2) * H,
                                   lnb + (size_t)(i * 3 + 2) * H,
                                   (i == L - 1) ? out : h);
    }
}